// round 5
// baseline (speedup 1.0000x reference)
#include <cuda_runtime.h>
#include <cuda_bf16.h>
#include <cstdint>

// ---------------- problem constants ----------------
#define NN 50000
#define EE 500000
#define GG 64

// ---------------- scratch (device globals; no allocation allowed) ----------
__device__ float g_t1[(size_t)EE * 256];     // 512 MB  edge intermediate 1
__device__ float g_t2[(size_t)EE * 256];     // 512 MB  edge intermediate 2
__device__ float g_hA[(size_t)NN * 256];     // node features ping
__device__ float g_hB[(size_t)NN * 256];     // node features pong
__device__ float g_stats[1024];              // sum1[256], sq1[256], sum2[256], sq2[256]
__device__ float g_norm[1024];               // a1[256], c1[256], a2[256], c2[256]
__device__ int   g_deg[NN];
__device__ int   g_rowptr[NN + 1];
__device__ int   g_cursor[NN];
__device__ int   g_eidx[EE];
__device__ int   g_cnt[GG];
__device__ int   g_gstart[GG + 1];
__device__ float g_pool[GG * 256];
__device__ float g_zbuf[GG * 128];
// transposed bf16 hi/lo weights (Wt[OC][KPAD]) for all 6 GEMMs
__device__ __nv_bfloat16 g_wth[172032];
__device__ __nv_bfloat16 g_wtl[172032];

// ---------------- mma.sync / ldmatrix helpers (sm_80+ PTX) -----------------
#define MMA_BF16(d, a, b)                                                        \
    asm volatile("mma.sync.aligned.m16n8k16.row.col.f32.bf16.bf16.f32 "          \
                 "{%0,%1,%2,%3}, {%4,%5,%6,%7}, {%8,%9}, {%0,%1,%2,%3};"         \
                 : "+f"((d)[0]), "+f"((d)[1]), "+f"((d)[2]), "+f"((d)[3])        \
                 : "r"((a)[0]), "r"((a)[1]), "r"((a)[2]), "r"((a)[3]),           \
                   "r"((b)[0]), "r"((b)[1]))

#define LDSM_X4(r0, r1, r2, r3, addr)                                            \
    asm volatile("ldmatrix.sync.aligned.m8n8.x4.shared.b16 {%0,%1,%2,%3}, [%4];" \
                 : "=r"(r0), "=r"(r1), "=r"(r2), "=r"(r3) : "r"(addr))

__device__ __forceinline__ uint32_t smem_u32(const void* p) {
    uint32_t a;
    asm("{ .reg .u64 t; cvta.to.shared.u64 t, %1; cvt.u32.u64 %0, t; }" : "=r"(a) : "l"(p));
    return a;
}

// ---------------- CSR build ----------------
__global__ void hist_deg_kernel(const int* __restrict__ dst, int* __restrict__ deg, int E) {
    int e = blockIdx.x * blockDim.x + threadIdx.x;
    if (e < E) atomicAdd(&deg[dst[e]], 1);
}
__global__ void hist_cnt_kernel(const int* __restrict__ batch, int* __restrict__ cnt, int n) {
    int i = blockIdx.x * blockDim.x + threadIdx.x;
    if (i < n) atomicAdd(&cnt[batch[i]], 1);
}
__global__ void scan_kernel(const int* __restrict__ deg, int* __restrict__ rowptr,
                            int* __restrict__ cursor, const int* __restrict__ cnt,
                            int* __restrict__ gstart, int n) {
    __shared__ int sh[1024];
    __shared__ int carry;
    int t = threadIdx.x;
    if (t == 0) carry = 0;
    __syncthreads();
    for (int base = 0; base < n; base += 1024) {
        int idx = base + t;
        int v = (idx < n) ? deg[idx] : 0;
        sh[t] = v;
        __syncthreads();
        for (int off = 1; off < 1024; off <<= 1) {
            int add = (t >= off) ? sh[t - off] : 0;
            __syncthreads();
            sh[t] += add;
            __syncthreads();
        }
        int ex = sh[t] - v;
        int cbase = carry;
        if (idx < n) { rowptr[idx] = cbase + ex; cursor[idx] = cbase + ex; }
        __syncthreads();
        if (t == 1023) carry = cbase + sh[1023];
        __syncthreads();
    }
    if (t == 0) {
        rowptr[n] = carry;
        int s = 0;
        for (int g = 0; g < GG; g++) { gstart[g] = s; s += cnt[g]; }
        gstart[GG] = s;
    }
}
__global__ void fill_csr_kernel(const int* __restrict__ dst, int* __restrict__ cursor,
                                int* __restrict__ eidx, int E) {
    int e = blockIdx.x * blockDim.x + threadIdx.x;
    if (e < E) {
        int p = atomicAdd(&cursor[dst[e]], 1);
        eidx[p] = e;
    }
}

// ---------------- weight convert: W[K,OC] fp32 -> Wt[OC][KPAD] bf16 hi/lo ---
__global__ void convert_w_kernel(const float* __restrict__ W,
                                 __nv_bfloat16* __restrict__ Wth,
                                 __nv_bfloat16* __restrict__ Wtl,
                                 int K, int OC, int KPAD) {
    int idx = blockIdx.x * blockDim.x + threadIdx.x;
    if (idx >= OC * KPAD) return;
    int n = idx / KPAD, k = idx % KPAD;
    float w = (k < K) ? W[(size_t)k * OC + n] : 0.f;
    __nv_bfloat16 h = __float2bfloat16_rn(w);
    Wth[idx] = h;
    Wtl[idx] = __float2bfloat16_rn(w - __bfloat162float(h));
}

// ---------------- tensor-core GEMM via mma.sync, fused BN stats ------------
// out[e, 0:OC] = A[e, 0:K] @ W[K, OC] + bias   (fp32 accumulate)
// A and W both split bf16 hi+lo; 3 MMAs per tile (AhBh + AhBl + AlBh).
// Also accumulates per-column sum / sum-of-squares into stat_sum / stat_sq.
// Block tile: 128 x BN.  8 warps = 4(M) x 2(N).  Warp tile: 32 x BN/2.
template <int C, int K, int OC, int BN, bool GATHER>
__global__ __launch_bounds__(256)
void mgemm_kernel(const float* __restrict__ feats,
                  const int* __restrict__ src, const int* __restrict__ dst,
                  const float* __restrict__ an, const float* __restrict__ cn,
                  const __nv_bfloat16* __restrict__ Wth,
                  const __nv_bfloat16* __restrict__ Wtl,
                  const float* __restrict__ bias,
                  float* __restrict__ out,
                  float* __restrict__ stat_sum, float* __restrict__ stat_sq,
                  int E) {
    constexpr int KPAD = (K + 31) / 32 * 32;
    constexpr int NCH = KPAD / 32;
    constexpr int NT = BN / 16;          // n8-tiles per warp (warp N = BN/2)
    constexpr int SAS = 72;              // smem stride (bf16): 144B, 16B-aligned,
                                         // 8-row LDSM phases hit 8 distinct banks

    __shared__ __nv_bfloat16 sAh[128 * SAS], sAl[128 * SAS];
    __shared__ __nv_bfloat16 sBh[BN * SAS], sBl[BN * SAS];
    __shared__ int sdst[128], ssrc[128];

    const int tid = threadIdx.x;
    const int lane = tid & 31;
    const int wid = tid >> 5;
    const int wm = wid & 3;              // 0..3 over M
    const int wn = wid >> 2;             // 0..1 over N
    const int e0 = blockIdx.x * 128;
    const int col0 = blockIdx.y * BN;

    const uint32_t sAh_u = smem_u32(sAh);
    const uint32_t sAl_u = smem_u32(sAl);
    const uint32_t sBh_u = smem_u32(sBh);
    const uint32_t sBl_u = smem_u32(sBl);

    if (GATHER && tid < 128) {
        int e = e0 + tid;
        int ee = (e < E) ? e : (E - 1);
        sdst[tid] = dst[ee];
        ssrc[tid] = src[ee];
    }
    __syncthreads();

    float acc[2][NT][4];
#pragma unroll
    for (int mt = 0; mt < 2; mt++)
#pragma unroll
        for (int nt = 0; nt < NT; nt++)
#pragma unroll
            for (int j = 0; j < 4; j++) acc[mt][nt][j] = 0.f;

    const int arow = tid >> 1;           // A production: row handled
    const int acg = (tid & 1) * 16;      // 16 cols within 32-col chunk

    // ldmatrix lane->address precompute
    const int a_lrow = (lane & 7) + ((lane >> 3) & 1) * 8;
    const int a_lcol = (lane >> 4) * 8;
    const int b_lrow = (lane & 7) + (lane >> 4) * 8;
    const int b_lcol = ((lane >> 3) & 1) * 8;

    for (int ch = 0; ch < NCH; ch++) {
        // ---- produce A chunk (128 x 32), hi/lo split ----
        {
            int nd = 0, ns = 0;
            if (GATHER) { nd = sdst[arow]; ns = ssrc[arow]; }
            const int e = e0 + arow;
#pragma unroll
            for (int u = 0; u < 4; u++) {
                const int k = ch * 32 + acg + u * 4;
                float4 v;
                if (GATHER) {
                    if (C % 4 == 0) {
                        if (k < C) {
                            v = *reinterpret_cast<const float4*>(&feats[(size_t)nd * C + k]);
                        } else {
                            float4 xs = *reinterpret_cast<const float4*>(&feats[(size_t)ns * C + (k - C)]);
                            float4 xd = *reinterpret_cast<const float4*>(&feats[(size_t)nd * C + (k - C)]);
                            v = make_float4(xs.x - xd.x, xs.y - xd.y, xs.z - xd.z, xs.w - xd.w);
                        }
                    } else {  // scalar path (C=7, K=14, KPAD=32)
                        float t[4];
#pragma unroll
                        for (int j = 0; j < 4; j++) {
                            int kk = k + j;
                            if (kk < C) t[j] = feats[(size_t)nd * C + kk];
                            else if (kk < K) t[j] = feats[(size_t)ns * C + (kk - C)] - feats[(size_t)nd * C + (kk - C)];
                            else t[j] = 0.f;
                        }
                        v = make_float4(t[0], t[1], t[2], t[3]);
                    }
                } else {
                    if (e < E) {
                        float4 t = *reinterpret_cast<const float4*>(&feats[(size_t)e * K + k]);
                        v.x = fmaxf(t.x * an[k + 0] + cn[k + 0], 0.f);
                        v.y = fmaxf(t.y * an[k + 1] + cn[k + 1], 0.f);
                        v.z = fmaxf(t.z * an[k + 2] + cn[k + 2], 0.f);
                        v.w = fmaxf(t.w * an[k + 3] + cn[k + 3], 0.f);
                    } else {
                        v = make_float4(0.f, 0.f, 0.f, 0.f);
                    }
                }
                __nv_bfloat162 h01 = __float22bfloat162_rn(make_float2(v.x, v.y));
                __nv_bfloat162 h23 = __float22bfloat162_rn(make_float2(v.z, v.w));
                float2 hf01 = __bfloat1622float2(h01);
                float2 hf23 = __bfloat1622float2(h23);
                __nv_bfloat162 l01 = __float22bfloat162_rn(make_float2(v.x - hf01.x, v.y - hf01.y));
                __nv_bfloat162 l23 = __float22bfloat162_rn(make_float2(v.z - hf23.x, v.w - hf23.y));
                uint2 H, L;
                H.x = *reinterpret_cast<uint32_t*>(&h01);
                H.y = *reinterpret_cast<uint32_t*>(&h23);
                L.x = *reinterpret_cast<uint32_t*>(&l01);
                L.y = *reinterpret_cast<uint32_t*>(&l23);
                int so = arow * SAS + acg + u * 4;
                *reinterpret_cast<uint2*>(&sAh[so]) = H;
                *reinterpret_cast<uint2*>(&sAl[so]) = L;
            }
        }
        // ---- load B chunk (BN x 32), hi + lo ----
        {
#pragma unroll
            for (int i = tid; i < BN * 4; i += 256) {
                int n = i >> 2, u = i & 3;
                size_t soff = (size_t)(col0 + n) * KPAD + ch * 32 + u * 8;
                int doff = n * SAS + u * 8;
                *reinterpret_cast<uint4*>(&sBh[doff]) =
                    *reinterpret_cast<const uint4*>(Wth + soff);
                *reinterpret_cast<uint4*>(&sBl[doff]) =
                    *reinterpret_cast<const uint4*>(Wtl + soff);
            }
        }
        __syncthreads();

        // ---- 2 x k16 MMA steps (ldmatrix fragment loads) ----
#pragma unroll
        for (int ks = 0; ks < 2; ks++) {
            const int kb = ks * 16;
            uint32_t ah[2][4], al[2][4];
#pragma unroll
            for (int mt = 0; mt < 2; mt++) {
                int r = wm * 32 + mt * 16 + a_lrow;
                uint32_t off = (uint32_t)(r * SAS + kb + a_lcol) * 2;
                LDSM_X4(ah[mt][0], ah[mt][1], ah[mt][2], ah[mt][3], sAh_u + off);
                LDSM_X4(al[mt][0], al[mt][1], al[mt][2], al[mt][3], sAl_u + off);
            }
#pragma unroll
            for (int p = 0; p < NT / 2; p++) {
                int n0 = wn * (BN / 2) + p * 16;
                uint32_t boff = (uint32_t)((n0 + b_lrow) * SAS + kb + b_lcol) * 2;
                uint32_t bh[4], bl[4];
                LDSM_X4(bh[0], bh[1], bh[2], bh[3], sBh_u + boff);
                LDSM_X4(bl[0], bl[1], bl[2], bl[3], sBl_u + boff);
#pragma unroll
                for (int mt = 0; mt < 2; mt++) {
                    MMA_BF16(acc[mt][2 * p], ah[mt], (&bh[0]));
                    MMA_BF16(acc[mt][2 * p], ah[mt], (&bl[0]));
                    MMA_BF16(acc[mt][2 * p], al[mt], (&bh[0]));
                    MMA_BF16(acc[mt][2 * p + 1], ah[mt], (&bh[2]));
                    MMA_BF16(acc[mt][2 * p + 1], ah[mt], (&bl[2]));
                    MMA_BF16(acc[mt][2 * p + 1], al[mt], (&bh[2]));
                }
            }
        }
        __syncthreads();
    }

    // ---- epilogue: bias + store + fused BN stats ----
    float* ssum = reinterpret_cast<float*>(sAh);   // reuse A smem (BN floats)
    float* ssq = ssum + BN;
    for (int i = tid; i < 2 * BN; i += 256) ssum[i] = 0.f;
    __syncthreads();

#pragma unroll
    for (int nt = 0; nt < NT; nt++) {
        const int colw = wn * (BN / 2) + nt * 8 + (lane & 3) * 2;
        const int col = col0 + colw;
        const float b0 = bias[col], b1 = bias[col + 1];
        float s0 = 0.f, q0 = 0.f, s1 = 0.f, q1 = 0.f;
#pragma unroll
        for (int mt = 0; mt < 2; mt++) {
            const int r = wm * 32 + mt * 16 + (lane >> 2);
            const int e1 = e0 + r, e2 = e0 + r + 8;
            float v0 = acc[mt][nt][0] + b0, v1 = acc[mt][nt][1] + b1;
            float v2 = acc[mt][nt][2] + b0, v3 = acc[mt][nt][3] + b1;
            if (e1 < E) {
                *reinterpret_cast<float2*>(&out[(size_t)e1 * OC + col]) = make_float2(v0, v1);
                s0 += v0; q0 += v0 * v0; s1 += v1; q1 += v1 * v1;
            }
            if (e2 < E) {
                *reinterpret_cast<float2*>(&out[(size_t)e2 * OC + col]) = make_float2(v2, v3);
                s0 += v2; q0 += v2 * v2; s1 += v3; q1 += v3 * v3;
            }
        }
#pragma unroll
        for (int m = 4; m <= 16; m <<= 1) {
            s0 += __shfl_xor_sync(0xffffffff, s0, m);
            q0 += __shfl_xor_sync(0xffffffff, q0, m);
            s1 += __shfl_xor_sync(0xffffffff, s1, m);
            q1 += __shfl_xor_sync(0xffffffff, q1, m);
        }
        if ((lane >> 2) == 0) {
            atomicAdd(&ssum[colw], s0);
            atomicAdd(&ssq[colw], q0);
            atomicAdd(&ssum[colw + 1], s1);
            atomicAdd(&ssq[colw + 1], q1);
        }
    }
    __syncthreads();
    for (int i = tid; i < BN; i += 256) {
        atomicAdd(&stat_sum[col0 + i], ssum[i]);
        atomicAdd(&stat_sq[col0 + i], ssq[i]);
    }
}

// ---------------- BN finalize ----------------
__global__ void finalize_kernel(const float* __restrict__ sum, const float* __restrict__ sq,
                                const float* __restrict__ gamma, const float* __restrict__ beta,
                                float* __restrict__ a, float* __restrict__ c,
                                int OC, float invE) {
    int i = blockIdx.x * blockDim.x + threadIdx.x;
    if (i < OC) {
        float m = sum[i] * invE;
        float var = sq[i] * invE - m * m;
        float rs = rsqrtf(var + 1e-5f);
        float ai = gamma[i] * rs;
        a[i] = ai;
        c[i] = beta[i] - m * ai;
    }
}

// ---------------- normalize + relu + mean-aggregate (CSR, warp per node) ----
template <int OC>
__global__ __launch_bounds__(256)
void aggregate_kernel(const float* __restrict__ t, const int* __restrict__ rowptr,
                      const int* __restrict__ eidx, const float* __restrict__ a,
                      const float* __restrict__ c, float* __restrict__ hout, int n) {
    int warp = (blockIdx.x * blockDim.x + threadIdx.x) >> 5;
    int lane = threadIdx.x & 31;
    if (warp >= n) return;
    constexpr int R = OC / 32;
    float av[R], cv[R], acc[R];
#pragma unroll
    for (int j = 0; j < R; j++) {
        int ch = j * 32 + lane;
        av[j] = a[ch]; cv[j] = c[ch]; acc[j] = 0.f;
    }
    int beg = rowptr[warp], end = rowptr[warp + 1];
    for (int p = beg; p < end; p++) {
        int e = eidx[p];
        const float* rowp = t + (size_t)e * OC;
#pragma unroll
        for (int j = 0; j < R; j++) {
            float v = rowp[j * 32 + lane];
            acc[j] += fmaxf(v * av[j] + cv[j], 0.f);
        }
    }
    float inv = 1.f / fmaxf((float)(end - beg), 1.f);
#pragma unroll
    for (int j = 0; j < R; j++) hout[(size_t)warp * OC + j * 32 + lane] = acc[j] * inv;
}

// ---------------- global mean pool + head ----------------
__global__ void pool_kernel(const float* __restrict__ h, const int* __restrict__ gstart,
                            float* __restrict__ pool) {
    int g = blockIdx.x;
    int ch = threadIdx.x;
    int beg = gstart[g], end = gstart[g + 1];
    float s = 0.f;
    for (int nidx = beg; nidx < end; nidx++) s += h[(size_t)nidx * 256 + ch];
    pool[g * 256 + ch] = s / fmaxf((float)(end - beg), 1.f);
}
__global__ void head1_kernel(const float* __restrict__ pool, const float* __restrict__ W,
                             const float* __restrict__ b, float* __restrict__ z) {
    int g = blockIdx.x, j = threadIdx.x;
    __shared__ float sp[256];
    sp[j] = pool[g * 256 + j];
    sp[j + 128] = pool[g * 256 + j + 128];
    __syncthreads();
    float s = b[j];
#pragma unroll 8
    for (int k = 0; k < 256; k++) s += sp[k] * W[k * 128 + j];
    z[g * 128 + j] = fmaxf(s, 0.f);
}
__global__ void head2_kernel(const float* __restrict__ z, const float* __restrict__ W,
                             const float* __restrict__ b, float* __restrict__ out) {
    int t = threadIdx.x;
    int g = t >> 1, j = t & 1;
    float s = b[j];
#pragma unroll 8
    for (int k = 0; k < 128; k++) s += z[g * 128 + k] * W[k * 2 + j];
    out[g * 2 + j] = s;
}

// ---------------- launch ----------------
extern "C" void kernel_launch(void* const* d_in, const int* in_sizes, int n_in,
                              void* d_out, int out_size) {
    const float* x     = (const float*)d_in[0];
    const int*   ei    = (const int*)d_in[1];
    const int*   batch = (const int*)d_in[2];

    const int E = in_sizes[1] / 2;
    const int n = in_sizes[2];
    const int* srcp = ei;
    const int* dstp = ei + E;

    const float* W[3][2];  const float* B[3][2];
    const float* Gm[3][2]; const float* Bt[3][2];
    for (int l = 0; l < 3; l++) {
        int base = 3 + l * 8;
        W[l][0]  = (const float*)d_in[base + 0];
        B[l][0]  = (const float*)d_in[base + 1];
        Gm[l][0] = (const float*)d_in[base + 2];
        Bt[l][0] = (const float*)d_in[base + 3];
        W[l][1]  = (const float*)d_in[base + 4];
        B[l][1]  = (const float*)d_in[base + 5];
        Gm[l][1] = (const float*)d_in[base + 6];
        Bt[l][1] = (const float*)d_in[base + 7];
    }
    const float* hW1 = (const float*)d_in[27];
    const float* hb1 = (const float*)d_in[28];
    const float* hW2 = (const float*)d_in[29];
    const float* hb2 = (const float*)d_in[30];

    float *t1, *t2, *hA, *hB, *stats, *norm, *pool, *zbuf;
    int *deg, *rowptr, *cursor, *eidx, *cnt, *gstart;
    __nv_bfloat16 *wth, *wtl;
    cudaGetSymbolAddress((void**)&t1, g_t1);
    cudaGetSymbolAddress((void**)&t2, g_t2);
    cudaGetSymbolAddress((void**)&hA, g_hA);
    cudaGetSymbolAddress((void**)&hB, g_hB);
    cudaGetSymbolAddress((void**)&stats, g_stats);
    cudaGetSymbolAddress((void**)&norm, g_norm);
    cudaGetSymbolAddress((void**)&deg, g_deg);
    cudaGetSymbolAddress((void**)&rowptr, g_rowptr);
    cudaGetSymbolAddress((void**)&cursor, g_cursor);
    cudaGetSymbolAddress((void**)&eidx, g_eidx);
    cudaGetSymbolAddress((void**)&cnt, g_cnt);
    cudaGetSymbolAddress((void**)&gstart, g_gstart);
    cudaGetSymbolAddress((void**)&pool, g_pool);
    cudaGetSymbolAddress((void**)&zbuf, g_zbuf);
    cudaGetSymbolAddress((void**)&wth, g_wth);
    cudaGetSymbolAddress((void**)&wtl, g_wtl);

    float* sum1 = stats + 0;   float* sq1 = stats + 256;
    float* sum2 = stats + 512; float* sq2 = stats + 768;
    float* a1 = norm + 0;   float* c1 = norm + 256;
    float* a2 = norm + 512; float* c2 = norm + 768;

    // transposed weight buffers: {L1g1(64x32), L1g2(64x64), L2g1(128x128),
    //                             L2g2(128x128), L3g1(256x256), L3g2(256x256)}
    const int wt_off[6] = {0, 2048, 6144, 22528, 38912, 104448};

    const float invE = 1.f / (float)E;
    const int EB = (E + 127) / 128;
    const int EG = (E + 255) / 256;
    const int NG = (n + 255) / 256;
    const int AGG = (n * 32 + 255) / 256;

    // ---- CSR build + weight conversion ----
    cudaMemsetAsync(deg, 0, n * sizeof(int));
    cudaMemsetAsync(cnt, 0, GG * sizeof(int));
    hist_deg_kernel<<<EG, 256>>>(dstp, deg, E);
    hist_cnt_kernel<<<NG, 256>>>(batch, cnt, n);
    scan_kernel<<<1, 1024>>>(deg, rowptr, cursor, cnt, gstart, n);
    fill_csr_kernel<<<EG, 256>>>(dstp, cursor, eidx, E);

    convert_w_kernel<<<(64 * 32 + 255) / 256, 256>>>(W[0][0], wth + wt_off[0], wtl + wt_off[0], 14, 64, 32);
    convert_w_kernel<<<(64 * 64 + 255) / 256, 256>>>(W[0][1], wth + wt_off[1], wtl + wt_off[1], 64, 64, 64);
    convert_w_kernel<<<(128 * 128 + 255) / 256, 256>>>(W[1][0], wth + wt_off[2], wtl + wt_off[2], 128, 128, 128);
    convert_w_kernel<<<(128 * 128 + 255) / 256, 256>>>(W[1][1], wth + wt_off[3], wtl + wt_off[3], 128, 128, 128);
    convert_w_kernel<<<(256 * 256 + 255) / 256, 256>>>(W[2][0], wth + wt_off[4], wtl + wt_off[4], 256, 256, 256);
    convert_w_kernel<<<(256 * 256 + 255) / 256, 256>>>(W[2][1], wth + wt_off[5], wtl + wt_off[5], 256, 256, 256);

    // ---- layer 1: 7 -> 64 ----
    cudaMemsetAsync(stats, 0, 1024 * sizeof(float));
    mgemm_kernel<7, 14, 64, 64, true><<<dim3(EB, 1), 256>>>(
        x, srcp, dstp, nullptr, nullptr, wth + wt_off[0], wtl + wt_off[0], B[0][0], t1, sum1, sq1, E);
    finalize_kernel<<<1, 64>>>(sum1, sq1, Gm[0][0], Bt[0][0], a1, c1, 64, invE);
    mgemm_kernel<0, 64, 64, 64, false><<<dim3(EB, 1), 256>>>(
        t1, nullptr, nullptr, a1, c1, wth + wt_off[1], wtl + wt_off[1], B[0][1], t2, sum2, sq2, E);
    finalize_kernel<<<1, 64>>>(sum2, sq2, Gm[0][1], Bt[0][1], a2, c2, 64, invE);
    aggregate_kernel<64><<<AGG, 256>>>(t2, rowptr, eidx, a2, c2, hA, n);

    // ---- layer 2: 64 -> 128 ----
    cudaMemsetAsync(stats, 0, 1024 * sizeof(float));
    mgemm_kernel<64, 128, 128, 128, true><<<dim3(EB, 1), 256>>>(
        hA, srcp, dstp, nullptr, nullptr, wth + wt_off[2], wtl + wt_off[2], B[1][0], t1, sum1, sq1, E);
    finalize_kernel<<<1, 128>>>(sum1, sq1, Gm[1][0], Bt[1][0], a1, c1, 128, invE);
    mgemm_kernel<0, 128, 128, 128, false><<<dim3(EB, 1), 256>>>(
        t1, nullptr, nullptr, a1, c1, wth + wt_off[3], wtl + wt_off[3], B[1][1], t2, sum2, sq2, E);
    finalize_kernel<<<1, 128>>>(sum2, sq2, Gm[1][1], Bt[1][1], a2, c2, 128, invE);
    aggregate_kernel<128><<<AGG, 256>>>(t2, rowptr, eidx, a2, c2, hB, n);

    // ---- layer 3: 128 -> 256 ----
    cudaMemsetAsync(stats, 0, 1024 * sizeof(float));
    mgemm_kernel<128, 256, 256, 128, true><<<dim3(EB, 2), 256>>>(
        hB, srcp, dstp, nullptr, nullptr, wth + wt_off[4], wtl + wt_off[4], B[2][0], t1, sum1, sq1, E);
    finalize_kernel<<<1, 256>>>(sum1, sq1, Gm[2][0], Bt[2][0], a1, c1, 256, invE);
    mgemm_kernel<0, 256, 256, 128, false><<<dim3(EB, 2), 256>>>(
        t1, nullptr, nullptr, a1, c1, wth + wt_off[5], wtl + wt_off[5], B[2][1], t2, sum2, sq2, E);
    finalize_kernel<<<1, 256>>>(sum2, sq2, Gm[2][1], Bt[2][1], a2, c2, 256, invE);
    aggregate_kernel<256><<<AGG, 256>>>(t2, rowptr, eidx, a2, c2, hA, n);

    // ---- pool + head ----
    pool_kernel<<<GG, 256>>>(hA, gstart, pool);
    head1_kernel<<<GG, 128>>>(pool, hW1, hb1, zbuf);
    head2_kernel<<<1, 128>>>(zbuf, hW2, hb2, (float*)d_out);
}

// round 6
// speedup vs baseline: 1.0071x; 1.0071x over previous
#include <cuda_runtime.h>
#include <cuda_bf16.h>
#include <cstdint>

// ---------------- problem constants ----------------
#define NN 50000
#define EE 500000
#define GG 64

// ---------------- scratch (device globals; no allocation allowed) ----------
__device__ float g_t1[(size_t)EE * 256];     // 512 MB  edge intermediate 1
__device__ float g_t2[(size_t)EE * 256];     // 512 MB  edge intermediate 2
__device__ float g_hA[(size_t)NN * 256];     // node features ping
__device__ float g_hB[(size_t)NN * 256];     // node features pong
__device__ float g_stats[1024];              // sum1[256], sq1[256], sum2[256], sq2[256]
__device__ float g_norm[1024];               // a1[256], c1[256], a2[256], c2[256]
__device__ int   g_deg[NN];
__device__ int   g_rowptr[NN + 1];
__device__ int   g_cursor[NN];
__device__ int   g_eidx[EE];
__device__ int   g_cnt[GG];
__device__ int   g_gstart[GG + 1];
__device__ float g_pool[GG * 256];
__device__ float g_zbuf[GG * 128];
// transposed bf16 hi/lo weights (Wt[OC][KPAD]) for all 6 GEMMs
__device__ __nv_bfloat16 g_wth[172032];
__device__ __nv_bfloat16 g_wtl[172032];

// ---------------- mma.sync / ldmatrix helpers (sm_80+ PTX) -----------------
#define MMA_BF16(d, a, b)                                                        \
    asm volatile("mma.sync.aligned.m16n8k16.row.col.f32.bf16.bf16.f32 "          \
                 "{%0,%1,%2,%3}, {%4,%5,%6,%7}, {%8,%9}, {%0,%1,%2,%3};"         \
                 : "+f"((d)[0]), "+f"((d)[1]), "+f"((d)[2]), "+f"((d)[3])        \
                 : "r"((a)[0]), "r"((a)[1]), "r"((a)[2]), "r"((a)[3]),           \
                   "r"((b)[0]), "r"((b)[1]))

#define LDSM_X4(r0, r1, r2, r3, addr)                                            \
    asm volatile("ldmatrix.sync.aligned.m8n8.x4.shared.b16 {%0,%1,%2,%3}, [%4];" \
                 : "=r"(r0), "=r"(r1), "=r"(r2), "=r"(r3) : "r"(addr))

__device__ __forceinline__ uint32_t smem_u32(const void* p) {
    uint32_t a;
    asm("{ .reg .u64 t; cvta.to.shared.u64 t, %1; cvt.u32.u64 %0, t; }" : "=r"(a) : "l"(p));
    return a;
}

// ---------------- CSR build ----------------
__global__ void hist_deg_kernel(const int* __restrict__ dst, int* __restrict__ deg, int E) {
    int e = blockIdx.x * blockDim.x + threadIdx.x;
    if (e < E) atomicAdd(&deg[dst[e]], 1);
}
__global__ void hist_cnt_kernel(const int* __restrict__ batch, int* __restrict__ cnt, int n) {
    int i = blockIdx.x * blockDim.x + threadIdx.x;
    if (i < n) atomicAdd(&cnt[batch[i]], 1);
}
__global__ void scan_kernel(const int* __restrict__ deg, int* __restrict__ rowptr,
                            int* __restrict__ cursor, const int* __restrict__ cnt,
                            int* __restrict__ gstart, int n) {
    __shared__ int sh[1024];
    __shared__ int carry;
    int t = threadIdx.x;
    if (t == 0) carry = 0;
    __syncthreads();
    for (int base = 0; base < n; base += 1024) {
        int idx = base + t;
        int v = (idx < n) ? deg[idx] : 0;
        sh[t] = v;
        __syncthreads();
        for (int off = 1; off < 1024; off <<= 1) {
            int add = (t >= off) ? sh[t - off] : 0;
            __syncthreads();
            sh[t] += add;
            __syncthreads();
        }
        int ex = sh[t] - v;
        int cbase = carry;
        if (idx < n) { rowptr[idx] = cbase + ex; cursor[idx] = cbase + ex; }
        __syncthreads();
        if (t == 1023) carry = cbase + sh[1023];
        __syncthreads();
    }
    if (t == 0) {
        rowptr[n] = carry;
        int s = 0;
        for (int g = 0; g < GG; g++) { gstart[g] = s; s += cnt[g]; }
        gstart[GG] = s;
    }
}
__global__ void fill_csr_kernel(const int* __restrict__ dst, int* __restrict__ cursor,
                                int* __restrict__ eidx, int E) {
    int e = blockIdx.x * blockDim.x + threadIdx.x;
    if (e < E) {
        int p = atomicAdd(&cursor[dst[e]], 1);
        eidx[p] = e;
    }
}

// ---------------- weight convert: W[K,OC] fp32 -> Wt[OC][KPAD] bf16 hi/lo ---
__global__ void convert_w_kernel(const float* __restrict__ W,
                                 __nv_bfloat16* __restrict__ Wth,
                                 __nv_bfloat16* __restrict__ Wtl,
                                 int K, int OC, int KPAD) {
    int idx = blockIdx.x * blockDim.x + threadIdx.x;
    if (idx >= OC * KPAD) return;
    int n = idx / KPAD, k = idx % KPAD;
    float w = (k < K) ? W[(size_t)k * OC + n] : 0.f;
    __nv_bfloat16 h = __float2bfloat16_rn(w);
    Wth[idx] = h;
    Wtl[idx] = __float2bfloat16_rn(w - __bfloat162float(h));
}

// ---------------- tensor-core GEMM via mma.sync, fused BN stats ------------
// out[e, 0:OC] = A[e, 0:K] @ W[K, OC] + bias   (fp32 accumulate)
// A and W both split bf16 hi+lo; 3 MMAs per tile (AhBh + AhBl + AlBh).
// Also accumulates per-column sum / sum-of-squares into stat_sum / stat_sq.
// Block tile: 128 x BN.  8 warps = 4(M) x 2(N).  Warp tile: 32 x BN/2.
// SAS=40 bf16 (80B row stride): multiple of 16B, and 8 consecutive rows map
// to offsets {0,80,32,112,64,16,96,48} mod 128 -> conflict-free ldmatrix.
template <int C, int K, int OC, int BN, bool GATHER>
__global__ __launch_bounds__(256)
void mgemm_kernel(const float* __restrict__ feats,
                  const int* __restrict__ src, const int* __restrict__ dst,
                  const float* __restrict__ an, const float* __restrict__ cn,
                  const __nv_bfloat16* __restrict__ Wth,
                  const __nv_bfloat16* __restrict__ Wtl,
                  const float* __restrict__ bias,
                  float* __restrict__ out,
                  float* __restrict__ stat_sum, float* __restrict__ stat_sq,
                  int E) {
    constexpr int KPAD = (K + 31) / 32 * 32;
    constexpr int NCH = KPAD / 32;
    constexpr int NT = BN / 16;          // n8-tiles per warp (warp N = BN/2)
    constexpr int SAS = 40;

    __shared__ __align__(16) __nv_bfloat16 sAh[128 * SAS], sAl[128 * SAS];
    __shared__ __align__(16) __nv_bfloat16 sBh[BN * SAS], sBl[BN * SAS];
    __shared__ int sdst[128], ssrc[128];

    const int tid = threadIdx.x;
    const int lane = tid & 31;
    const int wid = tid >> 5;
    const int wm = wid & 3;              // 0..3 over M
    const int wn = wid >> 2;             // 0..1 over N
    const int e0 = blockIdx.x * 128;
    const int col0 = blockIdx.y * BN;

    const uint32_t sAh_u = smem_u32(sAh);
    const uint32_t sAl_u = smem_u32(sAl);
    const uint32_t sBh_u = smem_u32(sBh);
    const uint32_t sBl_u = smem_u32(sBl);

    if (GATHER && tid < 128) {
        int e = e0 + tid;
        int ee = (e < E) ? e : (E - 1);
        sdst[tid] = dst[ee];
        ssrc[tid] = src[ee];
    }
    __syncthreads();

    float acc[2][NT][4];
#pragma unroll
    for (int mt = 0; mt < 2; mt++)
#pragma unroll
        for (int nt = 0; nt < NT; nt++)
#pragma unroll
            for (int j = 0; j < 4; j++) acc[mt][nt][j] = 0.f;

    const int arow = tid >> 1;           // A production: row handled
    const int acg = (tid & 1) * 16;      // 16 cols within 32-col chunk

    // ldmatrix lane->address precompute
    const int a_lrow = (lane & 7) + ((lane >> 3) & 1) * 8;
    const int a_lcol = (lane >> 4) * 8;
    const int b_lrow = (lane & 7) + (lane >> 4) * 8;
    const int b_lcol = ((lane >> 3) & 1) * 8;

    for (int ch = 0; ch < NCH; ch++) {
        // ---- produce A chunk (128 x 32), hi/lo split ----
        {
            int nd = 0, ns = 0;
            if (GATHER) { nd = sdst[arow]; ns = ssrc[arow]; }
            const int e = e0 + arow;
#pragma unroll
            for (int u = 0; u < 4; u++) {
                const int k = ch * 32 + acg + u * 4;
                float4 v;
                if (GATHER) {
                    if (C % 4 == 0) {
                        if (k < C) {
                            v = *reinterpret_cast<const float4*>(&feats[(size_t)nd * C + k]);
                        } else {
                            float4 xs = *reinterpret_cast<const float4*>(&feats[(size_t)ns * C + (k - C)]);
                            float4 xd = *reinterpret_cast<const float4*>(&feats[(size_t)nd * C + (k - C)]);
                            v = make_float4(xs.x - xd.x, xs.y - xd.y, xs.z - xd.z, xs.w - xd.w);
                        }
                    } else {  // scalar path (C=7, K=14, KPAD=32)
                        float t[4];
#pragma unroll
                        for (int j = 0; j < 4; j++) {
                            int kk = k + j;
                            if (kk < C) t[j] = feats[(size_t)nd * C + kk];
                            else if (kk < K) t[j] = feats[(size_t)ns * C + (kk - C)] - feats[(size_t)nd * C + (kk - C)];
                            else t[j] = 0.f;
                        }
                        v = make_float4(t[0], t[1], t[2], t[3]);
                    }
                } else {
                    if (e < E) {
                        float4 t = *reinterpret_cast<const float4*>(&feats[(size_t)e * K + k]);
                        v.x = fmaxf(t.x * an[k + 0] + cn[k + 0], 0.f);
                        v.y = fmaxf(t.y * an[k + 1] + cn[k + 1], 0.f);
                        v.z = fmaxf(t.z * an[k + 2] + cn[k + 2], 0.f);
                        v.w = fmaxf(t.w * an[k + 3] + cn[k + 3], 0.f);
                    } else {
                        v = make_float4(0.f, 0.f, 0.f, 0.f);
                    }
                }
                __nv_bfloat162 h01 = __float22bfloat162_rn(make_float2(v.x, v.y));
                __nv_bfloat162 h23 = __float22bfloat162_rn(make_float2(v.z, v.w));
                float2 hf01 = __bfloat1622float2(h01);
                float2 hf23 = __bfloat1622float2(h23);
                __nv_bfloat162 l01 = __float22bfloat162_rn(make_float2(v.x - hf01.x, v.y - hf01.y));
                __nv_bfloat162 l23 = __float22bfloat162_rn(make_float2(v.z - hf23.x, v.w - hf23.y));
                uint2 H, L;
                H.x = *reinterpret_cast<uint32_t*>(&h01);
                H.y = *reinterpret_cast<uint32_t*>(&h23);
                L.x = *reinterpret_cast<uint32_t*>(&l01);
                L.y = *reinterpret_cast<uint32_t*>(&l23);
                int so = arow * SAS + acg + u * 4;
                *reinterpret_cast<uint2*>(&sAh[so]) = H;
                *reinterpret_cast<uint2*>(&sAl[so]) = L;
            }
        }
        // ---- load B chunk (BN x 32), hi + lo ----
        {
#pragma unroll
            for (int i = tid; i < BN * 4; i += 256) {
                int n = i >> 2, u = i & 3;
                size_t soff = (size_t)(col0 + n) * KPAD + ch * 32 + u * 8;
                int doff = n * SAS + u * 8;
                *reinterpret_cast<uint4*>(&sBh[doff]) =
                    *reinterpret_cast<const uint4*>(Wth + soff);
                *reinterpret_cast<uint4*>(&sBl[doff]) =
                    *reinterpret_cast<const uint4*>(Wtl + soff);
            }
        }
        __syncthreads();

        // ---- 2 x k16 MMA steps (ldmatrix fragment loads) ----
#pragma unroll
        for (int ks = 0; ks < 2; ks++) {
            const int kb = ks * 16;
            uint32_t ah[2][4], al[2][4];
#pragma unroll
            for (int mt = 0; mt < 2; mt++) {
                int r = wm * 32 + mt * 16 + a_lrow;
                uint32_t off = (uint32_t)(r * SAS + kb + a_lcol) * 2;
                LDSM_X4(ah[mt][0], ah[mt][1], ah[mt][2], ah[mt][3], sAh_u + off);
                LDSM_X4(al[mt][0], al[mt][1], al[mt][2], al[mt][3], sAl_u + off);
            }
#pragma unroll
            for (int p = 0; p < NT / 2; p++) {
                int n0 = wn * (BN / 2) + p * 16;
                uint32_t boff = (uint32_t)((n0 + b_lrow) * SAS + kb + b_lcol) * 2;
                uint32_t bh[4], bl[4];
                LDSM_X4(bh[0], bh[1], bh[2], bh[3], sBh_u + boff);
                LDSM_X4(bl[0], bl[1], bl[2], bl[3], sBl_u + boff);
#pragma unroll
                for (int mt = 0; mt < 2; mt++) {
                    MMA_BF16(acc[mt][2 * p], ah[mt], (&bh[0]));
                    MMA_BF16(acc[mt][2 * p], ah[mt], (&bl[0]));
                    MMA_BF16(acc[mt][2 * p], al[mt], (&bh[0]));
                    MMA_BF16(acc[mt][2 * p + 1], ah[mt], (&bh[2]));
                    MMA_BF16(acc[mt][2 * p + 1], ah[mt], (&bl[2]));
                    MMA_BF16(acc[mt][2 * p + 1], al[mt], (&bh[2]));
                }
            }
        }
        __syncthreads();
    }

    // ---- epilogue: bias + store + fused BN stats ----
    float* ssum = reinterpret_cast<float*>(sAh);   // reuse A smem (BN floats)
    float* ssq = ssum + BN;
    for (int i = tid; i < 2 * BN; i += 256) ssum[i] = 0.f;
    __syncthreads();

#pragma unroll
    for (int nt = 0; nt < NT; nt++) {
        const int colw = wn * (BN / 2) + nt * 8 + (lane & 3) * 2;
        const int col = col0 + colw;
        const float b0 = bias[col], b1 = bias[col + 1];
        float s0 = 0.f, q0 = 0.f, s1 = 0.f, q1 = 0.f;
#pragma unroll
        for (int mt = 0; mt < 2; mt++) {
            const int r = wm * 32 + mt * 16 + (lane >> 2);
            const int e1 = e0 + r, e2 = e0 + r + 8;
            float v0 = acc[mt][nt][0] + b0, v1 = acc[mt][nt][1] + b1;
            float v2 = acc[mt][nt][2] + b0, v3 = acc[mt][nt][3] + b1;
            if (e1 < E) {
                *reinterpret_cast<float2*>(&out[(size_t)e1 * OC + col]) = make_float2(v0, v1);
                s0 += v0; q0 += v0 * v0; s1 += v1; q1 += v1 * v1;
            }
            if (e2 < E) {
                *reinterpret_cast<float2*>(&out[(size_t)e2 * OC + col]) = make_float2(v2, v3);
                s0 += v2; q0 += v2 * v2; s1 += v3; q1 += v3 * v3;
            }
        }
#pragma unroll
        for (int m = 4; m <= 16; m <<= 1) {
            s0 += __shfl_xor_sync(0xffffffff, s0, m);
            q0 += __shfl_xor_sync(0xffffffff, q0, m);
            s1 += __shfl_xor_sync(0xffffffff, s1, m);
            q1 += __shfl_xor_sync(0xffffffff, q1, m);
        }
        if ((lane >> 2) == 0) {
            atomicAdd(&ssum[colw], s0);
            atomicAdd(&ssq[colw], q0);
            atomicAdd(&ssum[colw + 1], s1);
            atomicAdd(&ssq[colw + 1], q1);
        }
    }
    __syncthreads();
    for (int i = tid; i < BN; i += 256) {
        atomicAdd(&stat_sum[col0 + i], ssum[i]);
        atomicAdd(&stat_sq[col0 + i], ssq[i]);
    }
}

// ---------------- BN finalize ----------------
__global__ void finalize_kernel(const float* __restrict__ sum, const float* __restrict__ sq,
                                const float* __restrict__ gamma, const float* __restrict__ beta,
                                float* __restrict__ a, float* __restrict__ c,
                                int OC, float invE) {
    int i = blockIdx.x * blockDim.x + threadIdx.x;
    if (i < OC) {
        float m = sum[i] * invE;
        float var = sq[i] * invE - m * m;
        float rs = rsqrtf(var + 1e-5f);
        float ai = gamma[i] * rs;
        a[i] = ai;
        c[i] = beta[i] - m * ai;
    }
}

// ---------------- normalize + relu + mean-aggregate (CSR, warp per node) ----
template <int OC>
__global__ __launch_bounds__(256)
void aggregate_kernel(const float* __restrict__ t, const int* __restrict__ rowptr,
                      const int* __restrict__ eidx, const float* __restrict__ a,
                      const float* __restrict__ c, float* __restrict__ hout, int n) {
    int warp = (blockIdx.x * blockDim.x + threadIdx.x) >> 5;
    int lane = threadIdx.x & 31;
    if (warp >= n) return;
    constexpr int R = OC / 32;
    float av[R], cv[R], acc[R];
#pragma unroll
    for (int j = 0; j < R; j++) {
        int ch = j * 32 + lane;
        av[j] = a[ch]; cv[j] = c[ch]; acc[j] = 0.f;
    }
    int beg = rowptr[warp], end = rowptr[warp + 1];
    for (int p = beg; p < end; p++) {
        int e = eidx[p];
        const float* rowp = t + (size_t)e * OC;
#pragma unroll
        for (int j = 0; j < R; j++) {
            float v = rowp[j * 32 + lane];
            acc[j] += fmaxf(v * av[j] + cv[j], 0.f);
        }
    }
    float inv = 1.f / fmaxf((float)(end - beg), 1.f);
#pragma unroll
    for (int j = 0; j < R; j++) hout[(size_t)warp * OC + j * 32 + lane] = acc[j] * inv;
}

// ---------------- global mean pool + head ----------------
__global__ void pool_kernel(const float* __restrict__ h, const int* __restrict__ gstart,
                            float* __restrict__ pool) {
    int g = blockIdx.x;
    int ch = threadIdx.x;
    int beg = gstart[g], end = gstart[g + 1];
    float s = 0.f;
    for (int nidx = beg; nidx < end; nidx++) s += h[(size_t)nidx * 256 + ch];
    pool[g * 256 + ch] = s / fmaxf((float)(end - beg), 1.f);
}
__global__ void head1_kernel(const float* __restrict__ pool, const float* __restrict__ W,
                             const float* __restrict__ b, float* __restrict__ z) {
    int g = blockIdx.x, j = threadIdx.x;
    __shared__ float sp[256];
    sp[j] = pool[g * 256 + j];
    sp[j + 128] = pool[g * 256 + j + 128];
    __syncthreads();
    float s = b[j];
#pragma unroll 8
    for (int k = 0; k < 256; k++) s += sp[k] * W[k * 128 + j];
    z[g * 128 + j] = fmaxf(s, 0.f);
}
__global__ void head2_kernel(const float* __restrict__ z, const float* __restrict__ W,
                             const float* __restrict__ b, float* __restrict__ out) {
    int t = threadIdx.x;
    int g = t >> 1, j = t & 1;
    float s = b[j];
#pragma unroll 8
    for (int k = 0; k < 128; k++) s += z[g * 128 + k] * W[k * 2 + j];
    out[g * 2 + j] = s;
}

// ---------------- launch ----------------
extern "C" void kernel_launch(void* const* d_in, const int* in_sizes, int n_in,
                              void* d_out, int out_size) {
    const float* x     = (const float*)d_in[0];
    const int*   ei    = (const int*)d_in[1];
    const int*   batch = (const int*)d_in[2];

    const int E = in_sizes[1] / 2;
    const int n = in_sizes[2];
    const int* srcp = ei;
    const int* dstp = ei + E;

    const float* W[3][2];  const float* B[3][2];
    const float* Gm[3][2]; const float* Bt[3][2];
    for (int l = 0; l < 3; l++) {
        int base = 3 + l * 8;
        W[l][0]  = (const float*)d_in[base + 0];
        B[l][0]  = (const float*)d_in[base + 1];
        Gm[l][0] = (const float*)d_in[base + 2];
        Bt[l][0] = (const float*)d_in[base + 3];
        W[l][1]  = (const float*)d_in[base + 4];
        B[l][1]  = (const float*)d_in[base + 5];
        Gm[l][1] = (const float*)d_in[base + 6];
        Bt[l][1] = (const float*)d_in[base + 7];
    }
    const float* hW1 = (const float*)d_in[27];
    const float* hb1 = (const float*)d_in[28];
    const float* hW2 = (const float*)d_in[29];
    const float* hb2 = (const float*)d_in[30];

    float *t1, *t2, *hA, *hB, *stats, *norm, *pool, *zbuf;
    int *deg, *rowptr, *cursor, *eidx, *cnt, *gstart;
    __nv_bfloat16 *wth, *wtl;
    cudaGetSymbolAddress((void**)&t1, g_t1);
    cudaGetSymbolAddress((void**)&t2, g_t2);
    cudaGetSymbolAddress((void**)&hA, g_hA);
    cudaGetSymbolAddress((void**)&hB, g_hB);
    cudaGetSymbolAddress((void**)&stats, g_stats);
    cudaGetSymbolAddress((void**)&norm, g_norm);
    cudaGetSymbolAddress((void**)&deg, g_deg);
    cudaGetSymbolAddress((void**)&rowptr, g_rowptr);
    cudaGetSymbolAddress((void**)&cursor, g_cursor);
    cudaGetSymbolAddress((void**)&eidx, g_eidx);
    cudaGetSymbolAddress((void**)&cnt, g_cnt);
    cudaGetSymbolAddress((void**)&gstart, g_gstart);
    cudaGetSymbolAddress((void**)&pool, g_pool);
    cudaGetSymbolAddress((void**)&zbuf, g_zbuf);
    cudaGetSymbolAddress((void**)&wth, g_wth);
    cudaGetSymbolAddress((void**)&wtl, g_wtl);

    float* sum1 = stats + 0;   float* sq1 = stats + 256;
    float* sum2 = stats + 512; float* sq2 = stats + 768;
    float* a1 = norm + 0;   float* c1 = norm + 256;
    float* a2 = norm + 512; float* c2 = norm + 768;

    // transposed weight buffers: {L1g1(64x32), L1g2(64x64), L2g1(128x128),
    //                             L2g2(128x128), L3g1(256x256), L3g2(256x256)}
    const int wt_off[6] = {0, 2048, 6144, 22528, 38912, 104448};

    const float invE = 1.f / (float)E;
    const int EB = (E + 127) / 128;
    const int EG = (E + 255) / 256;
    const int NG = (n + 255) / 256;
    const int AGG = (n * 32 + 255) / 256;

    // ---- CSR build + weight conversion ----
    cudaMemsetAsync(deg, 0, n * sizeof(int));
    cudaMemsetAsync(cnt, 0, GG * sizeof(int));
    hist_deg_kernel<<<EG, 256>>>(dstp, deg, E);
    hist_cnt_kernel<<<NG, 256>>>(batch, cnt, n);
    scan_kernel<<<1, 1024>>>(deg, rowptr, cursor, cnt, gstart, n);
    fill_csr_kernel<<<EG, 256>>>(dstp, cursor, eidx, E);

    convert_w_kernel<<<(64 * 32 + 255) / 256, 256>>>(W[0][0], wth + wt_off[0], wtl + wt_off[0], 14, 64, 32);
    convert_w_kernel<<<(64 * 64 + 255) / 256, 256>>>(W[0][1], wth + wt_off[1], wtl + wt_off[1], 64, 64, 64);
    convert_w_kernel<<<(128 * 128 + 255) / 256, 256>>>(W[1][0], wth + wt_off[2], wtl + wt_off[2], 128, 128, 128);
    convert_w_kernel<<<(128 * 128 + 255) / 256, 256>>>(W[1][1], wth + wt_off[3], wtl + wt_off[3], 128, 128, 128);
    convert_w_kernel<<<(256 * 256 + 255) / 256, 256>>>(W[2][0], wth + wt_off[4], wtl + wt_off[4], 256, 256, 256);
    convert_w_kernel<<<(256 * 256 + 255) / 256, 256>>>(W[2][1], wth + wt_off[5], wtl + wt_off[5], 256, 256, 256);

    // ---- layer 1: 7 -> 64 ----
    cudaMemsetAsync(stats, 0, 1024 * sizeof(float));
    mgemm_kernel<7, 14, 64, 64, true><<<dim3(EB, 1), 256>>>(
        x, srcp, dstp, nullptr, nullptr, wth + wt_off[0], wtl + wt_off[0], B[0][0], t1, sum1, sq1, E);
    finalize_kernel<<<1, 64>>>(sum1, sq1, Gm[0][0], Bt[0][0], a1, c1, 64, invE);
    mgemm_kernel<0, 64, 64, 64, false><<<dim3(EB, 1), 256>>>(
        t1, nullptr, nullptr, a1, c1, wth + wt_off[1], wtl + wt_off[1], B[0][1], t2, sum2, sq2, E);
    finalize_kernel<<<1, 64>>>(sum2, sq2, Gm[0][1], Bt[0][1], a2, c2, 64, invE);
    aggregate_kernel<64><<<AGG, 256>>>(t2, rowptr, eidx, a2, c2, hA, n);

    // ---- layer 2: 64 -> 128 ----
    cudaMemsetAsync(stats, 0, 1024 * sizeof(float));
    mgemm_kernel<64, 128, 128, 128, true><<<dim3(EB, 1), 256>>>(
        hA, srcp, dstp, nullptr, nullptr, wth + wt_off[2], wtl + wt_off[2], B[1][0], t1, sum1, sq1, E);
    finalize_kernel<<<1, 128>>>(sum1, sq1, Gm[1][0], Bt[1][0], a1, c1, 128, invE);
    mgemm_kernel<0, 128, 128, 128, false><<<dim3(EB, 1), 256>>>(
        t1, nullptr, nullptr, a1, c1, wth + wt_off[3], wtl + wt_off[3], B[1][1], t2, sum2, sq2, E);
    finalize_kernel<<<1, 128>>>(sum2, sq2, Gm[1][1], Bt[1][1], a2, c2, 128, invE);
    aggregate_kernel<128><<<AGG, 256>>>(t2, rowptr, eidx, a2, c2, hB, n);

    // ---- layer 3: 128 -> 256 ----
    cudaMemsetAsync(stats, 0, 1024 * sizeof(float));
    mgemm_kernel<128, 256, 256, 128, true><<<dim3(EB, 2), 256>>>(
        hB, srcp, dstp, nullptr, nullptr, wth + wt_off[4], wtl + wt_off[4], B[2][0], t1, sum1, sq1, E);
    finalize_kernel<<<1, 256>>>(sum1, sq1, Gm[2][0], Bt[2][0], a1, c1, 256, invE);
    mgemm_kernel<0, 256, 256, 128, false><<<dim3(EB, 2), 256>>>(
        t1, nullptr, nullptr, a1, c1, wth + wt_off[5], wtl + wt_off[5], B[2][1], t2, sum2, sq2, E);
    finalize_kernel<<<1, 256>>>(sum2, sq2, Gm[2][1], Bt[2][1], a2, c2, 256, invE);
    aggregate_kernel<256><<<AGG, 256>>>(t2, rowptr, eidx, a2, c2, hA, n);

    // ---- pool + head ----
    pool_kernel<<<GG, 256>>>(hA, gstart, pool);
    head1_kernel<<<GG, 128>>>(pool, hW1, hb1, zbuf);
    head2_kernel<<<1, 128>>>(zbuf, hW2, hb2, (float*)d_out);
}

// round 7
// speedup vs baseline: 1.1672x; 1.1590x over previous
#include <cuda_runtime.h>
#include <cuda_bf16.h>
#include <cstdint>

// ---------------- problem constants ----------------
#define NN 50000
#define EE 500000
#define GG 64

// ---------------- scratch (device globals; no allocation allowed) ----------
__device__ float g_t1[(size_t)EE * 256];
__device__ float g_t2[(size_t)EE * 256];
__device__ float g_hA[(size_t)NN * 256];
__device__ float g_hB[(size_t)NN * 256];
__device__ float g_stats[1024];
__device__ float g_norm[1024];
__device__ int   g_deg[NN];
__device__ int   g_rowptr[NN + 1];
__device__ int   g_cursor[NN];
__device__ int   g_eidx[EE];
__device__ int   g_cnt[GG];
__device__ int   g_gstart[GG + 1];
__device__ float g_pool[GG * 256];
__device__ float g_zbuf[GG * 128];
__device__ __nv_bfloat16 g_wth[172032];
__device__ __nv_bfloat16 g_wtl[172032];

// ---------------- mma.sync / ldmatrix helpers ------------------------------
#define MMA_BF16(d, a, b)                                                        \
    asm volatile("mma.sync.aligned.m16n8k16.row.col.f32.bf16.bf16.f32 "          \
                 "{%0,%1,%2,%3}, {%4,%5,%6,%7}, {%8,%9}, {%0,%1,%2,%3};"         \
                 : "+f"((d)[0]), "+f"((d)[1]), "+f"((d)[2]), "+f"((d)[3])        \
                 : "r"((a)[0]), "r"((a)[1]), "r"((a)[2]), "r"((a)[3]),           \
                   "r"((b)[0]), "r"((b)[1]))

#define LDSM_X4(r0, r1, r2, r3, addr)                                            \
    asm volatile("ldmatrix.sync.aligned.m8n8.x4.shared.b16 {%0,%1,%2,%3}, [%4];" \
                 : "=r"(r0), "=r"(r1), "=r"(r2), "=r"(r3) : "r"(addr))

__device__ __forceinline__ uint32_t smem_u32(const void* p) {
    uint32_t a;
    asm("{ .reg .u64 t; cvta.to.shared.u64 t, %1; cvt.u32.u64 %0, t; }" : "=r"(a) : "l"(p));
    return a;
}

// ---------------- small utility kernels ----------------
__global__ void zero_stats_kernel(float* __restrict__ s) {
    int i = threadIdx.x;
#pragma unroll
    for (int j = 0; j < 4; j++) s[i + j * 256] = 0.f;
}

__global__ void hist_deg_kernel(const int* __restrict__ dst, int* __restrict__ deg, int E) {
    int e = blockIdx.x * blockDim.x + threadIdx.x;
    if (e < E) atomicAdd(&deg[dst[e]], 1);
}
__global__ void hist_cnt_kernel(const int* __restrict__ batch, int* __restrict__ cnt, int n) {
    int i = blockIdx.x * blockDim.x + threadIdx.x;
    if (i < n) atomicAdd(&cnt[batch[i]], 1);
}
__global__ void scan_kernel(const int* __restrict__ deg, int* __restrict__ rowptr,
                            int* __restrict__ cursor, const int* __restrict__ cnt,
                            int* __restrict__ gstart, int n) {
    __shared__ int sh[1024];
    __shared__ int carry;
    int t = threadIdx.x;
    if (t == 0) carry = 0;
    __syncthreads();
    for (int base = 0; base < n; base += 1024) {
        int idx = base + t;
        int v = (idx < n) ? deg[idx] : 0;
        sh[t] = v;
        __syncthreads();
        for (int off = 1; off < 1024; off <<= 1) {
            int add = (t >= off) ? sh[t - off] : 0;
            __syncthreads();
            sh[t] += add;
            __syncthreads();
        }
        int ex = sh[t] - v;
        int cbase = carry;
        if (idx < n) { rowptr[idx] = cbase + ex; cursor[idx] = cbase + ex; }
        __syncthreads();
        if (t == 1023) carry = cbase + sh[1023];
        __syncthreads();
    }
    if (t == 0) {
        rowptr[n] = carry;
        int s = 0;
        for (int g = 0; g < GG; g++) { gstart[g] = s; s += cnt[g]; }
        gstart[GG] = s;
    }
}
__global__ void fill_csr_kernel(const int* __restrict__ dst, int* __restrict__ cursor,
                                int* __restrict__ eidx, int E) {
    int e = blockIdx.x * blockDim.x + threadIdx.x;
    if (e < E) {
        int p = atomicAdd(&cursor[dst[e]], 1);
        eidx[p] = e;
    }
}

__global__ void convert_w_kernel(const float* __restrict__ W,
                                 __nv_bfloat16* __restrict__ Wth,
                                 __nv_bfloat16* __restrict__ Wtl,
                                 int K, int OC, int KPAD) {
    int idx = blockIdx.x * blockDim.x + threadIdx.x;
    if (idx >= OC * KPAD) return;
    int n = idx / KPAD, k = idx % KPAD;
    float w = (k < K) ? W[(size_t)k * OC + n] : 0.f;
    __nv_bfloat16 h = __float2bfloat16_rn(w);
    Wth[idx] = h;
    Wtl[idx] = __float2bfloat16_rn(w - __bfloat162float(h));
}

// ---------------- tensor-core GEMM, reg-prefetch pipelined, fused stats ----
// Block tile 128 x 64.  8 warps = 4(M) x 2(N), warp tile 32 x 32.
// 3 MMAs per k16 tile (AhBh + AhBl + AlBh) for ~fp32 accuracy.
// Mainloop: store chunk ch to smem -> sync -> prefetch loads for ch+1 ->
//           ldmatrix+MMA on ch -> sync.   Loads overlap MMA.
template <int C, int K, int OC, bool GATHER>
__global__ __launch_bounds__(256, 2)
void mgemm_kernel(const float* __restrict__ feats,
                  const int* __restrict__ src, const int* __restrict__ dst,
                  const float* __restrict__ an, const float* __restrict__ cn,
                  const __nv_bfloat16* __restrict__ Wth,
                  const __nv_bfloat16* __restrict__ Wtl,
                  const float* __restrict__ bias,
                  float* __restrict__ out,
                  float* __restrict__ stat_sum, float* __restrict__ stat_sq,
                  int E) {
    constexpr int BN = 64;
    constexpr int KPAD = (K + 31) / 32 * 32;
    constexpr int NCH = KPAD / 32;
    constexpr int NT = BN / 16;          // 4 n8-tiles per warp
    constexpr int SAS = 40;              // 80B stride: conflict-free ldmatrix

    __shared__ __align__(16) __nv_bfloat16 sAh[128 * SAS], sAl[128 * SAS];
    __shared__ __align__(16) __nv_bfloat16 sBh[BN * SAS], sBl[BN * SAS];
    __shared__ int sdst[128], ssrc[128];
    __shared__ float sAn[KPAD], sCn[KPAD];

    const int tid = threadIdx.x;
    const int lane = tid & 31;
    const int wid = tid >> 5;
    const int wm = wid & 3;
    const int wn = wid >> 2;
    const int e0 = blockIdx.x * 128;
    const int col0 = blockIdx.y * BN;

    const uint32_t sAh_u = smem_u32(sAh);
    const uint32_t sAl_u = smem_u32(sAl);
    const uint32_t sBh_u = smem_u32(sBh);
    const uint32_t sBl_u = smem_u32(sBl);

    if (GATHER) {
        if (tid < 128) {
            int e = e0 + tid;
            int ee = (e < E) ? e : (E - 1);
            sdst[tid] = dst[ee];
            ssrc[tid] = src[ee];
        }
    } else {
        for (int i = tid; i < K; i += 256) { sAn[i] = an[i]; sCn[i] = cn[i]; }
    }
    __syncthreads();

    float acc[2][NT][4];
#pragma unroll
    for (int mt = 0; mt < 2; mt++)
#pragma unroll
        for (int nt = 0; nt < NT; nt++)
#pragma unroll
            for (int j = 0; j < 4; j++) acc[mt][nt][j] = 0.f;

    const int arow = tid >> 1;
    const int acg = (tid & 1) * 16;
    int nd = 0, ns = 0;
    if (GATHER) { nd = sdst[arow]; ns = ssrc[arow]; }

    // B prefetch mapping: one uint4 (hi) + one (lo) per thread per chunk
    const int bn_ = tid >> 2;            // 0..63
    const int bu_ = tid & 3;             // 0..3
    const int bdoff = bn_ * SAS + bu_ * 8;

    float4 P[4], Q[4];
    uint4 BHr, BLr;

    // ---- prefetch loaders (NO dependent math — regs only) ----
    auto load_chunk = [&](int ch) {
        const int k0 = ch * 32 + acg;
        if (GATHER) {
            if (C % 4 == 0) {
                if (k0 < C) {
#pragma unroll
                    for (int u = 0; u < 4; u++)
                        P[u] = *reinterpret_cast<const float4*>(&feats[(size_t)nd * C + k0 + u * 4]);
                } else {
#pragma unroll
                    for (int u = 0; u < 4; u++) {
                        P[u] = *reinterpret_cast<const float4*>(&feats[(size_t)ns * C + (k0 - C) + u * 4]);
                        Q[u] = *reinterpret_cast<const float4*>(&feats[(size_t)nd * C + (k0 - C) + u * 4]);
                    }
                }
            } else {  // C=7 scalar path (NCH==1)
#pragma unroll
                for (int u = 0; u < 4; u++) {
                    float t[4];
#pragma unroll
                    for (int j = 0; j < 4; j++) {
                        int kk = k0 + u * 4 + j;
                        if (kk < C) t[j] = feats[(size_t)nd * C + kk];
                        else if (kk < K) t[j] = feats[(size_t)ns * C + (kk - C)] - feats[(size_t)nd * C + (kk - C)];
                        else t[j] = 0.f;
                    }
                    P[u] = make_float4(t[0], t[1], t[2], t[3]);
                }
            }
        } else {
            const int e = e0 + arow;
            if (e < E) {
#pragma unroll
                for (int u = 0; u < 4; u++)
                    P[u] = *reinterpret_cast<const float4*>(&feats[(size_t)e * K + k0 + u * 4]);
            } else {
#pragma unroll
                for (int u = 0; u < 4; u++) P[u] = make_float4(0.f, 0.f, 0.f, 0.f);
            }
        }
    };
    auto load_B = [&](int ch) {
        size_t soff = (size_t)(col0 + bn_) * KPAD + ch * 32 + bu_ * 8;
        BHr = *reinterpret_cast<const uint4*>(Wth + soff);
        BLr = *reinterpret_cast<const uint4*>(Wtl + soff);
    };
    // ---- convert + store prefetched chunk to smem ----
    auto store_chunk = [&](int ch) {
        const int k0 = ch * 32 + acg;
#pragma unroll
        for (int u = 0; u < 4; u++) {
            float4 v;
            if (GATHER) {
                if (C % 4 == 0) {
                    if (k0 < C) v = P[u];
                    else v = make_float4(P[u].x - Q[u].x, P[u].y - Q[u].y,
                                         P[u].z - Q[u].z, P[u].w - Q[u].w);
                } else {
                    v = P[u];
                }
            } else {
                if (e0 + arow < E) {
                    const int k = k0 + u * 4;
                    v.x = fmaxf(P[u].x * sAn[k + 0] + sCn[k + 0], 0.f);
                    v.y = fmaxf(P[u].y * sAn[k + 1] + sCn[k + 1], 0.f);
                    v.z = fmaxf(P[u].z * sAn[k + 2] + sCn[k + 2], 0.f);
                    v.w = fmaxf(P[u].w * sAn[k + 3] + sCn[k + 3], 0.f);
                } else {
                    v = make_float4(0.f, 0.f, 0.f, 0.f);
                }
            }
            __nv_bfloat162 h01 = __float22bfloat162_rn(make_float2(v.x, v.y));
            __nv_bfloat162 h23 = __float22bfloat162_rn(make_float2(v.z, v.w));
            float2 hf01 = __bfloat1622float2(h01);
            float2 hf23 = __bfloat1622float2(h23);
            __nv_bfloat162 l01 = __float22bfloat162_rn(make_float2(v.x - hf01.x, v.y - hf01.y));
            __nv_bfloat162 l23 = __float22bfloat162_rn(make_float2(v.z - hf23.x, v.w - hf23.y));
            uint2 H, L;
            H.x = *reinterpret_cast<uint32_t*>(&h01);
            H.y = *reinterpret_cast<uint32_t*>(&h23);
            L.x = *reinterpret_cast<uint32_t*>(&l01);
            L.y = *reinterpret_cast<uint32_t*>(&l23);
            int so = arow * SAS + acg + u * 4;
            *reinterpret_cast<uint2*>(&sAh[so]) = H;
            *reinterpret_cast<uint2*>(&sAl[so]) = L;
        }
        *reinterpret_cast<uint4*>(&sBh[bdoff]) = BHr;
        *reinterpret_cast<uint4*>(&sBl[bdoff]) = BLr;
    };

    // ldmatrix lane->address precompute
    const int a_lrow = (lane & 7) + ((lane >> 3) & 1) * 8;
    const int a_lcol = (lane >> 4) * 8;
    const int b_lrow = (lane & 7) + (lane >> 4) * 8;
    const int b_lcol = ((lane >> 3) & 1) * 8;

    load_chunk(0);
    load_B(0);

    for (int ch = 0; ch < NCH; ch++) {
        store_chunk(ch);
        __syncthreads();

        // prefetch next chunk while MMA runs
        if (ch + 1 < NCH) { load_chunk(ch + 1); load_B(ch + 1); }

        // ---- MMA phase ----
#pragma unroll
        for (int ks = 0; ks < 2; ks++) {
            const int kb = ks * 16;
            uint32_t ah[2][4], al[2][4];
#pragma unroll
            for (int mt = 0; mt < 2; mt++) {
                int r = wm * 32 + mt * 16 + a_lrow;
                uint32_t off = (uint32_t)(r * SAS + kb + a_lcol) * 2;
                LDSM_X4(ah[mt][0], ah[mt][1], ah[mt][2], ah[mt][3], sAh_u + off);
                LDSM_X4(al[mt][0], al[mt][1], al[mt][2], al[mt][3], sAl_u + off);
            }
#pragma unroll
            for (int p = 0; p < NT / 2; p++) {
                int n0 = wn * (BN / 2) + p * 16;
                uint32_t boff = (uint32_t)((n0 + b_lrow) * SAS + kb + b_lcol) * 2;
                uint32_t bh[4], bl[4];
                LDSM_X4(bh[0], bh[1], bh[2], bh[3], sBh_u + boff);
                LDSM_X4(bl[0], bl[1], bl[2], bl[3], sBl_u + boff);
#pragma unroll
                for (int mt = 0; mt < 2; mt++) {
                    MMA_BF16(acc[mt][2 * p], ah[mt], (&bh[0]));
                    MMA_BF16(acc[mt][2 * p], ah[mt], (&bl[0]));
                    MMA_BF16(acc[mt][2 * p], al[mt], (&bh[0]));
                    MMA_BF16(acc[mt][2 * p + 1], ah[mt], (&bh[2]));
                    MMA_BF16(acc[mt][2 * p + 1], ah[mt], (&bl[2]));
                    MMA_BF16(acc[mt][2 * p + 1], al[mt], (&bh[2]));
                }
            }
        }
        __syncthreads();
    }

    // ---- epilogue: bias + store + fused BN stats ----
    float* ssum = reinterpret_cast<float*>(sAh);
    float* ssq = ssum + BN;
    for (int i = tid; i < 2 * BN; i += 256) ssum[i] = 0.f;
    __syncthreads();

#pragma unroll
    for (int nt = 0; nt < NT; nt++) {
        const int colw = wn * (BN / 2) + nt * 8 + (lane & 3) * 2;
        const int col = col0 + colw;
        const float b0 = bias[col], b1 = bias[col + 1];
        float s0 = 0.f, q0 = 0.f, s1 = 0.f, q1 = 0.f;
#pragma unroll
        for (int mt = 0; mt < 2; mt++) {
            const int r = wm * 32 + mt * 16 + (lane >> 2);
            const int e1 = e0 + r, e2 = e0 + r + 8;
            float v0 = acc[mt][nt][0] + b0, v1 = acc[mt][nt][1] + b1;
            float v2 = acc[mt][nt][2] + b0, v3 = acc[mt][nt][3] + b1;
            if (e1 < E) {
                *reinterpret_cast<float2*>(&out[(size_t)e1 * OC + col]) = make_float2(v0, v1);
                s0 += v0; q0 += v0 * v0; s1 += v1; q1 += v1 * v1;
            }
            if (e2 < E) {
                *reinterpret_cast<float2*>(&out[(size_t)e2 * OC + col]) = make_float2(v2, v3);
                s0 += v2; q0 += v2 * v2; s1 += v3; q1 += v3 * v3;
            }
        }
#pragma unroll
        for (int m = 4; m <= 16; m <<= 1) {
            s0 += __shfl_xor_sync(0xffffffff, s0, m);
            q0 += __shfl_xor_sync(0xffffffff, q0, m);
            s1 += __shfl_xor_sync(0xffffffff, s1, m);
            q1 += __shfl_xor_sync(0xffffffff, q1, m);
        }
        if ((lane >> 2) == 0) {
            atomicAdd(&ssum[colw], s0);
            atomicAdd(&ssq[colw], q0);
            atomicAdd(&ssum[colw + 1], s1);
            atomicAdd(&ssq[colw + 1], q1);
        }
    }
    __syncthreads();
    for (int i = tid; i < BN; i += 256) {
        atomicAdd(&stat_sum[col0 + i], ssum[i]);
        atomicAdd(&stat_sq[col0 + i], ssq[i]);
    }
}

// ---------------- BN finalize ----------------
__global__ void finalize_kernel(const float* __restrict__ sum, const float* __restrict__ sq,
                                const float* __restrict__ gamma, const float* __restrict__ beta,
                                float* __restrict__ a, float* __restrict__ c,
                                int OC, float invE) {
    int i = blockIdx.x * blockDim.x + threadIdx.x;
    if (i < OC) {
        float m = sum[i] * invE;
        float var = sq[i] * invE - m * m;
        float rs = rsqrtf(var + 1e-5f);
        float ai = gamma[i] * rs;
        a[i] = ai;
        c[i] = beta[i] - m * ai;
    }
}

// ---------------- normalize + relu + mean-aggregate (CSR, warp per node) ----
template <int OC>
__global__ __launch_bounds__(256)
void aggregate_kernel(const float* __restrict__ t, const int* __restrict__ rowptr,
                      const int* __restrict__ eidx, const float* __restrict__ a,
                      const float* __restrict__ c, float* __restrict__ hout, int n) {
    int warp = (blockIdx.x * blockDim.x + threadIdx.x) >> 5;
    int lane = threadIdx.x & 31;
    if (warp >= n) return;
    constexpr int R = OC / 32;
    float av[R], cv[R], acc[R];
#pragma unroll
    for (int j = 0; j < R; j++) {
        int ch = j * 32 + lane;
        av[j] = a[ch]; cv[j] = c[ch]; acc[j] = 0.f;
    }
    int beg = rowptr[warp], end = rowptr[warp + 1];
    for (int p = beg; p < end; p++) {
        int e = eidx[p];
        const float* rowp = t + (size_t)e * OC;
#pragma unroll
        for (int j = 0; j < R; j++) {
            float v = rowp[j * 32 + lane];
            acc[j] += fmaxf(v * av[j] + cv[j], 0.f);
        }
    }
    float inv = 1.f / fmaxf((float)(end - beg), 1.f);
#pragma unroll
    for (int j = 0; j < R; j++) hout[(size_t)warp * OC + j * 32 + lane] = acc[j] * inv;
}

// ---------------- global mean pool + head ----------------
__global__ void pool_kernel(const float* __restrict__ h, const int* __restrict__ gstart,
                            float* __restrict__ pool) {
    int g = blockIdx.x;
    int ch = threadIdx.x;
    int beg = gstart[g], end = gstart[g + 1];
    float s = 0.f;
    for (int nidx = beg; nidx < end; nidx++) s += h[(size_t)nidx * 256 + ch];
    pool[g * 256 + ch] = s / fmaxf((float)(end - beg), 1.f);
}
__global__ void head1_kernel(const float* __restrict__ pool, const float* __restrict__ W,
                             const float* __restrict__ b, float* __restrict__ z) {
    int g = blockIdx.x, j = threadIdx.x;
    __shared__ float sp[256];
    sp[j] = pool[g * 256 + j];
    sp[j + 128] = pool[g * 256 + j + 128];
    __syncthreads();
    float s = b[j];
#pragma unroll 8
    for (int k = 0; k < 256; k++) s += sp[k] * W[k * 128 + j];
    z[g * 128 + j] = fmaxf(s, 0.f);
}
__global__ void head2_kernel(const float* __restrict__ z, const float* __restrict__ W,
                             const float* __restrict__ b, float* __restrict__ out) {
    int t = threadIdx.x;
    int g = t >> 1, j = t & 1;
    float s = b[j];
#pragma unroll 8
    for (int k = 0; k < 128; k++) s += z[g * 128 + k] * W[k * 2 + j];
    out[g * 2 + j] = s;
}

// ---------------- launch ----------------
extern "C" void kernel_launch(void* const* d_in, const int* in_sizes, int n_in,
                              void* d_out, int out_size) {
    const float* x     = (const float*)d_in[0];
    const int*   ei    = (const int*)d_in[1];
    const int*   batch = (const int*)d_in[2];

    const int E = in_sizes[1] / 2;
    const int n = in_sizes[2];
    const int* srcp = ei;
    const int* dstp = ei + E;

    const float* W[3][2];  const float* B[3][2];
    const float* Gm[3][2]; const float* Bt[3][2];
    for (int l = 0; l < 3; l++) {
        int base = 3 + l * 8;
        W[l][0]  = (const float*)d_in[base + 0];
        B[l][0]  = (const float*)d_in[base + 1];
        Gm[l][0] = (const float*)d_in[base + 2];
        Bt[l][0] = (const float*)d_in[base + 3];
        W[l][1]  = (const float*)d_in[base + 4];
        B[l][1]  = (const float*)d_in[base + 5];
        Gm[l][1] = (const float*)d_in[base + 6];
        Bt[l][1] = (const float*)d_in[base + 7];
    }
    const float* hW1 = (const float*)d_in[27];
    const float* hb1 = (const float*)d_in[28];
    const float* hW2 = (const float*)d_in[29];
    const float* hb2 = (const float*)d_in[30];

    float *t1, *t2, *hA, *hB, *stats, *norm, *pool, *zbuf;
    int *deg, *rowptr, *cursor, *eidx, *cnt, *gstart;
    __nv_bfloat16 *wth, *wtl;
    cudaGetSymbolAddress((void**)&t1, g_t1);
    cudaGetSymbolAddress((void**)&t2, g_t2);
    cudaGetSymbolAddress((void**)&hA, g_hA);
    cudaGetSymbolAddress((void**)&hB, g_hB);
    cudaGetSymbolAddress((void**)&stats, g_stats);
    cudaGetSymbolAddress((void**)&norm, g_norm);
    cudaGetSymbolAddress((void**)&deg, g_deg);
    cudaGetSymbolAddress((void**)&rowptr, g_rowptr);
    cudaGetSymbolAddress((void**)&cursor, g_cursor);
    cudaGetSymbolAddress((void**)&eidx, g_eidx);
    cudaGetSymbolAddress((void**)&cnt, g_cnt);
    cudaGetSymbolAddress((void**)&gstart, g_gstart);
    cudaGetSymbolAddress((void**)&pool, g_pool);
    cudaGetSymbolAddress((void**)&zbuf, g_zbuf);
    cudaGetSymbolAddress((void**)&wth, g_wth);
    cudaGetSymbolAddress((void**)&wtl, g_wtl);

    float* sum1 = stats + 0;   float* sq1 = stats + 256;
    float* sum2 = stats + 512; float* sq2 = stats + 768;
    float* a1 = norm + 0;   float* c1 = norm + 256;
    float* a2 = norm + 512; float* c2 = norm + 768;

    const int wt_off[6] = {0, 2048, 6144, 22528, 38912, 104448};

    const float invE = 1.f / (float)E;
    const int EB = (E + 127) / 128;
    const int EG = (E + 255) / 256;
    const int NG = (n + 255) / 256;
    const int AGG = (n * 32 + 255) / 256;

    // ---- layer 1 first, ordered so ncu (-s 5 -c 1) profiles launch #6 =
    //      mgemm L1g2 (K=64 non-gather mainloop) ----
    zero_stats_kernel<<<1, 256>>>(stats);                                             // 1
    convert_w_kernel<<<(64 * 32 + 255) / 256, 256>>>(W[0][0], wth + wt_off[0], wtl + wt_off[0], 14, 64, 32);   // 2
    convert_w_kernel<<<(64 * 64 + 255) / 256, 256>>>(W[0][1], wth + wt_off[1], wtl + wt_off[1], 64, 64, 64);   // 3
    mgemm_kernel<7, 14, 64, true><<<dim3(EB, 1), 256>>>(                              // 4
        x, srcp, dstp, nullptr, nullptr, wth + wt_off[0], wtl + wt_off[0], B[0][0], t1, sum1, sq1, E);
    finalize_kernel<<<1, 64>>>(sum1, sq1, Gm[0][0], Bt[0][0], a1, c1, 64, invE);      // 5
    mgemm_kernel<0, 64, 64, false><<<dim3(EB, 1), 256>>>(                             // 6  <- profiled
        t1, nullptr, nullptr, a1, c1, wth + wt_off[1], wtl + wt_off[1], B[0][1], t2, sum2, sq2, E);
    finalize_kernel<<<1, 64>>>(sum2, sq2, Gm[0][1], Bt[0][1], a2, c2, 64, invE);

    // ---- CSR build (needed before aggregate) + remaining weight converts ----
    cudaMemsetAsync(deg, 0, n * sizeof(int));
    cudaMemsetAsync(cnt, 0, GG * sizeof(int));
    hist_deg_kernel<<<EG, 256>>>(dstp, deg, E);
    hist_cnt_kernel<<<NG, 256>>>(batch, cnt, n);
    scan_kernel<<<1, 1024>>>(deg, rowptr, cursor, cnt, gstart, n);
    fill_csr_kernel<<<EG, 256>>>(dstp, cursor, eidx, E);
    convert_w_kernel<<<(128 * 128 + 255) / 256, 256>>>(W[1][0], wth + wt_off[2], wtl + wt_off[2], 128, 128, 128);
    convert_w_kernel<<<(128 * 128 + 255) / 256, 256>>>(W[1][1], wth + wt_off[3], wtl + wt_off[3], 128, 128, 128);
    convert_w_kernel<<<(256 * 256 + 255) / 256, 256>>>(W[2][0], wth + wt_off[4], wtl + wt_off[4], 256, 256, 256);
    convert_w_kernel<<<(256 * 256 + 255) / 256, 256>>>(W[2][1], wth + wt_off[5], wtl + wt_off[5], 256, 256, 256);

    aggregate_kernel<64><<<AGG, 256>>>(t2, rowptr, eidx, a2, c2, hA, n);

    // ---- layer 2: 64 -> 128 ----
    zero_stats_kernel<<<1, 256>>>(stats);
    mgemm_kernel<64, 128, 128, true><<<dim3(EB, 2), 256>>>(
        hA, srcp, dstp, nullptr, nullptr, wth + wt_off[2], wtl + wt_off[2], B[1][0], t1, sum1, sq1, E);
    finalize_kernel<<<1, 128>>>(sum1, sq1, Gm[1][0], Bt[1][0], a1, c1, 128, invE);
    mgemm_kernel<0, 128, 128, false><<<dim3(EB, 2), 256>>>(
        t1, nullptr, nullptr, a1, c1, wth + wt_off[3], wtl + wt_off[3], B[1][1], t2, sum2, sq2, E);
    finalize_kernel<<<1, 128>>>(sum2, sq2, Gm[1][1], Bt[1][1], a2, c2, 128, invE);
    aggregate_kernel<128><<<AGG, 256>>>(t2, rowptr, eidx, a2, c2, hB, n);

    // ---- layer 3: 128 -> 256 ----
    zero_stats_kernel<<<1, 256>>>(stats);
    mgemm_kernel<128, 256, 256, true><<<dim3(EB, 4), 256>>>(
        hB, srcp, dstp, nullptr, nullptr, wth + wt_off[4], wtl + wt_off[4], B[2][0], t1, sum1, sq1, E);
    finalize_kernel<<<1, 256>>>(sum1, sq1, Gm[2][0], Bt[2][0], a1, c1, 256, invE);
    mgemm_kernel<0, 256, 256, false><<<dim3(EB, 4), 256>>>(
        t1, nullptr, nullptr, a1, c1, wth + wt_off[5], wtl + wt_off[5], B[2][1], t2, sum2, sq2, E);
    finalize_kernel<<<1, 256>>>(sum2, sq2, Gm[2][1], Bt[2][1], a2, c2, 256, invE);
    aggregate_kernel<256><<<AGG, 256>>>(t2, rowptr, eidx, a2, c2, hA, n);

    // ---- pool + head ----
    pool_kernel<<<GG, 256>>>(hA, gstart, pool);
    head1_kernel<<<GG, 128>>>(pool, hW1, hb1, zbuf);
    head2_kernel<<<1, 128>>>(zbuf, hW2, hb2, (float*)d_out);
}

// round 8
// speedup vs baseline: 1.1840x; 1.0144x over previous
#include <cuda_runtime.h>
#include <cuda_bf16.h>
#include <cstdint>

// ---------------- problem constants ----------------
#define NN 50000
#define EE 500000
#define GG 64

// ---------------- scratch (device globals; no allocation allowed) ----------
__device__ float g_t1[(size_t)EE * 256];
__device__ float g_t2[(size_t)EE * 256];
__device__ float g_hA[(size_t)NN * 256];
__device__ float g_hB[(size_t)NN * 256];
__device__ float g_stats[1024];
__device__ float g_norm[1024];
__device__ int   g_deg[NN];
__device__ int   g_rowptr[NN + 1];
__device__ int   g_cursor[NN];
__device__ int   g_eidx[EE];
__device__ int   g_cnt[GG];
__device__ int   g_gstart[GG + 1];
__device__ float g_pool[GG * 256];
__device__ float g_zbuf[GG * 128];
__device__ __nv_bfloat16 g_wth[172032];
__device__ __nv_bfloat16 g_wtl[172032];

// ---------------- mma.sync / ldmatrix helpers ------------------------------
#define MMA_BF16(d, a, b)                                                        \
    asm volatile("mma.sync.aligned.m16n8k16.row.col.f32.bf16.bf16.f32 "          \
                 "{%0,%1,%2,%3}, {%4,%5,%6,%7}, {%8,%9}, {%0,%1,%2,%3};"         \
                 : "+f"((d)[0]), "+f"((d)[1]), "+f"((d)[2]), "+f"((d)[3])        \
                 : "r"((a)[0]), "r"((a)[1]), "r"((a)[2]), "r"((a)[3]),           \
                   "r"((b)[0]), "r"((b)[1]))

#define LDSM_X4(r0, r1, r2, r3, addr)                                            \
    asm volatile("ldmatrix.sync.aligned.m8n8.x4.shared.b16 {%0,%1,%2,%3}, [%4];" \
                 : "=r"(r0), "=r"(r1), "=r"(r2), "=r"(r3) : "r"(addr))

__device__ __forceinline__ uint32_t smem_u32(const void* p) {
    uint32_t a;
    asm("{ .reg .u64 t; cvta.to.shared.u64 t, %1; cvt.u32.u64 %0, t; }" : "=r"(a) : "l"(p));
    return a;
}

// ---------------- small utility kernels ----------------
__global__ void zero_stats_kernel(float* __restrict__ s) {
    int i = threadIdx.x;
#pragma unroll
    for (int j = 0; j < 4; j++) s[i + j * 256] = 0.f;
}

__global__ void hist_deg_kernel(const int* __restrict__ dst, int* __restrict__ deg, int E) {
    int e = blockIdx.x * blockDim.x + threadIdx.x;
    if (e < E) atomicAdd(&deg[dst[e]], 1);
}
__global__ void hist_cnt_kernel(const int* __restrict__ batch, int* __restrict__ cnt, int n) {
    int i = blockIdx.x * blockDim.x + threadIdx.x;
    if (i < n) atomicAdd(&cnt[batch[i]], 1);
}
__global__ void scan_kernel(const int* __restrict__ deg, int* __restrict__ rowptr,
                            int* __restrict__ cursor, const int* __restrict__ cnt,
                            int* __restrict__ gstart, int n) {
    __shared__ int sh[1024];
    __shared__ int carry;
    int t = threadIdx.x;
    if (t == 0) carry = 0;
    __syncthreads();
    for (int base = 0; base < n; base += 1024) {
        int idx = base + t;
        int v = (idx < n) ? deg[idx] : 0;
        sh[t] = v;
        __syncthreads();
        for (int off = 1; off < 1024; off <<= 1) {
            int add = (t >= off) ? sh[t - off] : 0;
            __syncthreads();
            sh[t] += add;
            __syncthreads();
        }
        int ex = sh[t] - v;
        int cbase = carry;
        if (idx < n) { rowptr[idx] = cbase + ex; cursor[idx] = cbase + ex; }
        __syncthreads();
        if (t == 1023) carry = cbase + sh[1023];
        __syncthreads();
    }
    if (t == 0) {
        rowptr[n] = carry;
        int s = 0;
        for (int g = 0; g < GG; g++) { gstart[g] = s; s += cnt[g]; }
        gstart[GG] = s;
    }
}
__global__ void fill_csr_kernel(const int* __restrict__ dst, int* __restrict__ cursor,
                                int* __restrict__ eidx, int E) {
    int e = blockIdx.x * blockDim.x + threadIdx.x;
    if (e < E) {
        int p = atomicAdd(&cursor[dst[e]], 1);
        eidx[p] = e;
    }
}

__global__ void convert_w_kernel(const float* __restrict__ W,
                                 __nv_bfloat16* __restrict__ Wth,
                                 __nv_bfloat16* __restrict__ Wtl,
                                 int K, int OC, int KPAD) {
    int idx = blockIdx.x * blockDim.x + threadIdx.x;
    if (idx >= OC * KPAD) return;
    int n = idx / KPAD, k = idx % KPAD;
    float w = (k < K) ? W[(size_t)k * OC + n] : 0.f;
    __nv_bfloat16 h = __float2bfloat16_rn(w);
    Wth[idx] = h;
    Wtl[idx] = __float2bfloat16_rn(w - __bfloat162float(h));
}

// ---------------- tensor-core GEMM, reg-prefetch pipelined, fused stats ----
// Block tile 128 x 64.  8 warps = 4(M) x 2(N), warp tile 32 x 32.
// 3 MMAs per k16 tile (AhBh + AhBl + AlBh) for ~fp32 accuracy.
// Epilogue stages results through smem for fully-coalesced STG.128.
template <int C, int K, int OC, bool GATHER>
__global__ __launch_bounds__(256, 2)
void mgemm_kernel(const float* __restrict__ feats,
                  const int* __restrict__ src, const int* __restrict__ dst,
                  const float* __restrict__ an, const float* __restrict__ cn,
                  const __nv_bfloat16* __restrict__ Wth,
                  const __nv_bfloat16* __restrict__ Wtl,
                  const float* __restrict__ bias,
                  float* __restrict__ out,
                  float* __restrict__ stat_sum, float* __restrict__ stat_sq,
                  int E) {
    constexpr int BN = 64;
    constexpr int KPAD = (K + 31) / 32 * 32;
    constexpr int NCH = KPAD / 32;
    constexpr int NT = BN / 16;          // 4 n8-tiles per warp
    constexpr int SAS = 40;              // 80B stride: conflict-free ldmatrix

    // flat smem blob with manual layout (epilogue buffer overlays A region)
    constexpr int OFF_AH = 0;            // 128*40*2  = 10240
    constexpr int OFF_AL = 10240;        // 10240
    constexpr int OFF_BH = 20480;        // 64*40*2   = 5120
    constexpr int OFF_BL = 25600;        // 5120
    constexpr int OFF_DST = 30720;       // 512
    constexpr int OFF_SRC = 31232;       // 512
    constexpr int OFF_AN = 31744;        // 1024
    constexpr int OFF_CN = 32768;        // 1024 -> total 33792
    constexpr int OFF_BUF = 0;           // epilogue: 64*72*4 = 18432
    constexpr int OFF_SSUM = 18432;      // 256
    constexpr int OFF_SSQ = 18688;       // 256
    constexpr int EST = 72;              // epilogue buf row stride (floats)

    __shared__ __align__(16) char SM[33792];
    __nv_bfloat16* sAh = reinterpret_cast<__nv_bfloat16*>(SM + OFF_AH);
    __nv_bfloat16* sAl = reinterpret_cast<__nv_bfloat16*>(SM + OFF_AL);
    __nv_bfloat16* sBh = reinterpret_cast<__nv_bfloat16*>(SM + OFF_BH);
    __nv_bfloat16* sBl = reinterpret_cast<__nv_bfloat16*>(SM + OFF_BL);
    int* sdst = reinterpret_cast<int*>(SM + OFF_DST);
    int* ssrc = reinterpret_cast<int*>(SM + OFF_SRC);
    float* sAn = reinterpret_cast<float*>(SM + OFF_AN);
    float* sCn = reinterpret_cast<float*>(SM + OFF_CN);

    const int tid = threadIdx.x;
    const int lane = tid & 31;
    const int wid = tid >> 5;
    const int wm = wid & 3;
    const int wn = wid >> 2;
    const int e0 = blockIdx.x * 128;
    const int col0 = blockIdx.y * BN;

    const uint32_t sAh_u = smem_u32(sAh);
    const uint32_t sAl_u = smem_u32(sAl);
    const uint32_t sBh_u = smem_u32(sBh);
    const uint32_t sBl_u = smem_u32(sBl);

    if (GATHER) {
        if (tid < 128) {
            int e = e0 + tid;
            int ee = (e < E) ? e : (E - 1);
            sdst[tid] = dst[ee];
            ssrc[tid] = src[ee];
        }
    } else {
        for (int i = tid; i < K; i += 256) { sAn[i] = an[i]; sCn[i] = cn[i]; }
    }
    __syncthreads();

    float acc[2][NT][4];
#pragma unroll
    for (int mt = 0; mt < 2; mt++)
#pragma unroll
        for (int nt = 0; nt < NT; nt++)
#pragma unroll
            for (int j = 0; j < 4; j++) acc[mt][nt][j] = 0.f;

    const int arow = tid >> 1;
    const int acg = (tid & 1) * 16;
    int nd = 0, ns = 0;
    if (GATHER) { nd = sdst[arow]; ns = ssrc[arow]; }

    const int bn_ = tid >> 2;
    const int bu_ = tid & 3;
    const int bdoff = bn_ * SAS + bu_ * 8;

    float4 P[4], Q[4];
    uint4 BHr, BLr;

    auto load_chunk = [&](int ch) {
        const int k0 = ch * 32 + acg;
        if (GATHER) {
            if (C % 4 == 0) {
                if (k0 < C) {
#pragma unroll
                    for (int u = 0; u < 4; u++)
                        P[u] = *reinterpret_cast<const float4*>(&feats[(size_t)nd * C + k0 + u * 4]);
                } else {
#pragma unroll
                    for (int u = 0; u < 4; u++) {
                        P[u] = *reinterpret_cast<const float4*>(&feats[(size_t)ns * C + (k0 - C) + u * 4]);
                        Q[u] = *reinterpret_cast<const float4*>(&feats[(size_t)nd * C + (k0 - C) + u * 4]);
                    }
                }
            } else {  // C=7 scalar path (NCH==1)
#pragma unroll
                for (int u = 0; u < 4; u++) {
                    float t[4];
#pragma unroll
                    for (int j = 0; j < 4; j++) {
                        int kk = k0 + u * 4 + j;
                        if (kk < C) t[j] = feats[(size_t)nd * C + kk];
                        else if (kk < K) t[j] = feats[(size_t)ns * C + (kk - C)] - feats[(size_t)nd * C + (kk - C)];
                        else t[j] = 0.f;
                    }
                    P[u] = make_float4(t[0], t[1], t[2], t[3]);
                }
            }
        } else {
            const int e = e0 + arow;
            if (e < E) {
#pragma unroll
                for (int u = 0; u < 4; u++)
                    P[u] = *reinterpret_cast<const float4*>(&feats[(size_t)e * K + k0 + u * 4]);
            } else {
#pragma unroll
                for (int u = 0; u < 4; u++) P[u] = make_float4(0.f, 0.f, 0.f, 0.f);
            }
        }
    };
    auto load_B = [&](int ch) {
        size_t soff = (size_t)(col0 + bn_) * KPAD + ch * 32 + bu_ * 8;
        BHr = *reinterpret_cast<const uint4*>(Wth + soff);
        BLr = *reinterpret_cast<const uint4*>(Wtl + soff);
    };
    auto store_chunk = [&](int ch) {
        const int k0 = ch * 32 + acg;
#pragma unroll
        for (int u = 0; u < 4; u++) {
            float4 v;
            if (GATHER) {
                if (C % 4 == 0) {
                    if (k0 < C) v = P[u];
                    else v = make_float4(P[u].x - Q[u].x, P[u].y - Q[u].y,
                                         P[u].z - Q[u].z, P[u].w - Q[u].w);
                } else {
                    v = P[u];
                }
            } else {
                if (e0 + arow < E) {
                    const int k = k0 + u * 4;
                    v.x = fmaxf(P[u].x * sAn[k + 0] + sCn[k + 0], 0.f);
                    v.y = fmaxf(P[u].y * sAn[k + 1] + sCn[k + 1], 0.f);
                    v.z = fmaxf(P[u].z * sAn[k + 2] + sCn[k + 2], 0.f);
                    v.w = fmaxf(P[u].w * sAn[k + 3] + sCn[k + 3], 0.f);
                } else {
                    v = make_float4(0.f, 0.f, 0.f, 0.f);
                }
            }
            __nv_bfloat162 h01 = __float22bfloat162_rn(make_float2(v.x, v.y));
            __nv_bfloat162 h23 = __float22bfloat162_rn(make_float2(v.z, v.w));
            float2 hf01 = __bfloat1622float2(h01);
            float2 hf23 = __bfloat1622float2(h23);
            __nv_bfloat162 l01 = __float22bfloat162_rn(make_float2(v.x - hf01.x, v.y - hf01.y));
            __nv_bfloat162 l23 = __float22bfloat162_rn(make_float2(v.z - hf23.x, v.w - hf23.y));
            uint2 H, L;
            H.x = *reinterpret_cast<uint32_t*>(&h01);
            H.y = *reinterpret_cast<uint32_t*>(&h23);
            L.x = *reinterpret_cast<uint32_t*>(&l01);
            L.y = *reinterpret_cast<uint32_t*>(&l23);
            int so = arow * SAS + acg + u * 4;
            *reinterpret_cast<uint2*>(&sAh[so]) = H;
            *reinterpret_cast<uint2*>(&sAl[so]) = L;
        }
        *reinterpret_cast<uint4*>(&sBh[bdoff]) = BHr;
        *reinterpret_cast<uint4*>(&sBl[bdoff]) = BLr;
    };

    const int a_lrow = (lane & 7) + ((lane >> 3) & 1) * 8;
    const int a_lcol = (lane >> 4) * 8;
    const int b_lrow = (lane & 7) + (lane >> 4) * 8;
    const int b_lcol = ((lane >> 3) & 1) * 8;

    load_chunk(0);
    load_B(0);

    for (int ch = 0; ch < NCH; ch++) {
        store_chunk(ch);
        __syncthreads();

        if (ch + 1 < NCH) { load_chunk(ch + 1); load_B(ch + 1); }

#pragma unroll
        for (int ks = 0; ks < 2; ks++) {
            const int kb = ks * 16;
            uint32_t ah[2][4], al[2][4];
#pragma unroll
            for (int mt = 0; mt < 2; mt++) {
                int r = wm * 32 + mt * 16 + a_lrow;
                uint32_t off = (uint32_t)(r * SAS + kb + a_lcol) * 2;
                LDSM_X4(ah[mt][0], ah[mt][1], ah[mt][2], ah[mt][3], sAh_u + off);
                LDSM_X4(al[mt][0], al[mt][1], al[mt][2], al[mt][3], sAl_u + off);
            }
#pragma unroll
            for (int p = 0; p < NT / 2; p++) {
                int n0 = wn * (BN / 2) + p * 16;
                uint32_t boff = (uint32_t)((n0 + b_lrow) * SAS + kb + b_lcol) * 2;
                uint32_t bh[4], bl[4];
                LDSM_X4(bh[0], bh[1], bh[2], bh[3], sBh_u + boff);
                LDSM_X4(bl[0], bl[1], bl[2], bl[3], sBl_u + boff);
#pragma unroll
                for (int mt = 0; mt < 2; mt++) {
                    MMA_BF16(acc[mt][2 * p], ah[mt], (&bh[0]));
                    MMA_BF16(acc[mt][2 * p], ah[mt], (&bl[0]));
                    MMA_BF16(acc[mt][2 * p], al[mt], (&bh[0]));
                    MMA_BF16(acc[mt][2 * p + 1], ah[mt], (&bh[2]));
                    MMA_BF16(acc[mt][2 * p + 1], ah[mt], (&bl[2]));
                    MMA_BF16(acc[mt][2 * p + 1], al[mt], (&bh[2]));
                }
            }
        }
        __syncthreads();
    }

    // ---- epilogue: bias into acc, fused BN stats, coalesced smem-staged store
    float* ebuf = reinterpret_cast<float*>(SM + OFF_BUF);
    float* ssum = reinterpret_cast<float*>(SM + OFF_SSUM);
    float* ssq = reinterpret_cast<float*>(SM + OFF_SSQ);

    const int q = lane >> 2, s = lane & 3;

    // bias add
#pragma unroll
    for (int nt = 0; nt < NT; nt++) {
        const int col = col0 + wn * (BN / 2) + nt * 8 + s * 2;
        const float b0 = bias[col], b1 = bias[col + 1];
#pragma unroll
        for (int mt = 0; mt < 2; mt++) {
            acc[mt][nt][0] += b0; acc[mt][nt][1] += b1;
            acc[mt][nt][2] += b0; acc[mt][nt][3] += b1;
        }
    }

    if (tid < 2 * BN) reinterpret_cast<float*>(SM + OFF_SSUM)[tid] = 0.f;
    __syncthreads();

    // stats (only valid rows)
#pragma unroll
    for (int nt = 0; nt < NT; nt++) {
        const int colw = wn * (BN / 2) + nt * 8 + s * 2;
        float s0 = 0.f, q0 = 0.f, s1 = 0.f, q1 = 0.f;
#pragma unroll
        for (int mt = 0; mt < 2; mt++) {
            const int r = wm * 32 + mt * 16 + q;
            if (e0 + r < E) {
                s0 += acc[mt][nt][0]; q0 += acc[mt][nt][0] * acc[mt][nt][0];
                s1 += acc[mt][nt][1]; q1 += acc[mt][nt][1] * acc[mt][nt][1];
            }
            if (e0 + r + 8 < E) {
                s0 += acc[mt][nt][2]; q0 += acc[mt][nt][2] * acc[mt][nt][2];
                s1 += acc[mt][nt][3]; q1 += acc[mt][nt][3] * acc[mt][nt][3];
            }
        }
#pragma unroll
        for (int m = 4; m <= 16; m <<= 1) {
            s0 += __shfl_xor_sync(0xffffffff, s0, m);
            q0 += __shfl_xor_sync(0xffffffff, q0, m);
            s1 += __shfl_xor_sync(0xffffffff, s1, m);
            q1 += __shfl_xor_sync(0xffffffff, q1, m);
        }
        if (q == 0) {
            atomicAdd(&ssum[colw], s0);
            atomicAdd(&ssq[colw], q0);
            atomicAdd(&ssum[colw + 1], s1);
            atomicAdd(&ssq[colw + 1], q1);
        }
    }
    __syncthreads();
    if (tid < BN) {
        atomicAdd(&stat_sum[col0 + tid], ssum[tid]);
        atomicAdd(&stat_sq[col0 + tid], ssq[tid]);
    }

    // two 64-row passes: acc -> smem (stride-72, conflict-free) -> STG.128
#pragma unroll
    for (int pass = 0; pass < 2; pass++) {
        if ((wm >> 1) == pass) {
            const int wml = wm & 1;
#pragma unroll
            for (int mt = 0; mt < 2; mt++) {
                const int rl = wml * 32 + mt * 16 + q;
#pragma unroll
                for (int nt = 0; nt < NT; nt++) {
                    const int colw = wn * (BN / 2) + nt * 8 + s * 2;
                    *reinterpret_cast<float2*>(&ebuf[rl * EST + colw]) =
                        make_float2(acc[mt][nt][0], acc[mt][nt][1]);
                    *reinterpret_cast<float2*>(&ebuf[(rl + 8) * EST + colw]) =
                        make_float2(acc[mt][nt][2], acc[mt][nt][3]);
                }
            }
        }
        __syncthreads();
#pragma unroll
        for (int ii = 0; ii < 4; ii++) {
            const int i = tid + ii * 256;        // 0..1023
            const int row = i >> 4, c4 = i & 15;
            const int e = e0 + pass * 64 + row;
            if (e < E) {
                float4 v = *reinterpret_cast<float4*>(&ebuf[row * EST + c4 * 4]);
                *reinterpret_cast<float4*>(&out[(size_t)e * OC + col0 + c4 * 4]) = v;
            }
        }
        __syncthreads();
    }
}

// ---------------- BN finalize ----------------
__global__ void finalize_kernel(const float* __restrict__ sum, const float* __restrict__ sq,
                                const float* __restrict__ gamma, const float* __restrict__ beta,
                                float* __restrict__ a, float* __restrict__ c,
                                int OC, float invE) {
    int i = blockIdx.x * blockDim.x + threadIdx.x;
    if (i < OC) {
        float m = sum[i] * invE;
        float var = sq[i] * invE - m * m;
        float rs = rsqrtf(var + 1e-5f);
        float ai = gamma[i] * rs;
        a[i] = ai;
        c[i] = beta[i] - m * ai;
    }
}

// ---------------- normalize + relu + mean-aggregate (CSR, warp per node) ----
template <int OC>
__global__ __launch_bounds__(256)
void aggregate_kernel(const float* __restrict__ t, const int* __restrict__ rowptr,
                      const int* __restrict__ eidx, const float* __restrict__ a,
                      const float* __restrict__ c, float* __restrict__ hout, int n) {
    int warp = (blockIdx.x * blockDim.x + threadIdx.x) >> 5;
    int lane = threadIdx.x & 31;
    if (warp >= n) return;
    constexpr int R = OC / 32;
    float av[R], cv[R], acc[R];
#pragma unroll
    for (int j = 0; j < R; j++) {
        int ch = j * 32 + lane;
        av[j] = a[ch]; cv[j] = c[ch]; acc[j] = 0.f;
    }
    int beg = rowptr[warp], end = rowptr[warp + 1];
    for (int p = beg; p < end; p++) {
        int e = eidx[p];
        const float* rowp = t + (size_t)e * OC;
#pragma unroll
        for (int j = 0; j < R; j++) {
            float v = rowp[j * 32 + lane];
            acc[j] += fmaxf(v * av[j] + cv[j], 0.f);
        }
    }
    float inv = 1.f / fmaxf((float)(end - beg), 1.f);
#pragma unroll
    for (int j = 0; j < R; j++) hout[(size_t)warp * OC + j * 32 + lane] = acc[j] * inv;
}

// ---------------- global mean pool + head ----------------
__global__ void pool_kernel(const float* __restrict__ h, const int* __restrict__ gstart,
                            float* __restrict__ pool) {
    int g = blockIdx.x;
    int ch = threadIdx.x;
    int beg = gstart[g], end = gstart[g + 1];
    float s = 0.f;
    for (int nidx = beg; nidx < end; nidx++) s += h[(size_t)nidx * 256 + ch];
    pool[g * 256 + ch] = s / fmaxf((float)(end - beg), 1.f);
}
__global__ void head1_kernel(const float* __restrict__ pool, const float* __restrict__ W,
                             const float* __restrict__ b, float* __restrict__ z) {
    int g = blockIdx.x, j = threadIdx.x;
    __shared__ float sp[256];
    sp[j] = pool[g * 256 + j];
    sp[j + 128] = pool[g * 256 + j + 128];
    __syncthreads();
    float s = b[j];
#pragma unroll 8
    for (int k = 0; k < 256; k++) s += sp[k] * W[k * 128 + j];
    z[g * 128 + j] = fmaxf(s, 0.f);
}
__global__ void head2_kernel(const float* __restrict__ z, const float* __restrict__ W,
                             const float* __restrict__ b, float* __restrict__ out) {
    int t = threadIdx.x;
    int g = t >> 1, j = t & 1;
    float s = b[j];
#pragma unroll 8
    for (int k = 0; k < 128; k++) s += z[g * 128 + k] * W[k * 2 + j];
    out[g * 2 + j] = s;
}

// ---------------- launch ----------------
extern "C" void kernel_launch(void* const* d_in, const int* in_sizes, int n_in,
                              void* d_out, int out_size) {
    const float* x     = (const float*)d_in[0];
    const int*   ei    = (const int*)d_in[1];
    const int*   batch = (const int*)d_in[2];

    const int E = in_sizes[1] / 2;
    const int n = in_sizes[2];
    const int* srcp = ei;
    const int* dstp = ei + E;

    const float* W[3][2];  const float* B[3][2];
    const float* Gm[3][2]; const float* Bt[3][2];
    for (int l = 0; l < 3; l++) {
        int base = 3 + l * 8;
        W[l][0]  = (const float*)d_in[base + 0];
        B[l][0]  = (const float*)d_in[base + 1];
        Gm[l][0] = (const float*)d_in[base + 2];
        Bt[l][0] = (const float*)d_in[base + 3];
        W[l][1]  = (const float*)d_in[base + 4];
        B[l][1]  = (const float*)d_in[base + 5];
        Gm[l][1] = (const float*)d_in[base + 6];
        Bt[l][1] = (const float*)d_in[base + 7];
    }
    const float* hW1 = (const float*)d_in[27];
    const float* hb1 = (const float*)d_in[28];
    const float* hW2 = (const float*)d_in[29];
    const float* hb2 = (const float*)d_in[30];

    float *t1, *t2, *hA, *hB, *stats, *norm, *pool, *zbuf;
    int *deg, *rowptr, *cursor, *eidx, *cnt, *gstart;
    __nv_bfloat16 *wth, *wtl;
    cudaGetSymbolAddress((void**)&t1, g_t1);
    cudaGetSymbolAddress((void**)&t2, g_t2);
    cudaGetSymbolAddress((void**)&hA, g_hA);
    cudaGetSymbolAddress((void**)&hB, g_hB);
    cudaGetSymbolAddress((void**)&stats, g_stats);
    cudaGetSymbolAddress((void**)&norm, g_norm);
    cudaGetSymbolAddress((void**)&deg, g_deg);
    cudaGetSymbolAddress((void**)&rowptr, g_rowptr);
    cudaGetSymbolAddress((void**)&cursor, g_cursor);
    cudaGetSymbolAddress((void**)&eidx, g_eidx);
    cudaGetSymbolAddress((void**)&cnt, g_cnt);
    cudaGetSymbolAddress((void**)&gstart, g_gstart);
    cudaGetSymbolAddress((void**)&pool, g_pool);
    cudaGetSymbolAddress((void**)&zbuf, g_zbuf);
    cudaGetSymbolAddress((void**)&wth, g_wth);
    cudaGetSymbolAddress((void**)&wtl, g_wtl);

    float* sum1 = stats + 0;   float* sq1 = stats + 256;
    float* sum2 = stats + 512; float* sq2 = stats + 768;
    float* a1 = norm + 0;   float* c1 = norm + 256;
    float* a2 = norm + 512; float* c2 = norm + 768;

    const int wt_off[6] = {0, 2048, 6144, 22528, 38912, 104448};

    const float invE = 1.f / (float)E;
    const int EB = (E + 127) / 128;
    const int EG = (E + 255) / 256;
    const int NG = (n + 255) / 256;
    const int AGG = (n * 32 + 255) / 256;

    // ---- layer 1 first (profiled launches land on mgemm) ----
    zero_stats_kernel<<<1, 256>>>(stats);
    convert_w_kernel<<<(64 * 32 + 255) / 256, 256>>>(W[0][0], wth + wt_off[0], wtl + wt_off[0], 14, 64, 32);
    convert_w_kernel<<<(64 * 64 + 255) / 256, 256>>>(W[0][1], wth + wt_off[1], wtl + wt_off[1], 64, 64, 64);
    mgemm_kernel<7, 14, 64, true><<<dim3(EB, 1), 256>>>(
        x, srcp, dstp, nullptr, nullptr, wth + wt_off[0], wtl + wt_off[0], B[0][0], t1, sum1, sq1, E);
    finalize_kernel<<<1, 64>>>(sum1, sq1, Gm[0][0], Bt[0][0], a1, c1, 64, invE);
    mgemm_kernel<0, 64, 64, false><<<dim3(EB, 1), 256>>>(
        t1, nullptr, nullptr, a1, c1, wth + wt_off[1], wtl + wt_off[1], B[0][1], t2, sum2, sq2, E);
    finalize_kernel<<<1, 64>>>(sum2, sq2, Gm[0][1], Bt[0][1], a2, c2, 64, invE);

    // ---- CSR build + remaining weight converts ----
    cudaMemsetAsync(deg, 0, n * sizeof(int));
    cudaMemsetAsync(cnt, 0, GG * sizeof(int));
    hist_deg_kernel<<<EG, 256>>>(dstp, deg, E);
    hist_cnt_kernel<<<NG, 256>>>(batch, cnt, n);
    scan_kernel<<<1, 1024>>>(deg, rowptr, cursor, cnt, gstart, n);
    fill_csr_kernel<<<EG, 256>>>(dstp, cursor, eidx, E);
    convert_w_kernel<<<(128 * 128 + 255) / 256, 256>>>(W[1][0], wth + wt_off[2], wtl + wt_off[2], 128, 128, 128);
    convert_w_kernel<<<(128 * 128 + 255) / 256, 256>>>(W[1][1], wth + wt_off[3], wtl + wt_off[3], 128, 128, 128);
    convert_w_kernel<<<(256 * 256 + 255) / 256, 256>>>(W[2][0], wth + wt_off[4], wtl + wt_off[4], 256, 256, 256);
    convert_w_kernel<<<(256 * 256 + 255) / 256, 256>>>(W[2][1], wth + wt_off[5], wtl + wt_off[5], 256, 256, 256);

    aggregate_kernel<64><<<AGG, 256>>>(t2, rowptr, eidx, a2, c2, hA, n);

    // ---- layer 2: 64 -> 128 ----
    zero_stats_kernel<<<1, 256>>>(stats);
    mgemm_kernel<64, 128, 128, true><<<dim3(EB, 2), 256>>>(
        hA, srcp, dstp, nullptr, nullptr, wth + wt_off[2], wtl + wt_off[2], B[1][0], t1, sum1, sq1, E);
    finalize_kernel<<<1, 128>>>(sum1, sq1, Gm[1][0], Bt[1][0], a1, c1, 128, invE);
    mgemm_kernel<0, 128, 128, false><<<dim3(EB, 2), 256>>>(
        t1, nullptr, nullptr, a1, c1, wth + wt_off[3], wtl + wt_off[3], B[1][1], t2, sum2, sq2, E);
    finalize_kernel<<<1, 128>>>(sum2, sq2, Gm[1][1], Bt[1][1], a2, c2, 128, invE);
    aggregate_kernel<128><<<AGG, 256>>>(t2, rowptr, eidx, a2, c2, hB, n);

    // ---- layer 3: 128 -> 256 ----
    zero_stats_kernel<<<1, 256>>>(stats);
    mgemm_kernel<128, 256, 256, true><<<dim3(EB, 4), 256>>>(
        hB, srcp, dstp, nullptr, nullptr, wth + wt_off[4], wtl + wt_off[4], B[2][0], t1, sum1, sq1, E);
    finalize_kernel<<<1, 256>>>(sum1, sq1, Gm[2][0], Bt[2][0], a1, c1, 256, invE);
    mgemm_kernel<0, 256, 256, false><<<dim3(EB, 4), 256>>>(
        t1, nullptr, nullptr, a1, c1, wth + wt_off[5], wtl + wt_off[5], B[2][1], t2, sum2, sq2, E);
    finalize_kernel<<<1, 256>>>(sum2, sq2, Gm[2][1], Bt[2][1], a2, c2, 256, invE);
    aggregate_kernel<256><<<AGG, 256>>>(t2, rowptr, eidx, a2, c2, hA, n);

    // ---- pool + head ----
    pool_kernel<<<GG, 256>>>(hA, gstart, pool);
    head1_kernel<<<GG, 128>>>(pool, hW1, hb1, zbuf);
    head2_kernel<<<1, 128>>>(zbuf, hW2, hb2, (float*)d_out);
}

// round 9
// speedup vs baseline: 1.5241x; 1.2872x over previous
#include <cuda_runtime.h>
#include <cuda_bf16.h>
#include <cstdint>

// ---------------- problem constants ----------------
#define NN 50000
#define EE 500000
#define GG 64

// ---------------- scratch (device globals; no allocation allowed) ----------
__device__ float g_t1[(size_t)EE * 256];     // UV node buffer (<= 50K x 512)
__device__ float g_t2[(size_t)EE * 256];     // edge intermediate t2
__device__ float g_hA[(size_t)NN * 256];
__device__ float g_hB[(size_t)NN * 256];
__device__ float g_stats[1024];
__device__ float g_norm[1024];
__device__ float g_bias2[512];
__device__ int   g_deg[NN];
__device__ int   g_rowptr[NN + 1];
__device__ int   g_cursor[NN];
__device__ int   g_eidx[EE];
__device__ int   g_cnt[GG];
__device__ int   g_gstart[GG + 1];
__device__ float g_pool[GG * 256];
__device__ float g_zbuf[GG * 128];
__device__ __nv_bfloat16 g_wth[172032];
__device__ __nv_bfloat16 g_wtl[172032];

// ---------------- mma.sync / ldmatrix helpers ------------------------------
#define MMA_BF16(d, a, b)                                                        \
    asm volatile("mma.sync.aligned.m16n8k16.row.col.f32.bf16.bf16.f32 "          \
                 "{%0,%1,%2,%3}, {%4,%5,%6,%7}, {%8,%9}, {%0,%1,%2,%3};"         \
                 : "+f"((d)[0]), "+f"((d)[1]), "+f"((d)[2]), "+f"((d)[3])        \
                 : "r"((a)[0]), "r"((a)[1]), "r"((a)[2]), "r"((a)[3]),           \
                   "r"((b)[0]), "r"((b)[1]))

#define LDSM_X4(r0, r1, r2, r3, addr)                                            \
    asm volatile("ldmatrix.sync.aligned.m8n8.x4.shared.b16 {%0,%1,%2,%3}, [%4];" \
                 : "=r"(r0), "=r"(r1), "=r"(r2), "=r"(r3) : "r"(addr))

__device__ __forceinline__ uint32_t smem_u32(const void* p) {
    uint32_t a;
    asm("{ .reg .u64 t; cvta.to.shared.u64 t, %1; cvt.u32.u64 %0, t; }" : "=r"(a) : "l"(p));
    return a;
}

// ---------------- small utility kernels ----------------
__global__ void zero_stats_kernel(float* __restrict__ s) {
    int i = threadIdx.x;
#pragma unroll
    for (int j = 0; j < 4; j++) s[i + j * 256] = 0.f;
}

__global__ void hist_deg_kernel(const int* __restrict__ dst, int* __restrict__ deg, int E) {
    int e = blockIdx.x * blockDim.x + threadIdx.x;
    if (e < E) atomicAdd(&deg[dst[e]], 1);
}
__global__ void hist_cnt_kernel(const int* __restrict__ batch, int* __restrict__ cnt, int n) {
    int i = blockIdx.x * blockDim.x + threadIdx.x;
    if (i < n) atomicAdd(&cnt[batch[i]], 1);
}
__global__ void scan_kernel(const int* __restrict__ deg, int* __restrict__ rowptr,
                            int* __restrict__ cursor, const int* __restrict__ cnt,
                            int* __restrict__ gstart, int n) {
    __shared__ int sh[1024];
    __shared__ int carry;
    int t = threadIdx.x;
    if (t == 0) carry = 0;
    __syncthreads();
    for (int base = 0; base < n; base += 1024) {
        int idx = base + t;
        int v = (idx < n) ? deg[idx] : 0;
        sh[t] = v;
        __syncthreads();
        for (int off = 1; off < 1024; off <<= 1) {
            int add = (t >= off) ? sh[t - off] : 0;
            __syncthreads();
            sh[t] += add;
            __syncthreads();
        }
        int ex = sh[t] - v;
        int cbase = carry;
        if (idx < n) { rowptr[idx] = cbase + ex; cursor[idx] = cbase + ex; }
        __syncthreads();
        if (t == 1023) carry = cbase + sh[1023];
        __syncthreads();
    }
    if (t == 0) {
        rowptr[n] = carry;
        int s = 0;
        for (int g = 0; g < GG; g++) { gstart[g] = s; s += cnt[g]; }
        gstart[GG] = s;
    }
}
__global__ void fill_csr_kernel(const int* __restrict__ dst, int* __restrict__ cursor,
                                int* __restrict__ eidx, int E) {
    int e = blockIdx.x * blockDim.x + threadIdx.x;
    if (e < E) {
        int p = atomicAdd(&cursor[dst[e]], 1);
        eidx[p] = e;
    }
}

// W2[K,OC] fp32 -> Wt[OC][KPAD] bf16 hi/lo (transposed)
__global__ void convert_w_kernel(const float* __restrict__ W,
                                 __nv_bfloat16* __restrict__ Wth,
                                 __nv_bfloat16* __restrict__ Wtl,
                                 int K, int OC, int KPAD) {
    int idx = blockIdx.x * blockDim.x + threadIdx.x;
    if (idx >= OC * KPAD) return;
    int n = idx / KPAD, k = idx % KPAD;
    float w = (k < K) ? W[(size_t)k * OC + n] : 0.f;
    __nv_bfloat16 h = __float2bfloat16_rn(w);
    Wth[idx] = h;
    Wtl[idx] = __float2bfloat16_rn(w - __bfloat162float(h));
}

// W1[2C,OC] -> combined [2OC][KPAD(C)]: rows 0..OC-1 = (Wa-Wb)^T, OC..2OC-1 = Wb^T
__global__ void convert_wsplit_kernel(const float* __restrict__ W1,
                                      __nv_bfloat16* __restrict__ Wth,
                                      __nv_bfloat16* __restrict__ Wtl,
                                      int C, int OC, int KPAD) {
    int idx = blockIdx.x * blockDim.x + threadIdx.x;
    if (idx >= 2 * OC * KPAD) return;
    int n = idx / KPAD, k = idx % KPAD;
    float w = 0.f;
    if (k < C) {
        if (n < OC) w = W1[(size_t)k * OC + n] - W1[(size_t)(k + C) * OC + n];
        else        w = W1[(size_t)(k + C) * OC + (n - OC)];
    }
    __nv_bfloat16 h = __float2bfloat16_rn(w);
    Wth[idx] = h;
    Wtl[idx] = __float2bfloat16_rn(w - __bfloat162float(h));
}

// ---------------- tensor-core GEMM ------------------------------------------
// MODE 0: node GEMM. A row i = fA[i*K .. ] (plain). Rows = N.
// MODE 1: edge GEMM. A row e = relu((U[dst[e]] + V[src[e]]) * an + cn),
//         where U row = fA + nd*2K, V row = fA + ns*2K + K.  Rows = E.
// out[r, 0:OC] = A @ W + bias.  STATS: fused per-column sum/sumsq.
// Block tile 128 x 64, 8 warps (4M x 2N), 3 MMAs per k16 (hi/lo split).
template <int K, int OC, int MODE, bool STATS>
__global__ __launch_bounds__(256, 2)
void mgemm_kernel(const float* __restrict__ fA,
                  const int* __restrict__ src, const int* __restrict__ dst,
                  const float* __restrict__ an, const float* __restrict__ cn,
                  const __nv_bfloat16* __restrict__ Wth,
                  const __nv_bfloat16* __restrict__ Wtl,
                  const float* __restrict__ bias,
                  float* __restrict__ out,
                  float* __restrict__ stat_sum, float* __restrict__ stat_sq,
                  int Rows) {
    constexpr int BN = 64;
    constexpr int KPAD = (K + 31) / 32 * 32;
    constexpr int NCH = KPAD / 32;
    constexpr int NT = BN / 16;
    constexpr int SAS = 40;
    constexpr int ASTR = (MODE == 1) ? 2 * K : K;   // input row stride

    constexpr int OFF_AH = 0;
    constexpr int OFF_AL = 10240;
    constexpr int OFF_BH = 20480;
    constexpr int OFF_BL = 25600;
    constexpr int OFF_DST = 30720;
    constexpr int OFF_SRC = 31232;
    constexpr int OFF_AN = 31744;
    constexpr int OFF_CN = 32768;
    constexpr int OFF_BUF = 0;
    constexpr int OFF_SSUM = 18432;
    constexpr int OFF_SSQ = 18688;
    constexpr int EST = 72;

    __shared__ __align__(16) char SM[33792];
    __nv_bfloat16* sAh = reinterpret_cast<__nv_bfloat16*>(SM + OFF_AH);
    __nv_bfloat16* sAl = reinterpret_cast<__nv_bfloat16*>(SM + OFF_AL);
    __nv_bfloat16* sBh = reinterpret_cast<__nv_bfloat16*>(SM + OFF_BH);
    __nv_bfloat16* sBl = reinterpret_cast<__nv_bfloat16*>(SM + OFF_BL);
    int* sdst = reinterpret_cast<int*>(SM + OFF_DST);
    int* ssrc = reinterpret_cast<int*>(SM + OFF_SRC);
    float* sAn = reinterpret_cast<float*>(SM + OFF_AN);
    float* sCn = reinterpret_cast<float*>(SM + OFF_CN);

    const int tid = threadIdx.x;
    const int lane = tid & 31;
    const int wid = tid >> 5;
    const int wm = wid & 3;
    const int wn = wid >> 2;
    const int e0 = blockIdx.x * 128;
    const int col0 = blockIdx.y * BN;

    const uint32_t sAh_u = smem_u32(sAh);
    const uint32_t sAl_u = smem_u32(sAl);
    const uint32_t sBh_u = smem_u32(sBh);
    const uint32_t sBl_u = smem_u32(sBl);

    if (MODE == 1) {
        if (tid < 128) {
            int e = e0 + tid;
            int ee = (e < Rows) ? e : (Rows - 1);
            sdst[tid] = dst[ee];
            ssrc[tid] = src[ee];
        }
        for (int i = tid; i < K; i += 256) { sAn[i] = an[i]; sCn[i] = cn[i]; }
    }
    __syncthreads();

    float acc[2][NT][4];
#pragma unroll
    for (int mt = 0; mt < 2; mt++)
#pragma unroll
        for (int nt = 0; nt < NT; nt++)
#pragma unroll
            for (int j = 0; j < 4; j++) acc[mt][nt][j] = 0.f;

    const int arow = tid >> 1;
    const int acg = (tid & 1) * 16;
    int nd = 0, ns = 0;
    if (MODE == 1) { nd = sdst[arow]; ns = ssrc[arow]; }

    const int bn_ = tid >> 2;
    const int bu_ = tid & 3;
    const int bdoff = bn_ * SAS + bu_ * 8;

    float4 P[4], Q[4];
    uint4 BHr, BLr;

    auto load_chunk = [&](int ch) {
        const int k0 = ch * 32 + acg;
        if (MODE == 1) {
            const float* Ur = fA + (size_t)nd * ASTR;
            const float* Vr = fA + (size_t)ns * ASTR + K;
#pragma unroll
            for (int u = 0; u < 4; u++) {
                P[u] = *reinterpret_cast<const float4*>(Ur + k0 + u * 4);
                Q[u] = *reinterpret_cast<const float4*>(Vr + k0 + u * 4);
            }
        } else {
            const int i = e0 + arow;
            if (K % 4 == 0) {
                if (i < Rows) {
#pragma unroll
                    for (int u = 0; u < 4; u++)
                        P[u] = *reinterpret_cast<const float4*>(&fA[(size_t)i * K + k0 + u * 4]);
                } else {
#pragma unroll
                    for (int u = 0; u < 4; u++) P[u] = make_float4(0.f, 0.f, 0.f, 0.f);
                }
            } else {  // K=7 scalar path (NCH==1)
#pragma unroll
                for (int u = 0; u < 4; u++) {
                    float t[4];
#pragma unroll
                    for (int j = 0; j < 4; j++) {
                        int kk = k0 + u * 4 + j;
                        t[j] = (i < Rows && kk < K) ? fA[(size_t)i * K + kk] : 0.f;
                    }
                    P[u] = make_float4(t[0], t[1], t[2], t[3]);
                }
            }
        }
    };
    auto load_B = [&](int ch) {
        size_t soff = (size_t)(col0 + bn_) * KPAD + ch * 32 + bu_ * 8;
        BHr = *reinterpret_cast<const uint4*>(Wth + soff);
        BLr = *reinterpret_cast<const uint4*>(Wtl + soff);
    };
    auto store_chunk = [&](int ch) {
        const int k0 = ch * 32 + acg;
#pragma unroll
        for (int u = 0; u < 4; u++) {
            float4 v;
            if (MODE == 1) {
                const int k = k0 + u * 4;
                v.x = fmaxf((P[u].x + Q[u].x) * sAn[k + 0] + sCn[k + 0], 0.f);
                v.y = fmaxf((P[u].y + Q[u].y) * sAn[k + 1] + sCn[k + 1], 0.f);
                v.z = fmaxf((P[u].z + Q[u].z) * sAn[k + 2] + sCn[k + 2], 0.f);
                v.w = fmaxf((P[u].w + Q[u].w) * sAn[k + 3] + sCn[k + 3], 0.f);
            } else {
                v = P[u];
            }
            __nv_bfloat162 h01 = __float22bfloat162_rn(make_float2(v.x, v.y));
            __nv_bfloat162 h23 = __float22bfloat162_rn(make_float2(v.z, v.w));
            float2 hf01 = __bfloat1622float2(h01);
            float2 hf23 = __bfloat1622float2(h23);
            __nv_bfloat162 l01 = __float22bfloat162_rn(make_float2(v.x - hf01.x, v.y - hf01.y));
            __nv_bfloat162 l23 = __float22bfloat162_rn(make_float2(v.z - hf23.x, v.w - hf23.y));
            uint2 H, L;
            H.x = *reinterpret_cast<uint32_t*>(&h01);
            H.y = *reinterpret_cast<uint32_t*>(&h23);
            L.x = *reinterpret_cast<uint32_t*>(&l01);
            L.y = *reinterpret_cast<uint32_t*>(&l23);
            int so = arow * SAS + acg + u * 4;
            *reinterpret_cast<uint2*>(&sAh[so]) = H;
            *reinterpret_cast<uint2*>(&sAl[so]) = L;
        }
        *reinterpret_cast<uint4*>(&sBh[bdoff]) = BHr;
        *reinterpret_cast<uint4*>(&sBl[bdoff]) = BLr;
    };

    const int a_lrow = (lane & 7) + ((lane >> 3) & 1) * 8;
    const int a_lcol = (lane >> 4) * 8;
    const int b_lrow = (lane & 7) + (lane >> 4) * 8;
    const int b_lcol = ((lane >> 3) & 1) * 8;

    load_chunk(0);
    load_B(0);

    for (int ch = 0; ch < NCH; ch++) {
        store_chunk(ch);
        __syncthreads();

        if (ch + 1 < NCH) { load_chunk(ch + 1); load_B(ch + 1); }

#pragma unroll
        for (int ks = 0; ks < 2; ks++) {
            const int kb = ks * 16;
            uint32_t ah[2][4], al[2][4];
#pragma unroll
            for (int mt = 0; mt < 2; mt++) {
                int r = wm * 32 + mt * 16 + a_lrow;
                uint32_t off = (uint32_t)(r * SAS + kb + a_lcol) * 2;
                LDSM_X4(ah[mt][0], ah[mt][1], ah[mt][2], ah[mt][3], sAh_u + off);
                LDSM_X4(al[mt][0], al[mt][1], al[mt][2], al[mt][3], sAl_u + off);
            }
#pragma unroll
            for (int p = 0; p < NT / 2; p++) {
                int n0 = wn * (BN / 2) + p * 16;
                uint32_t boff = (uint32_t)((n0 + b_lrow) * SAS + kb + b_lcol) * 2;
                uint32_t bh[4], bl[4];
                LDSM_X4(bh[0], bh[1], bh[2], bh[3], sBh_u + boff);
                LDSM_X4(bl[0], bl[1], bl[2], bl[3], sBl_u + boff);
#pragma unroll
                for (int mt = 0; mt < 2; mt++) {
                    MMA_BF16(acc[mt][2 * p], ah[mt], (&bh[0]));
                    MMA_BF16(acc[mt][2 * p], ah[mt], (&bl[0]));
                    MMA_BF16(acc[mt][2 * p], al[mt], (&bh[0]));
                    MMA_BF16(acc[mt][2 * p + 1], ah[mt], (&bh[2]));
                    MMA_BF16(acc[mt][2 * p + 1], ah[mt], (&bl[2]));
                    MMA_BF16(acc[mt][2 * p + 1], al[mt], (&bh[2]));
                }
            }
        }
        __syncthreads();
    }

    // ---- epilogue ----
    float* ebuf = reinterpret_cast<float*>(SM + OFF_BUF);
    float* ssum = reinterpret_cast<float*>(SM + OFF_SSUM);
    float* ssq = reinterpret_cast<float*>(SM + OFF_SSQ);

    const int q = lane >> 2, s = lane & 3;

#pragma unroll
    for (int nt = 0; nt < NT; nt++) {
        const int col = col0 + wn * (BN / 2) + nt * 8 + s * 2;
        const float b0 = bias[col], b1 = bias[col + 1];
#pragma unroll
        for (int mt = 0; mt < 2; mt++) {
            acc[mt][nt][0] += b0; acc[mt][nt][1] += b1;
            acc[mt][nt][2] += b0; acc[mt][nt][3] += b1;
        }
    }

    if (STATS) {
        if (tid < 2 * BN) reinterpret_cast<float*>(SM + OFF_SSUM)[tid] = 0.f;
        __syncthreads();
#pragma unroll
        for (int nt = 0; nt < NT; nt++) {
            const int colw = wn * (BN / 2) + nt * 8 + s * 2;
            float s0 = 0.f, q0 = 0.f, s1 = 0.f, q1 = 0.f;
#pragma unroll
            for (int mt = 0; mt < 2; mt++) {
                const int r = wm * 32 + mt * 16 + q;
                if (e0 + r < Rows) {
                    s0 += acc[mt][nt][0]; q0 += acc[mt][nt][0] * acc[mt][nt][0];
                    s1 += acc[mt][nt][1]; q1 += acc[mt][nt][1] * acc[mt][nt][1];
                }
                if (e0 + r + 8 < Rows) {
                    s0 += acc[mt][nt][2]; q0 += acc[mt][nt][2] * acc[mt][nt][2];
                    s1 += acc[mt][nt][3]; q1 += acc[mt][nt][3] * acc[mt][nt][3];
                }
            }
#pragma unroll
            for (int m = 4; m <= 16; m <<= 1) {
                s0 += __shfl_xor_sync(0xffffffff, s0, m);
                q0 += __shfl_xor_sync(0xffffffff, q0, m);
                s1 += __shfl_xor_sync(0xffffffff, s1, m);
                q1 += __shfl_xor_sync(0xffffffff, q1, m);
            }
            if (q == 0) {
                atomicAdd(&ssum[colw], s0);
                atomicAdd(&ssq[colw], q0);
                atomicAdd(&ssum[colw + 1], s1);
                atomicAdd(&ssq[colw + 1], q1);
            }
        }
        __syncthreads();
        if (tid < BN) {
            atomicAdd(&stat_sum[col0 + tid], ssum[tid]);
            atomicAdd(&stat_sq[col0 + tid], ssq[tid]);
        }
    }

    // coalesced smem-staged store
#pragma unroll
    for (int pass = 0; pass < 2; pass++) {
        __syncthreads();
        if ((wm >> 1) == pass) {
            const int wml = wm & 1;
#pragma unroll
            for (int mt = 0; mt < 2; mt++) {
                const int rl = wml * 32 + mt * 16 + q;
#pragma unroll
                for (int nt = 0; nt < NT; nt++) {
                    const int colw = wn * (BN / 2) + nt * 8 + s * 2;
                    *reinterpret_cast<float2*>(&ebuf[rl * EST + colw]) =
                        make_float2(acc[mt][nt][0], acc[mt][nt][1]);
                    *reinterpret_cast<float2*>(&ebuf[(rl + 8) * EST + colw]) =
                        make_float2(acc[mt][nt][2], acc[mt][nt][3]);
                }
            }
        }
        __syncthreads();
#pragma unroll
        for (int ii = 0; ii < 4; ii++) {
            const int i = tid + ii * 256;
            const int row = i >> 4, c4 = i & 15;
            const int e = e0 + pass * 64 + row;
            if (e < Rows) {
                float4 v = *reinterpret_cast<float4*>(&ebuf[row * EST + c4 * 4]);
                *reinterpret_cast<float4*>(&out[(size_t)e * OC + col0 + c4 * 4]) = v;
            }
        }
    }
}

// ---------------- edge stats of t1 = U[dst]+V[src] (bias already in U) ------
template <int OC>
__global__ __launch_bounds__(256)
void estats_kernel(const float* __restrict__ UV,
                   const int* __restrict__ src, const int* __restrict__ dst,
                   float* __restrict__ sum, float* __restrict__ sq, int E) {
    constexpr int R = OC / 32;
    __shared__ float ss[OC], sv[OC];
    const int tid = threadIdx.x, lane = tid & 31, wid = tid >> 5;
    for (int i = tid; i < OC; i += 256) { ss[i] = 0.f; sv[i] = 0.f; }
    __syncthreads();
    float s[R], q[R];
#pragma unroll
    for (int j = 0; j < R; j++) { s[j] = 0.f; q[j] = 0.f; }
    for (int e = blockIdx.x * 8 + wid; e < E; e += gridDim.x * 8) {
        const int nd = dst[e], ns = src[e];
        const float* Ur = UV + (size_t)nd * (2 * OC);
        const float* Vr = UV + (size_t)ns * (2 * OC) + OC;
#pragma unroll
        for (int j = 0; j < R; j++) {
            float v = Ur[j * 32 + lane] + Vr[j * 32 + lane];
            s[j] += v; q[j] += v * v;
        }
    }
#pragma unroll
    for (int j = 0; j < R; j++) {
        atomicAdd(&ss[j * 32 + lane], s[j]);
        atomicAdd(&sv[j * 32 + lane], q[j]);
    }
    __syncthreads();
    for (int i = tid; i < OC; i += 256) {
        atomicAdd(&sum[i], ss[i]);
        atomicAdd(&sq[i], sv[i]);
    }
}

// ---------------- BN finalize ----------------
__global__ void finalize_kernel(const float* __restrict__ sum, const float* __restrict__ sq,
                                const float* __restrict__ gamma, const float* __restrict__ beta,
                                float* __restrict__ a, float* __restrict__ c,
                                int OC, float invE) {
    int i = blockIdx.x * blockDim.x + threadIdx.x;
    if (i < OC) {
        float m = sum[i] * invE;
        float var = sq[i] * invE - m * m;
        float rs = rsqrtf(var + 1e-5f);
        float ai = gamma[i] * rs;
        a[i] = ai;
        c[i] = beta[i] - m * ai;
    }
}

// ---------------- normalize + relu + mean-aggregate (CSR, warp per node) ----
template <int OC>
__global__ __launch_bounds__(256)
void aggregate_kernel(const float* __restrict__ t, const int* __restrict__ rowptr,
                      const int* __restrict__ eidx, const float* __restrict__ a,
                      const float* __restrict__ c, float* __restrict__ hout, int n) {
    int warp = (blockIdx.x * blockDim.x + threadIdx.x) >> 5;
    int lane = threadIdx.x & 31;
    if (warp >= n) return;
    constexpr int R = OC / 32;
    float av[R], cv[R], acc[R];
#pragma unroll
    for (int j = 0; j < R; j++) {
        int ch = j * 32 + lane;
        av[j] = a[ch]; cv[j] = c[ch]; acc[j] = 0.f;
    }
    int beg = rowptr[warp], end = rowptr[warp + 1];
    for (int p = beg; p < end; p++) {
        int e = eidx[p];
        const float* rowp = t + (size_t)e * OC;
#pragma unroll
        for (int j = 0; j < R; j++) {
            float v = rowp[j * 32 + lane];
            acc[j] += fmaxf(v * av[j] + cv[j], 0.f);
        }
    }
    float inv = 1.f / fmaxf((float)(end - beg), 1.f);
#pragma unroll
    for (int j = 0; j < R; j++) hout[(size_t)warp * OC + j * 32 + lane] = acc[j] * inv;
}

// ---------------- global mean pool + head ----------------
__global__ void pool_kernel(const float* __restrict__ h, const int* __restrict__ gstart,
                            float* __restrict__ pool) {
    int g = blockIdx.x;
    int ch = threadIdx.x;
    int beg = gstart[g], end = gstart[g + 1];
    float s = 0.f;
    for (int nidx = beg; nidx < end; nidx++) s += h[(size_t)nidx * 256 + ch];
    pool[g * 256 + ch] = s / fmaxf((float)(end - beg), 1.f);
}
__global__ void head1_kernel(const float* __restrict__ pool, const float* __restrict__ W,
                             const float* __restrict__ b, float* __restrict__ z) {
    int g = blockIdx.x, j = threadIdx.x;
    __shared__ float sp[256];
    sp[j] = pool[g * 256 + j];
    sp[j + 128] = pool[g * 256 + j + 128];
    __syncthreads();
    float s = b[j];
#pragma unroll 8
    for (int k = 0; k < 256; k++) s += sp[k] * W[k * 128 + j];
    z[g * 128 + j] = fmaxf(s, 0.f);
}
__global__ void head2_kernel(const float* __restrict__ z, const float* __restrict__ W,
                             const float* __restrict__ b, float* __restrict__ out) {
    int t = threadIdx.x;
    int g = t >> 1, j = t & 1;
    float s = b[j];
#pragma unroll 8
    for (int k = 0; k < 128; k++) s += z[g * 128 + k] * W[k * 2 + j];
    out[g * 2 + j] = s;
}

// ---------------- launch ----------------
extern "C" void kernel_launch(void* const* d_in, const int* in_sizes, int n_in,
                              void* d_out, int out_size) {
    const float* x     = (const float*)d_in[0];
    const int*   ei    = (const int*)d_in[1];
    const int*   batch = (const int*)d_in[2];

    const int E = in_sizes[1] / 2;
    const int n = in_sizes[2];
    const int* srcp = ei;
    const int* dstp = ei + E;

    const float* W[3][2];  const float* B[3][2];
    const float* Gm[3][2]; const float* Bt[3][2];
    for (int l = 0; l < 3; l++) {
        int base = 3 + l * 8;
        W[l][0]  = (const float*)d_in[base + 0];
        B[l][0]  = (const float*)d_in[base + 1];
        Gm[l][0] = (const float*)d_in[base + 2];
        Bt[l][0] = (const float*)d_in[base + 3];
        W[l][1]  = (const float*)d_in[base + 4];
        B[l][1]  = (const float*)d_in[base + 5];
        Gm[l][1] = (const float*)d_in[base + 6];
        Bt[l][1] = (const float*)d_in[base + 7];
    }
    const float* hW1 = (const float*)d_in[27];
    const float* hb1 = (const float*)d_in[28];
    const float* hW2 = (const float*)d_in[29];
    const float* hb2 = (const float*)d_in[30];

    float *UV, *t2, *hA, *hB, *stats, *norm, *pool, *zbuf, *bias2;
    int *deg, *rowptr, *cursor, *eidx, *cnt, *gstart;
    __nv_bfloat16 *wth, *wtl;
    cudaGetSymbolAddress((void**)&UV, g_t1);
    cudaGetSymbolAddress((void**)&t2, g_t2);
    cudaGetSymbolAddress((void**)&hA, g_hA);
    cudaGetSymbolAddress((void**)&hB, g_hB);
    cudaGetSymbolAddress((void**)&stats, g_stats);
    cudaGetSymbolAddress((void**)&norm, g_norm);
    cudaGetSymbolAddress((void**)&bias2, g_bias2);
    cudaGetSymbolAddress((void**)&deg, g_deg);
    cudaGetSymbolAddress((void**)&rowptr, g_rowptr);
    cudaGetSymbolAddress((void**)&cursor, g_cursor);
    cudaGetSymbolAddress((void**)&eidx, g_eidx);
    cudaGetSymbolAddress((void**)&cnt, g_cnt);
    cudaGetSymbolAddress((void**)&gstart, g_gstart);
    cudaGetSymbolAddress((void**)&pool, g_pool);
    cudaGetSymbolAddress((void**)&zbuf, g_zbuf);
    cudaGetSymbolAddress((void**)&wth, g_wth);
    cudaGetSymbolAddress((void**)&wtl, g_wtl);

    float* sum1 = stats + 0;   float* sq1 = stats + 256;
    float* sum2 = stats + 512; float* sq2 = stats + 768;
    float* a1 = norm + 0;   float* c1 = norm + 256;
    float* a2 = norm + 512; float* c2 = norm + 768;

    // weight offsets: L1split(128x32)=0, L1W2(64x64)=4096,
    //   L2split(256x64)=8192, L2W2(128x128)=24576,
    //   L3split(512x128)=40960, L3W2(256x256)=106496
    const float invE = 1.f / (float)E;
    const int EB = (E + 127) / 128;
    const int NB = (n + 127) / 128;
    const int EG = (E + 255) / 256;
    const int NG = (n + 255) / 256;
    const int AGG = (n * 32 + 255) / 256;
    const int SGRID = 1184;

    // ---- CSR build ----
    cudaMemsetAsync(deg, 0, n * sizeof(int));
    cudaMemsetAsync(cnt, 0, GG * sizeof(int));
    hist_deg_kernel<<<EG, 256>>>(dstp, deg, E);
    hist_cnt_kernel<<<NG, 256>>>(batch, cnt, n);
    scan_kernel<<<1, 1024>>>(deg, rowptr, cursor, cnt, gstart, n);
    fill_csr_kernel<<<EG, 256>>>(dstp, cursor, eidx, E);

    // ---- weight conversion ----
    convert_wsplit_kernel<<<(128 * 32 + 255) / 256, 256>>>(W[0][0], wth + 0, wtl + 0, 7, 64, 32);
    convert_w_kernel<<<(64 * 64 + 255) / 256, 256>>>(W[0][1], wth + 4096, wtl + 4096, 64, 64, 64);
    convert_wsplit_kernel<<<(256 * 64 + 255) / 256, 256>>>(W[1][0], wth + 8192, wtl + 8192, 64, 128, 64);
    convert_w_kernel<<<(128 * 128 + 255) / 256, 256>>>(W[1][1], wth + 24576, wtl + 24576, 128, 128, 128);
    convert_wsplit_kernel<<<(512 * 128 + 255) / 256, 256>>>(W[2][0], wth + 40960, wtl + 40960, 128, 256, 128);
    convert_w_kernel<<<(256 * 256 + 255) / 256, 256>>>(W[2][1], wth + 106496, wtl + 106496, 256, 256, 256);

    // ==== layer 1: 7 -> 64 ====
    cudaMemsetAsync(bias2, 0, 512 * sizeof(float));
    cudaMemcpyAsync(bias2, B[0][0], 64 * sizeof(float), cudaMemcpyDeviceToDevice);
    zero_stats_kernel<<<1, 256>>>(stats);
    mgemm_kernel<7, 128, 0, false><<<dim3(NB, 2), 256>>>(
        x, nullptr, nullptr, nullptr, nullptr, wth + 0, wtl + 0, bias2, UV, nullptr, nullptr, n);
    estats_kernel<64><<<SGRID, 256>>>(UV, srcp, dstp, sum1, sq1, E);
    finalize_kernel<<<1, 64>>>(sum1, sq1, Gm[0][0], Bt[0][0], a1, c1, 64, invE);
    mgemm_kernel<64, 64, 1, true><<<dim3(EB, 1), 256>>>(
        UV, srcp, dstp, a1, c1, wth + 4096, wtl + 4096, B[0][1], t2, sum2, sq2, E);
    finalize_kernel<<<1, 64>>>(sum2, sq2, Gm[0][1], Bt[0][1], a2, c2, 64, invE);
    aggregate_kernel<64><<<AGG, 256>>>(t2, rowptr, eidx, a2, c2, hA, n);

    // ==== layer 2: 64 -> 128 ====
    cudaMemsetAsync(bias2, 0, 512 * sizeof(float));
    cudaMemcpyAsync(bias2, B[1][0], 128 * sizeof(float), cudaMemcpyDeviceToDevice);
    zero_stats_kernel<<<1, 256>>>(stats);
    mgemm_kernel<64, 256, 0, false><<<dim3(NB, 4), 256>>>(
        hA, nullptr, nullptr, nullptr, nullptr, wth + 8192, wtl + 8192, bias2, UV, nullptr, nullptr, n);
    estats_kernel<128><<<SGRID, 256>>>(UV, srcp, dstp, sum1, sq1, E);
    finalize_kernel<<<1, 128>>>(sum1, sq1, Gm[1][0], Bt[1][0], a1, c1, 128, invE);
    mgemm_kernel<128, 128, 1, true><<<dim3(EB, 2), 256>>>(
        UV, srcp, dstp, a1, c1, wth + 24576, wtl + 24576, B[1][1], t2, sum2, sq2, E);
    finalize_kernel<<<1, 128>>>(sum2, sq2, Gm[1][1], Bt[1][1], a2, c2, 128, invE);
    aggregate_kernel<128><<<AGG, 256>>>(t2, rowptr, eidx, a2, c2, hB, n);

    // ==== layer 3: 128 -> 256 ====
    cudaMemsetAsync(bias2, 0, 512 * sizeof(float));
    cudaMemcpyAsync(bias2, B[2][0], 256 * sizeof(float), cudaMemcpyDeviceToDevice);
    zero_stats_kernel<<<1, 256>>>(stats);
    mgemm_kernel<128, 512, 0, false><<<dim3(NB, 8), 256>>>(
        hB, nullptr, nullptr, nullptr, nullptr, wth + 40960, wtl + 40960, bias2, UV, nullptr, nullptr, n);
    estats_kernel<256><<<SGRID, 256>>>(UV, srcp, dstp, sum1, sq1, E);
    finalize_kernel<<<1, 256>>>(sum1, sq1, Gm[2][0], Bt[2][0], a1, c1, 256, invE);
    mgemm_kernel<256, 256, 1, true><<<dim3(EB, 4), 256>>>(
        UV, srcp, dstp, a1, c1, wth + 106496, wtl + 106496, B[2][1], t2, sum2, sq2, E);
    finalize_kernel<<<1, 256>>>(sum2, sq2, Gm[2][1], Bt[2][1], a2, c2, 256, invE);
    aggregate_kernel<256><<<AGG, 256>>>(t2, rowptr, eidx, a2, c2, hA, n);

    // ---- pool + head ----
    pool_kernel<<<GG, 256>>>(hA, gstart, pool);
    head1_kernel<<<GG, 128>>>(pool, hW1, hb1, zbuf);
    head2_kernel<<<1, 128>>>(zbuf, hW2, hb2, (float*)d_out);
}

// round 10
// speedup vs baseline: 1.6675x; 1.0941x over previous
#include <cuda_runtime.h>
#include <cuda_bf16.h>
#include <cstdint>

// ---------------- problem constants ----------------
#define NN 50000
#define EE 500000
#define GG 64

// ---------------- scratch (device globals; no allocation allowed) ----------
__device__ float g_t1[(size_t)EE * 256];     // UV node buffer (<= 50K x 512)
__device__ float g_t2[(size_t)EE * 256];     // edge intermediate t2 (PERMUTED order)
__device__ float g_hA[(size_t)NN * 256];
__device__ float g_hB[(size_t)NN * 256];
__device__ float g_stats[1024];
__device__ float g_norm[1024];
__device__ float g_bias2[512];
__device__ int   g_deg[NN];
__device__ int   g_rowptr[NN + 1];
__device__ int   g_cursor[NN];
__device__ int   g_eidx[EE];
__device__ int   g_psrc[EE];
__device__ int   g_pdst[EE];
__device__ int   g_cnt[GG];
__device__ int   g_gstart[GG + 1];
__device__ float g_pool[GG * 256];
__device__ float g_zbuf[GG * 128];
__device__ __nv_bfloat16 g_wth[172032];
__device__ __nv_bfloat16 g_wtl[172032];

// ---------------- mma.sync / ldmatrix helpers ------------------------------
#define MMA_BF16(d, a, b)                                                        \
    asm volatile("mma.sync.aligned.m16n8k16.row.col.f32.bf16.bf16.f32 "          \
                 "{%0,%1,%2,%3}, {%4,%5,%6,%7}, {%8,%9}, {%0,%1,%2,%3};"         \
                 : "+f"((d)[0]), "+f"((d)[1]), "+f"((d)[2]), "+f"((d)[3])        \
                 : "r"((a)[0]), "r"((a)[1]), "r"((a)[2]), "r"((a)[3]),           \
                   "r"((b)[0]), "r"((b)[1]))

#define LDSM_X4(r0, r1, r2, r3, addr)                                            \
    asm volatile("ldmatrix.sync.aligned.m8n8.x4.shared.b16 {%0,%1,%2,%3}, [%4];" \
                 : "=r"(r0), "=r"(r1), "=r"(r2), "=r"(r3) : "r"(addr))

__device__ __forceinline__ uint32_t smem_u32(const void* p) {
    uint32_t a;
    asm("{ .reg .u64 t; cvta.to.shared.u64 t, %1; cvt.u32.u64 %0, t; }" : "=r"(a) : "l"(p));
    return a;
}

// ---------------- small utility kernels ----------------
__global__ void zero_stats_kernel(float* __restrict__ s) {
    int i = threadIdx.x;
#pragma unroll
    for (int j = 0; j < 4; j++) s[i + j * 256] = 0.f;
}

__global__ void hist_deg_kernel(const int* __restrict__ dst, int* __restrict__ deg, int E) {
    int e = blockIdx.x * blockDim.x + threadIdx.x;
    if (e < E) atomicAdd(&deg[dst[e]], 1);
}
__global__ void hist_cnt_kernel(const int* __restrict__ batch, int* __restrict__ cnt, int n) {
    int i = blockIdx.x * blockDim.x + threadIdx.x;
    if (i < n) atomicAdd(&cnt[batch[i]], 1);
}
__global__ void scan_kernel(const int* __restrict__ deg, int* __restrict__ rowptr,
                            int* __restrict__ cursor, const int* __restrict__ cnt,
                            int* __restrict__ gstart, int n) {
    __shared__ int sh[1024];
    __shared__ int carry;
    int t = threadIdx.x;
    if (t == 0) carry = 0;
    __syncthreads();
    for (int base = 0; base < n; base += 1024) {
        int idx = base + t;
        int v = (idx < n) ? deg[idx] : 0;
        sh[t] = v;
        __syncthreads();
        for (int off = 1; off < 1024; off <<= 1) {
            int add = (t >= off) ? sh[t - off] : 0;
            __syncthreads();
            sh[t] += add;
            __syncthreads();
        }
        int ex = sh[t] - v;
        int cbase = carry;
        if (idx < n) { rowptr[idx] = cbase + ex; cursor[idx] = cbase + ex; }
        __syncthreads();
        if (t == 1023) carry = cbase + sh[1023];
        __syncthreads();
    }
    if (t == 0) {
        rowptr[n] = carry;
        int s = 0;
        for (int g = 0; g < GG; g++) { gstart[g] = s; s += cnt[g]; }
        gstart[GG] = s;
    }
}
__global__ void fill_csr_kernel(const int* __restrict__ dst, int* __restrict__ cursor,
                                int* __restrict__ eidx, int E) {
    int e = blockIdx.x * blockDim.x + threadIdx.x;
    if (e < E) {
        int p = atomicAdd(&cursor[dst[e]], 1);
        eidx[p] = e;
    }
}
// psrc[p] = src[eidx[p]], pdst[p] = dst[eidx[p]]  (pdst is sorted)
__global__ void build_perm_kernel(const int* __restrict__ eidx,
                                  const int* __restrict__ src, const int* __restrict__ dst,
                                  int* __restrict__ psrc, int* __restrict__ pdst, int E) {
    int p = blockIdx.x * blockDim.x + threadIdx.x;
    if (p < E) {
        int e = eidx[p];
        psrc[p] = src[e];
        pdst[p] = dst[e];
    }
}

// W2[K,OC] fp32 -> Wt[OC][KPAD] bf16 hi/lo (transposed)
__global__ void convert_w_kernel(const float* __restrict__ W,
                                 __nv_bfloat16* __restrict__ Wth,
                                 __nv_bfloat16* __restrict__ Wtl,
                                 int K, int OC, int KPAD) {
    int idx = blockIdx.x * blockDim.x + threadIdx.x;
    if (idx >= OC * KPAD) return;
    int n = idx / KPAD, k = idx % KPAD;
    float w = (k < K) ? W[(size_t)k * OC + n] : 0.f;
    __nv_bfloat16 h = __float2bfloat16_rn(w);
    Wth[idx] = h;
    Wtl[idx] = __float2bfloat16_rn(w - __bfloat162float(h));
}

// W1[2C,OC] -> combined [2OC][KPAD(C)]: rows 0..OC-1 = (Wa-Wb)^T, OC..2OC-1 = Wb^T
__global__ void convert_wsplit_kernel(const float* __restrict__ W1,
                                      __nv_bfloat16* __restrict__ Wth,
                                      __nv_bfloat16* __restrict__ Wtl,
                                      int C, int OC, int KPAD) {
    int idx = blockIdx.x * blockDim.x + threadIdx.x;
    if (idx >= 2 * OC * KPAD) return;
    int n = idx / KPAD, k = idx % KPAD;
    float w = 0.f;
    if (k < C) {
        if (n < OC) w = W1[(size_t)k * OC + n] - W1[(size_t)(k + C) * OC + n];
        else        w = W1[(size_t)(k + C) * OC + (n - OC)];
    }
    __nv_bfloat16 h = __float2bfloat16_rn(w);
    Wth[idx] = h;
    Wtl[idx] = __float2bfloat16_rn(w - __bfloat162float(h));
}

// ---------------- tensor-core GEMM ------------------------------------------
// MODE 0: node GEMM. A row i = fA[i*K ..].  Rows = N.
// MODE 1: edge GEMM over PERMUTED edges.  A row p = relu((U[pdst[p]] +
//         V[psrc[p]]) * an + cn); U row = fA + nd*2K, V row = fA + ns*2K + K.
//         Output row p (permuted order).  pdst sorted -> U gathers cache-hot.
template <int K, int OC, int MODE, bool STATS>
__global__ __launch_bounds__(256, 2)
void mgemm_kernel(const float* __restrict__ fA,
                  const int* __restrict__ src, const int* __restrict__ dst,
                  const float* __restrict__ an, const float* __restrict__ cn,
                  const __nv_bfloat16* __restrict__ Wth,
                  const __nv_bfloat16* __restrict__ Wtl,
                  const float* __restrict__ bias,
                  float* __restrict__ out,
                  float* __restrict__ stat_sum, float* __restrict__ stat_sq,
                  int Rows) {
    constexpr int BN = 64;
    constexpr int KPAD = (K + 31) / 32 * 32;
    constexpr int NCH = KPAD / 32;
    constexpr int NT = BN / 16;
    constexpr int SAS = 40;
    constexpr int ASTR = (MODE == 1) ? 2 * K : K;

    constexpr int OFF_AH = 0;
    constexpr int OFF_AL = 10240;
    constexpr int OFF_BH = 20480;
    constexpr int OFF_BL = 25600;
    constexpr int OFF_DST = 30720;
    constexpr int OFF_SRC = 31232;
    constexpr int OFF_AN = 31744;
    constexpr int OFF_CN = 32768;
    constexpr int OFF_BUF = 0;
    constexpr int OFF_SSUM = 18432;
    constexpr int OFF_SSQ = 18688;
    constexpr int EST = 72;

    __shared__ __align__(16) char SM[33792];
    __nv_bfloat16* sAh = reinterpret_cast<__nv_bfloat16*>(SM + OFF_AH);
    __nv_bfloat16* sAl = reinterpret_cast<__nv_bfloat16*>(SM + OFF_AL);
    __nv_bfloat16* sBh = reinterpret_cast<__nv_bfloat16*>(SM + OFF_BH);
    __nv_bfloat16* sBl = reinterpret_cast<__nv_bfloat16*>(SM + OFF_BL);
    int* sdst = reinterpret_cast<int*>(SM + OFF_DST);
    int* ssrc = reinterpret_cast<int*>(SM + OFF_SRC);
    float* sAn = reinterpret_cast<float*>(SM + OFF_AN);
    float* sCn = reinterpret_cast<float*>(SM + OFF_CN);

    const int tid = threadIdx.x;
    const int lane = tid & 31;
    const int wid = tid >> 5;
    const int wm = wid & 3;
    const int wn = wid >> 2;
    const int e0 = blockIdx.x * 128;
    const int col0 = blockIdx.y * BN;

    const uint32_t sAh_u = smem_u32(sAh);
    const uint32_t sAl_u = smem_u32(sAl);
    const uint32_t sBh_u = smem_u32(sBh);
    const uint32_t sBl_u = smem_u32(sBl);

    if (MODE == 1) {
        if (tid < 128) {
            int e = e0 + tid;
            int ee = (e < Rows) ? e : (Rows - 1);
            sdst[tid] = dst[ee];
            ssrc[tid] = src[ee];
        }
        for (int i = tid; i < K; i += 256) { sAn[i] = an[i]; sCn[i] = cn[i]; }
    }
    __syncthreads();

    float acc[2][NT][4];
#pragma unroll
    for (int mt = 0; mt < 2; mt++)
#pragma unroll
        for (int nt = 0; nt < NT; nt++)
#pragma unroll
            for (int j = 0; j < 4; j++) acc[mt][nt][j] = 0.f;

    const int arow = tid >> 1;
    const int acg = (tid & 1) * 16;
    int nd = 0, ns = 0;
    if (MODE == 1) { nd = sdst[arow]; ns = ssrc[arow]; }

    const int bn_ = tid >> 2;
    const int bu_ = tid & 3;
    const int bdoff = bn_ * SAS + bu_ * 8;

    float4 P[4], Q[4];
    uint4 BHr, BLr;

    auto load_chunk = [&](int ch) {
        const int k0 = ch * 32 + acg;
        if (MODE == 1) {
            const float* Ur = fA + (size_t)nd * ASTR;
            const float* Vr = fA + (size_t)ns * ASTR + K;
#pragma unroll
            for (int u = 0; u < 4; u++) {
                P[u] = *reinterpret_cast<const float4*>(Ur + k0 + u * 4);
                Q[u] = *reinterpret_cast<const float4*>(Vr + k0 + u * 4);
            }
        } else {
            const int i = e0 + arow;
            if (K % 4 == 0) {
                if (i < Rows) {
#pragma unroll
                    for (int u = 0; u < 4; u++)
                        P[u] = *reinterpret_cast<const float4*>(&fA[(size_t)i * K + k0 + u * 4]);
                } else {
#pragma unroll
                    for (int u = 0; u < 4; u++) P[u] = make_float4(0.f, 0.f, 0.f, 0.f);
                }
            } else {  // K=7 scalar path (NCH==1)
#pragma unroll
                for (int u = 0; u < 4; u++) {
                    float t[4];
#pragma unroll
                    for (int j = 0; j < 4; j++) {
                        int kk = k0 + u * 4 + j;
                        t[j] = (i < Rows && kk < K) ? fA[(size_t)i * K + kk] : 0.f;
                    }
                    P[u] = make_float4(t[0], t[1], t[2], t[3]);
                }
            }
        }
    };
    auto load_B = [&](int ch) {
        size_t soff = (size_t)(col0 + bn_) * KPAD + ch * 32 + bu_ * 8;
        BHr = *reinterpret_cast<const uint4*>(Wth + soff);
        BLr = *reinterpret_cast<const uint4*>(Wtl + soff);
    };
    auto store_chunk = [&](int ch) {
        const int k0 = ch * 32 + acg;
#pragma unroll
        for (int u = 0; u < 4; u++) {
            float4 v;
            if (MODE == 1) {
                const int k = k0 + u * 4;
                v.x = fmaxf((P[u].x + Q[u].x) * sAn[k + 0] + sCn[k + 0], 0.f);
                v.y = fmaxf((P[u].y + Q[u].y) * sAn[k + 1] + sCn[k + 1], 0.f);
                v.z = fmaxf((P[u].z + Q[u].z) * sAn[k + 2] + sCn[k + 2], 0.f);
                v.w = fmaxf((P[u].w + Q[u].w) * sAn[k + 3] + sCn[k + 3], 0.f);
            } else {
                v = P[u];
            }
            __nv_bfloat162 h01 = __float22bfloat162_rn(make_float2(v.x, v.y));
            __nv_bfloat162 h23 = __float22bfloat162_rn(make_float2(v.z, v.w));
            float2 hf01 = __bfloat1622float2(h01);
            float2 hf23 = __bfloat1622float2(h23);
            __nv_bfloat162 l01 = __float22bfloat162_rn(make_float2(v.x - hf01.x, v.y - hf01.y));
            __nv_bfloat162 l23 = __float22bfloat162_rn(make_float2(v.z - hf23.x, v.w - hf23.y));
            uint2 H, L;
            H.x = *reinterpret_cast<uint32_t*>(&h01);
            H.y = *reinterpret_cast<uint32_t*>(&h23);
            L.x = *reinterpret_cast<uint32_t*>(&l01);
            L.y = *reinterpret_cast<uint32_t*>(&l23);
            int so = arow * SAS + acg + u * 4;
            *reinterpret_cast<uint2*>(&sAh[so]) = H;
            *reinterpret_cast<uint2*>(&sAl[so]) = L;
        }
        *reinterpret_cast<uint4*>(&sBh[bdoff]) = BHr;
        *reinterpret_cast<uint4*>(&sBl[bdoff]) = BLr;
    };

    const int a_lrow = (lane & 7) + ((lane >> 3) & 1) * 8;
    const int a_lcol = (lane >> 4) * 8;
    const int b_lrow = (lane & 7) + (lane >> 4) * 8;
    const int b_lcol = ((lane >> 3) & 1) * 8;

    load_chunk(0);
    load_B(0);

    for (int ch = 0; ch < NCH; ch++) {
        store_chunk(ch);
        __syncthreads();

        if (ch + 1 < NCH) { load_chunk(ch + 1); load_B(ch + 1); }

#pragma unroll
        for (int ks = 0; ks < 2; ks++) {
            const int kb = ks * 16;
            uint32_t ah[2][4], al[2][4];
#pragma unroll
            for (int mt = 0; mt < 2; mt++) {
                int r = wm * 32 + mt * 16 + a_lrow;
                uint32_t off = (uint32_t)(r * SAS + kb + a_lcol) * 2;
                LDSM_X4(ah[mt][0], ah[mt][1], ah[mt][2], ah[mt][3], sAh_u + off);
                LDSM_X4(al[mt][0], al[mt][1], al[mt][2], al[mt][3], sAl_u + off);
            }
#pragma unroll
            for (int p = 0; p < NT / 2; p++) {
                int n0 = wn * (BN / 2) + p * 16;
                uint32_t boff = (uint32_t)((n0 + b_lrow) * SAS + kb + b_lcol) * 2;
                uint32_t bh[4], bl[4];
                LDSM_X4(bh[0], bh[1], bh[2], bh[3], sBh_u + boff);
                LDSM_X4(bl[0], bl[1], bl[2], bl[3], sBl_u + boff);
#pragma unroll
                for (int mt = 0; mt < 2; mt++) {
                    MMA_BF16(acc[mt][2 * p], ah[mt], (&bh[0]));
                    MMA_BF16(acc[mt][2 * p], ah[mt], (&bl[0]));
                    MMA_BF16(acc[mt][2 * p], al[mt], (&bh[0]));
                    MMA_BF16(acc[mt][2 * p + 1], ah[mt], (&bh[2]));
                    MMA_BF16(acc[mt][2 * p + 1], ah[mt], (&bl[2]));
                    MMA_BF16(acc[mt][2 * p + 1], al[mt], (&bh[2]));
                }
            }
        }
        __syncthreads();
    }

    // ---- epilogue ----
    float* ebuf = reinterpret_cast<float*>(SM + OFF_BUF);
    float* ssum = reinterpret_cast<float*>(SM + OFF_SSUM);
    float* ssq = reinterpret_cast<float*>(SM + OFF_SSQ);

    const int q = lane >> 2, s = lane & 3;

#pragma unroll
    for (int nt = 0; nt < NT; nt++) {
        const int col = col0 + wn * (BN / 2) + nt * 8 + s * 2;
        const float b0 = bias[col], b1 = bias[col + 1];
#pragma unroll
        for (int mt = 0; mt < 2; mt++) {
            acc[mt][nt][0] += b0; acc[mt][nt][1] += b1;
            acc[mt][nt][2] += b0; acc[mt][nt][3] += b1;
        }
    }

    if (STATS) {
        if (tid < 2 * BN) reinterpret_cast<float*>(SM + OFF_SSUM)[tid] = 0.f;
        __syncthreads();
#pragma unroll
        for (int nt = 0; nt < NT; nt++) {
            const int colw = wn * (BN / 2) + nt * 8 + s * 2;
            float s0 = 0.f, q0 = 0.f, s1 = 0.f, q1 = 0.f;
#pragma unroll
            for (int mt = 0; mt < 2; mt++) {
                const int r = wm * 32 + mt * 16 + q;
                if (e0 + r < Rows) {
                    s0 += acc[mt][nt][0]; q0 += acc[mt][nt][0] * acc[mt][nt][0];
                    s1 += acc[mt][nt][1]; q1 += acc[mt][nt][1] * acc[mt][nt][1];
                }
                if (e0 + r + 8 < Rows) {
                    s0 += acc[mt][nt][2]; q0 += acc[mt][nt][2] * acc[mt][nt][2];
                    s1 += acc[mt][nt][3]; q1 += acc[mt][nt][3] * acc[mt][nt][3];
                }
            }
#pragma unroll
            for (int m = 4; m <= 16; m <<= 1) {
                s0 += __shfl_xor_sync(0xffffffff, s0, m);
                q0 += __shfl_xor_sync(0xffffffff, q0, m);
                s1 += __shfl_xor_sync(0xffffffff, s1, m);
                q1 += __shfl_xor_sync(0xffffffff, q1, m);
            }
            if (q == 0) {
                atomicAdd(&ssum[colw], s0);
                atomicAdd(&ssq[colw], q0);
                atomicAdd(&ssum[colw + 1], s1);
                atomicAdd(&ssq[colw + 1], q1);
            }
        }
        __syncthreads();
        if (tid < BN) {
            atomicAdd(&stat_sum[col0 + tid], ssum[tid]);
            atomicAdd(&stat_sq[col0 + tid], ssq[tid]);
        }
    }

    // coalesced smem-staged store
#pragma unroll
    for (int pass = 0; pass < 2; pass++) {
        __syncthreads();
        if ((wm >> 1) == pass) {
            const int wml = wm & 1;
#pragma unroll
            for (int mt = 0; mt < 2; mt++) {
                const int rl = wml * 32 + mt * 16 + q;
#pragma unroll
                for (int nt = 0; nt < NT; nt++) {
                    const int colw = wn * (BN / 2) + nt * 8 + s * 2;
                    *reinterpret_cast<float2*>(&ebuf[rl * EST + colw]) =
                        make_float2(acc[mt][nt][0], acc[mt][nt][1]);
                    *reinterpret_cast<float2*>(&ebuf[(rl + 8) * EST + colw]) =
                        make_float2(acc[mt][nt][2], acc[mt][nt][3]);
                }
            }
        }
        __syncthreads();
#pragma unroll
        for (int ii = 0; ii < 4; ii++) {
            const int i = tid + ii * 256;
            const int row = i >> 4, c4 = i & 15;
            const int e = e0 + pass * 64 + row;
            if (e < Rows) {
                float4 v = *reinterpret_cast<float4*>(&ebuf[row * EST + c4 * 4]);
                *reinterpret_cast<float4*>(&out[(size_t)e * OC + col0 + c4 * 4]) = v;
            }
        }
    }
}

// ---------------- edge stats of t1 = U[dst]+V[src] (bias already in U) ------
template <int OC>
__global__ __launch_bounds__(256)
void estats_kernel(const float* __restrict__ UV,
                   const int* __restrict__ src, const int* __restrict__ dst,
                   float* __restrict__ sum, float* __restrict__ sq, int E) {
    constexpr int R = OC / 32;
    __shared__ float ss[OC], sv[OC];
    const int tid = threadIdx.x, lane = tid & 31, wid = tid >> 5;
    for (int i = tid; i < OC; i += 256) { ss[i] = 0.f; sv[i] = 0.f; }
    __syncthreads();
    float s[R], q[R];
#pragma unroll
    for (int j = 0; j < R; j++) { s[j] = 0.f; q[j] = 0.f; }
    for (int e = blockIdx.x * 8 + wid; e < E; e += gridDim.x * 8) {
        const int nd = dst[e], ns = src[e];
        const float* Ur = UV + (size_t)nd * (2 * OC);
        const float* Vr = UV + (size_t)ns * (2 * OC) + OC;
#pragma unroll
        for (int j = 0; j < R; j++) {
            float v = Ur[j * 32 + lane] + Vr[j * 32 + lane];
            s[j] += v; q[j] += v * v;
        }
    }
#pragma unroll
    for (int j = 0; j < R; j++) {
        atomicAdd(&ss[j * 32 + lane], s[j]);
        atomicAdd(&sv[j * 32 + lane], q[j]);
    }
    __syncthreads();
    for (int i = tid; i < OC; i += 256) {
        atomicAdd(&sum[i], ss[i]);
        atomicAdd(&sq[i], sv[i]);
    }
}

// ---------------- BN finalize ----------------
__global__ void finalize_kernel(const float* __restrict__ sum, const float* __restrict__ sq,
                                const float* __restrict__ gamma, const float* __restrict__ beta,
                                float* __restrict__ a, float* __restrict__ c,
                                int OC, float invE) {
    int i = blockIdx.x * blockDim.x + threadIdx.x;
    if (i < OC) {
        float m = sum[i] * invE;
        float var = sq[i] * invE - m * m;
        float rs = rsqrtf(var + 1e-5f);
        float ai = gamma[i] * rs;
        a[i] = ai;
        c[i] = beta[i] - m * ai;
    }
}

// ---------------- normalize + relu + mean-aggregate (CONTIGUOUS rows) ------
// t2 is in permuted (dst-sorted) order: node i's edges are rows
// [rowptr[i], rowptr[i+1]) -- fully streaming reads, no indirection.
template <int OC>
__global__ __launch_bounds__(256)
void aggregate_kernel(const float* __restrict__ t, const int* __restrict__ rowptr,
                      const float* __restrict__ a,
                      const float* __restrict__ c, float* __restrict__ hout, int n) {
    int warp = (blockIdx.x * blockDim.x + threadIdx.x) >> 5;
    int lane = threadIdx.x & 31;
    if (warp >= n) return;
    constexpr int R = OC / 32;
    float av[R], cv[R], acc[R];
#pragma unroll
    for (int j = 0; j < R; j++) {
        int ch = j * 32 + lane;
        av[j] = a[ch]; cv[j] = c[ch]; acc[j] = 0.f;
    }
    int beg = rowptr[warp], end = rowptr[warp + 1];
    for (int p = beg; p < end; p++) {
        const float* rowp = t + (size_t)p * OC;
#pragma unroll
        for (int j = 0; j < R; j++) {
            float v = rowp[j * 32 + lane];
            acc[j] += fmaxf(v * av[j] + cv[j], 0.f);
        }
    }
    float inv = 1.f / fmaxf((float)(end - beg), 1.f);
#pragma unroll
    for (int j = 0; j < R; j++) hout[(size_t)warp * OC + j * 32 + lane] = acc[j] * inv;
}

// ---------------- global mean pool + head ----------------
__global__ void pool_kernel(const float* __restrict__ h, const int* __restrict__ gstart,
                            float* __restrict__ pool) {
    int g = blockIdx.x;
    int ch = threadIdx.x;
    int beg = gstart[g], end = gstart[g + 1];
    float s = 0.f;
    for (int nidx = beg; nidx < end; nidx++) s += h[(size_t)nidx * 256 + ch];
    pool[g * 256 + ch] = s / fmaxf((float)(end - beg), 1.f);
}
__global__ void head1_kernel(const float* __restrict__ pool, const float* __restrict__ W,
                             const float* __restrict__ b, float* __restrict__ z) {
    int g = blockIdx.x, j = threadIdx.x;
    __shared__ float sp[256];
    sp[j] = pool[g * 256 + j];
    sp[j + 128] = pool[g * 256 + j + 128];
    __syncthreads();
    float s = b[j];
#pragma unroll 8
    for (int k = 0; k < 256; k++) s += sp[k] * W[k * 128 + j];
    z[g * 128 + j] = fmaxf(s, 0.f);
}
__global__ void head2_kernel(const float* __restrict__ z, const float* __restrict__ W,
                             const float* __restrict__ b, float* __restrict__ out) {
    int t = threadIdx.x;
    int g = t >> 1, j = t & 1;
    float s = b[j];
#pragma unroll 8
    for (int k = 0; k < 128; k++) s += z[g * 128 + k] * W[k * 2 + j];
    out[g * 2 + j] = s;
}

// ---------------- launch ----------------
extern "C" void kernel_launch(void* const* d_in, const int* in_sizes, int n_in,
                              void* d_out, int out_size) {
    const float* x     = (const float*)d_in[0];
    const int*   ei    = (const int*)d_in[1];
    const int*   batch = (const int*)d_in[2];

    const int E = in_sizes[1] / 2;
    const int n = in_sizes[2];
    const int* srcp = ei;
    const int* dstp = ei + E;

    const float* W[3][2];  const float* B[3][2];
    const float* Gm[3][2]; const float* Bt[3][2];
    for (int l = 0; l < 3; l++) {
        int base = 3 + l * 8;
        W[l][0]  = (const float*)d_in[base + 0];
        B[l][0]  = (const float*)d_in[base + 1];
        Gm[l][0] = (const float*)d_in[base + 2];
        Bt[l][0] = (const float*)d_in[base + 3];
        W[l][1]  = (const float*)d_in[base + 4];
        B[l][1]  = (const float*)d_in[base + 5];
        Gm[l][1] = (const float*)d_in[base + 6];
        Bt[l][1] = (const float*)d_in[base + 7];
    }
    const float* hW1 = (const float*)d_in[27];
    const float* hb1 = (const float*)d_in[28];
    const float* hW2 = (const float*)d_in[29];
    const float* hb2 = (const float*)d_in[30];

    float *UV, *t2, *hA, *hB, *stats, *norm, *pool, *zbuf, *bias2;
    int *deg, *rowptr, *cursor, *eidx, *psrc, *pdst, *cnt, *gstart;
    __nv_bfloat16 *wth, *wtl;
    cudaGetSymbolAddress((void**)&UV, g_t1);
    cudaGetSymbolAddress((void**)&t2, g_t2);
    cudaGetSymbolAddress((void**)&hA, g_hA);
    cudaGetSymbolAddress((void**)&hB, g_hB);
    cudaGetSymbolAddress((void**)&stats, g_stats);
    cudaGetSymbolAddress((void**)&norm, g_norm);
    cudaGetSymbolAddress((void**)&bias2, g_bias2);
    cudaGetSymbolAddress((void**)&deg, g_deg);
    cudaGetSymbolAddress((void**)&rowptr, g_rowptr);
    cudaGetSymbolAddress((void**)&cursor, g_cursor);
    cudaGetSymbolAddress((void**)&eidx, g_eidx);
    cudaGetSymbolAddress((void**)&psrc, g_psrc);
    cudaGetSymbolAddress((void**)&pdst, g_pdst);
    cudaGetSymbolAddress((void**)&cnt, g_cnt);
    cudaGetSymbolAddress((void**)&gstart, g_gstart);
    cudaGetSymbolAddress((void**)&pool, g_pool);
    cudaGetSymbolAddress((void**)&zbuf, g_zbuf);
    cudaGetSymbolAddress((void**)&wth, g_wth);
    cudaGetSymbolAddress((void**)&wtl, g_wtl);

    float* sum1 = stats + 0;   float* sq1 = stats + 256;
    float* sum2 = stats + 512; float* sq2 = stats + 768;
    float* a1 = norm + 0;   float* c1 = norm + 256;
    float* a2 = norm + 512; float* c2 = norm + 768;

    const float invE = 1.f / (float)E;
    const int EB = (E + 127) / 128;
    const int NB = (n + 127) / 128;
    const int EG = (E + 255) / 256;
    const int NG = (n + 255) / 256;
    const int AGG = (n * 32 + 255) / 256;
    const int SGRID = 1184;

    // ---- CSR build + permutation ----
    cudaMemsetAsync(deg, 0, n * sizeof(int));
    cudaMemsetAsync(cnt, 0, GG * sizeof(int));
    hist_deg_kernel<<<EG, 256>>>(dstp, deg, E);
    hist_cnt_kernel<<<NG, 256>>>(batch, cnt, n);
    scan_kernel<<<1, 1024>>>(deg, rowptr, cursor, cnt, gstart, n);
    fill_csr_kernel<<<EG, 256>>>(dstp, cursor, eidx, E);
    build_perm_kernel<<<EG, 256>>>(eidx, srcp, dstp, psrc, pdst, E);

    // ---- weight conversion ----
    convert_wsplit_kernel<<<(128 * 32 + 255) / 256, 256>>>(W[0][0], wth + 0, wtl + 0, 7, 64, 32);
    convert_w_kernel<<<(64 * 64 + 255) / 256, 256>>>(W[0][1], wth + 4096, wtl + 4096, 64, 64, 64);
    convert_wsplit_kernel<<<(256 * 64 + 255) / 256, 256>>>(W[1][0], wth + 8192, wtl + 8192, 64, 128, 64);
    convert_w_kernel<<<(128 * 128 + 255) / 256, 256>>>(W[1][1], wth + 24576, wtl + 24576, 128, 128, 128);
    convert_wsplit_kernel<<<(512 * 128 + 255) / 256, 256>>>(W[2][0], wth + 40960, wtl + 40960, 128, 256, 128);
    convert_w_kernel<<<(256 * 256 + 255) / 256, 256>>>(W[2][1], wth + 106496, wtl + 106496, 256, 256, 256);

    // ==== layer 1: 7 -> 64 ====
    cudaMemsetAsync(bias2, 0, 512 * sizeof(float));
    cudaMemcpyAsync(bias2, B[0][0], 64 * sizeof(float), cudaMemcpyDeviceToDevice);
    zero_stats_kernel<<<1, 256>>>(stats);
    mgemm_kernel<7, 128, 0, false><<<dim3(NB, 2), 256>>>(
        x, nullptr, nullptr, nullptr, nullptr, wth + 0, wtl + 0, bias2, UV, nullptr, nullptr, n);
    estats_kernel<64><<<SGRID, 256>>>(UV, psrc, pdst, sum1, sq1, E);
    finalize_kernel<<<1, 64>>>(sum1, sq1, Gm[0][0], Bt[0][0], a1, c1, 64, invE);
    mgemm_kernel<64, 64, 1, true><<<dim3(EB, 1), 256>>>(
        UV, psrc, pdst, a1, c1, wth + 4096, wtl + 4096, B[0][1], t2, sum2, sq2, E);
    finalize_kernel<<<1, 64>>>(sum2, sq2, Gm[0][1], Bt[0][1], a2, c2, 64, invE);
    aggregate_kernel<64><<<AGG, 256>>>(t2, rowptr, a2, c2, hA, n);

    // ==== layer 2: 64 -> 128 ====
    cudaMemsetAsync(bias2, 0, 512 * sizeof(float));
    cudaMemcpyAsync(bias2, B[1][0], 128 * sizeof(float), cudaMemcpyDeviceToDevice);
    zero_stats_kernel<<<1, 256>>>(stats);
    mgemm_kernel<64, 256, 0, false><<<dim3(NB, 4), 256>>>(
        hA, nullptr, nullptr, nullptr, nullptr, wth + 8192, wtl + 8192, bias2, UV, nullptr, nullptr, n);
    estats_kernel<128><<<SGRID, 256>>>(UV, psrc, pdst, sum1, sq1, E);
    finalize_kernel<<<1, 128>>>(sum1, sq1, Gm[1][0], Bt[1][0], a1, c1, 128, invE);
    mgemm_kernel<128, 128, 1, true><<<dim3(EB, 2), 256>>>(
        UV, psrc, pdst, a1, c1, wth + 24576, wtl + 24576, B[1][1], t2, sum2, sq2, E);
    finalize_kernel<<<1, 128>>>(sum2, sq2, Gm[1][1], Bt[1][1], a2, c2, 128, invE);
    aggregate_kernel<128><<<AGG, 256>>>(t2, rowptr, a2, c2, hB, n);

    // ==== layer 3: 128 -> 256 ====
    cudaMemsetAsync(bias2, 0, 512 * sizeof(float));
    cudaMemcpyAsync(bias2, B[2][0], 256 * sizeof(float), cudaMemcpyDeviceToDevice);
    zero_stats_kernel<<<1, 256>>>(stats);
    mgemm_kernel<128, 512, 0, false><<<dim3(NB, 8), 256>>>(
        hB, nullptr, nullptr, nullptr, nullptr, wth + 40960, wtl + 40960, bias2, UV, nullptr, nullptr, n);
    estats_kernel<256><<<SGRID, 256>>>(UV, psrc, pdst, sum1, sq1, E);
    finalize_kernel<<<1, 256>>>(sum1, sq1, Gm[2][0], Bt[2][0], a1, c1, 256, invE);
    mgemm_kernel<256, 256, 1, true><<<dim3(EB, 4), 256>>>(
        UV, psrc, pdst, a1, c1, wth + 106496, wtl + 106496, B[2][1], t2, sum2, sq2, E);
    finalize_kernel<<<1, 256>>>(sum2, sq2, Gm[2][1], Bt[2][1], a2, c2, 256, invE);
    aggregate_kernel<256><<<AGG, 256>>>(t2, rowptr, a2, c2, hA, n);

    // ---- pool + head ----
    pool_kernel<<<GG, 256>>>(hA, gstart, pool);
    head1_kernel<<<GG, 128>>>(pool, hW1, hb1, zbuf);
    head2_kernel<<<1, 128>>>(zbuf, hW2, hb2, (float*)d_out);
}

// round 11
// speedup vs baseline: 1.7985x; 1.0785x over previous
#include <cuda_runtime.h>
#include <cuda_bf16.h>
#include <cstdint>

// ---------------- problem constants ----------------
#define NN 50000
#define EE 500000
#define GG 64

// ---------------- scratch (device globals; no allocation allowed) ----------
__device__ float g_t1[(size_t)EE * 256];     // UV node buffer (<= 50K x 512)
__device__ float g_t2[(size_t)EE * 256];     // edge intermediate t2 (PERMUTED order)
__device__ float g_hA[(size_t)NN * 256];
__device__ float g_hB[(size_t)NN * 256];
__device__ float g_stats[1024];
__device__ float g_norm[1024];
__device__ float g_bias2[512];
__device__ int   g_deg[NN];
__device__ int   g_rowptr[NN + 1];
__device__ int   g_cursor[NN];
__device__ int   g_psrc[EE];
__device__ int   g_pdst[EE];
__device__ int   g_cnt[GG];
__device__ int   g_gstart[GG + 1];
__device__ float g_pool[GG * 256];
__device__ float g_zbuf[GG * 128];
__device__ __nv_bfloat16 g_wth[172032];
__device__ __nv_bfloat16 g_wtl[172032];

// ---------------- mma.sync / ldmatrix helpers ------------------------------
#define MMA_BF16(d, a, b)                                                        \
    asm volatile("mma.sync.aligned.m16n8k16.row.col.f32.bf16.bf16.f32 "          \
                 "{%0,%1,%2,%3}, {%4,%5,%6,%7}, {%8,%9}, {%0,%1,%2,%3};"         \
                 : "+f"((d)[0]), "+f"((d)[1]), "+f"((d)[2]), "+f"((d)[3])        \
                 : "r"((a)[0]), "r"((a)[1]), "r"((a)[2]), "r"((a)[3]),           \
                   "r"((b)[0]), "r"((b)[1]))

#define LDSM_X4(r0, r1, r2, r3, addr)                                            \
    asm volatile("ldmatrix.sync.aligned.m8n8.x4.shared.b16 {%0,%1,%2,%3}, [%4];" \
                 : "=r"(r0), "=r"(r1), "=r"(r2), "=r"(r3) : "r"(addr))

__device__ __forceinline__ uint32_t smem_u32(const void* p) {
    uint32_t a;
    asm("{ .reg .u64 t; cvta.to.shared.u64 t, %1; cvt.u32.u64 %0, t; }" : "=r"(a) : "l"(p));
    return a;
}

// ---------------- small utility kernels ----------------
__global__ void hist_deg_kernel(const int* __restrict__ dst, int* __restrict__ deg, int E) {
    int e = blockIdx.x * blockDim.x + threadIdx.x;
    if (e < E) atomicAdd(&deg[dst[e]], 1);
}
__global__ void hist_cnt_kernel(const int* __restrict__ batch, int* __restrict__ cnt, int n) {
    int i = blockIdx.x * blockDim.x + threadIdx.x;
    if (i < n) atomicAdd(&cnt[batch[i]], 1);
}
__global__ void scan_kernel(const int* __restrict__ deg, int* __restrict__ rowptr,
                            int* __restrict__ cursor, const int* __restrict__ cnt,
                            int* __restrict__ gstart, int n) {
    __shared__ int sh[1024];
    __shared__ int carry;
    int t = threadIdx.x;
    if (t == 0) carry = 0;
    __syncthreads();
    for (int base = 0; base < n; base += 1024) {
        int idx = base + t;
        int v = (idx < n) ? deg[idx] : 0;
        sh[t] = v;
        __syncthreads();
        for (int off = 1; off < 1024; off <<= 1) {
            int add = (t >= off) ? sh[t - off] : 0;
            __syncthreads();
            sh[t] += add;
            __syncthreads();
        }
        int ex = sh[t] - v;
        int cbase = carry;
        if (idx < n) { rowptr[idx] = cbase + ex; cursor[idx] = cbase + ex; }
        __syncthreads();
        if (t == 1023) carry = cbase + sh[1023];
        __syncthreads();
    }
    if (t == 0) {
        rowptr[n] = carry;
        int s = 0;
        for (int g = 0; g < GG; g++) { gstart[g] = s; s += cnt[g]; }
        gstart[GG] = s;
    }
}
// scatter edges into permuted order directly
__global__ void fill_csr_kernel(const int* __restrict__ src, const int* __restrict__ dst,
                                int* __restrict__ cursor,
                                int* __restrict__ psrc, int* __restrict__ pdst, int E) {
    int e = blockIdx.x * blockDim.x + threadIdx.x;
    if (e < E) {
        int d = dst[e];
        int p = atomicAdd(&cursor[d], 1);
        psrc[p] = src[e];
        pdst[p] = d;
    }
}

// W2[K,OC] fp32 -> Wt[OC][KPAD] bf16 hi/lo (transposed)
__global__ void convert_w_kernel(const float* __restrict__ W,
                                 __nv_bfloat16* __restrict__ Wth,
                                 __nv_bfloat16* __restrict__ Wtl,
                                 int K, int OC, int KPAD) {
    int idx = blockIdx.x * blockDim.x + threadIdx.x;
    if (idx >= OC * KPAD) return;
    int n = idx / KPAD, k = idx % KPAD;
    float w = (k < K) ? W[(size_t)k * OC + n] : 0.f;
    __nv_bfloat16 h = __float2bfloat16_rn(w);
    Wth[idx] = h;
    Wtl[idx] = __float2bfloat16_rn(w - __bfloat162float(h));
}

// W1[2C,OC] -> combined [2OC][KPAD(C)]: rows 0..OC-1 = (Wa-Wb)^T, OC..2OC-1 = Wb^T
__global__ void convert_wsplit_kernel(const float* __restrict__ W1,
                                      __nv_bfloat16* __restrict__ Wth,
                                      __nv_bfloat16* __restrict__ Wtl,
                                      int C, int OC, int KPAD) {
    int idx = blockIdx.x * blockDim.x + threadIdx.x;
    if (idx >= 2 * OC * KPAD) return;
    int n = idx / KPAD, k = idx % KPAD;
    float w = 0.f;
    if (k < C) {
        if (n < OC) w = W1[(size_t)k * OC + n] - W1[(size_t)(k + C) * OC + n];
        else        w = W1[(size_t)(k + C) * OC + (n - OC)];
    }
    __nv_bfloat16 h = __float2bfloat16_rn(w);
    Wth[idx] = h;
    Wtl[idx] = __float2bfloat16_rn(w - __bfloat162float(h));
}

// ---------------- tensor-core GEMM ------------------------------------------
// BN in {64, 128}.  THREADS = BN*4.  Warps = BN/8 laid out 4(M) x (BN/32)(N),
// warp tile 32x32, NT=4 n8-tiles, acc = 32 regs.  3 MMAs per k16 (hi/lo split).
// MODE 0: node GEMM, A row i = fA[i*K..].        Rows = N.
// MODE 1: edge GEMM over permuted edges: A row p = relu((U[pdst]+V[psrc])*an+cn).
template <int K, int OC, int BN, int MODE, bool STATS>
__global__ __launch_bounds__(BN * 4, 128 / BN)
void mgemm_kernel(const float* __restrict__ fA,
                  const int* __restrict__ src, const int* __restrict__ dst,
                  const float* __restrict__ an, const float* __restrict__ cn,
                  const __nv_bfloat16* __restrict__ Wth,
                  const __nv_bfloat16* __restrict__ Wtl,
                  const float* __restrict__ bias,
                  float* __restrict__ out,
                  float* __restrict__ stat_sum, float* __restrict__ stat_sq,
                  int Rows) {
    constexpr int THREADS = BN * 4;
    constexpr int KPAD = (K + 31) / 32 * 32;
    constexpr int NCH = KPAD / 32;
    constexpr int SAS = 40;
    constexpr int ASTR = (MODE == 1) ? 2 * K : K;
    constexpr int TPR = THREADS / 128;       // threads per A row (2 or 4)
    constexpr int UNITS = 8 / TPR;           // float4 units per thread (4 or 2)
    constexpr int EST = BN + 8;

    constexpr int OFF_AH = 0;
    constexpr int OFF_AL = 10240;
    constexpr int OFF_BH = 20480;
    constexpr int OFF_BL = 20480 + BN * 80;
    constexpr int OFF_DST = 20480 + BN * 160;
    constexpr int OFF_SRC = OFF_DST + 512;
    constexpr int OFF_AN = OFF_SRC + 512;
    constexpr int OFF_CN = OFF_AN + KPAD * 4;
    constexpr int PROD_SZ = OFF_CN + KPAD * 4;
    constexpr int OFF_BUF = 0;
    constexpr int OFF_SSUM = 64 * EST * 4;
    constexpr int OFF_SSQ = OFF_SSUM + BN * 4;
    constexpr int EPI_SZ = OFF_SSQ + BN * 4;
    constexpr int SMEM_SZ = (PROD_SZ > EPI_SZ) ? PROD_SZ : EPI_SZ;

    __shared__ __align__(16) char SM[SMEM_SZ];
    __nv_bfloat16* sAh = reinterpret_cast<__nv_bfloat16*>(SM + OFF_AH);
    __nv_bfloat16* sAl = reinterpret_cast<__nv_bfloat16*>(SM + OFF_AL);
    int* sdst = reinterpret_cast<int*>(SM + OFF_DST);
    int* ssrc = reinterpret_cast<int*>(SM + OFF_SRC);
    float* sAn = reinterpret_cast<float*>(SM + OFF_AN);
    float* sCn = reinterpret_cast<float*>(SM + OFF_CN);

    const int tid = threadIdx.x;
    const int lane = tid & 31;
    const int wid = tid >> 5;
    const int wm = wid & 3;
    const int wn = wid >> 2;
    const int e0 = blockIdx.x * 128;
    const int col0 = blockIdx.y * BN;

    const uint32_t sAh_u = smem_u32(SM + OFF_AH);
    const uint32_t sAl_u = smem_u32(SM + OFF_AL);
    const uint32_t sBh_u = smem_u32(SM + OFF_BH);
    const uint32_t sBl_u = smem_u32(SM + OFF_BL);
    __nv_bfloat16* sBh = reinterpret_cast<__nv_bfloat16*>(SM + OFF_BH);
    __nv_bfloat16* sBl = reinterpret_cast<__nv_bfloat16*>(SM + OFF_BL);

    if (MODE == 1) {
        if (tid < 128) {
            int e = e0 + tid;
            int ee = (e < Rows) ? e : (Rows - 1);
            sdst[tid] = dst[ee];
            ssrc[tid] = src[ee];
        }
        for (int i = tid; i < K; i += THREADS) { sAn[i] = an[i]; sCn[i] = cn[i]; }
    }
    __syncthreads();

    float acc[2][4][4];
#pragma unroll
    for (int mt = 0; mt < 2; mt++)
#pragma unroll
        for (int nt = 0; nt < 4; nt++)
#pragma unroll
            for (int j = 0; j < 4; j++) acc[mt][nt][j] = 0.f;

    const int arow = tid / TPR;
    const int acg = (tid % TPR) * (32 / TPR);
    int nd = 0, ns = 0;
    if (MODE == 1) { nd = sdst[arow]; ns = ssrc[arow]; }

    const int bn_ = tid >> 2;                // 0..BN-1
    const int bu_ = tid & 3;
    const int bdoff = bn_ * SAS + bu_ * 8;

    float4 P[UNITS], Q[UNITS];
    uint4 BHr, BLr;

    auto load_chunk = [&](int ch) {
        const int k0 = ch * 32 + acg;
        if (MODE == 1) {
            const float* Ur = fA + (size_t)nd * ASTR;
            const float* Vr = fA + (size_t)ns * ASTR + K;
#pragma unroll
            for (int u = 0; u < UNITS; u++) {
                P[u] = *reinterpret_cast<const float4*>(Ur + k0 + u * 4);
                Q[u] = *reinterpret_cast<const float4*>(Vr + k0 + u * 4);
            }
        } else {
            const int i = e0 + arow;
            if (K % 4 == 0) {
                if (i < Rows) {
#pragma unroll
                    for (int u = 0; u < UNITS; u++)
                        P[u] = *reinterpret_cast<const float4*>(&fA[(size_t)i * K + k0 + u * 4]);
                } else {
#pragma unroll
                    for (int u = 0; u < UNITS; u++) P[u] = make_float4(0.f, 0.f, 0.f, 0.f);
                }
            } else {  // K=7 scalar path (NCH==1)
#pragma unroll
                for (int u = 0; u < UNITS; u++) {
                    float t[4];
#pragma unroll
                    for (int j = 0; j < 4; j++) {
                        int kk = k0 + u * 4 + j;
                        t[j] = (i < Rows && kk < K) ? fA[(size_t)i * K + kk] : 0.f;
                    }
                    P[u] = make_float4(t[0], t[1], t[2], t[3]);
                }
            }
        }
    };
    auto load_B = [&](int ch) {
        size_t soff = (size_t)(col0 + bn_) * KPAD + ch * 32 + bu_ * 8;
        BHr = *reinterpret_cast<const uint4*>(Wth + soff);
        BLr = *reinterpret_cast<const uint4*>(Wtl + soff);
    };
    auto store_chunk = [&](int ch) {
        const int k0 = ch * 32 + acg;
#pragma unroll
        for (int u = 0; u < UNITS; u++) {
            float4 v;
            if (MODE == 1) {
                const int k = k0 + u * 4;
                v.x = fmaxf((P[u].x + Q[u].x) * sAn[k + 0] + sCn[k + 0], 0.f);
                v.y = fmaxf((P[u].y + Q[u].y) * sAn[k + 1] + sCn[k + 1], 0.f);
                v.z = fmaxf((P[u].z + Q[u].z) * sAn[k + 2] + sCn[k + 2], 0.f);
                v.w = fmaxf((P[u].w + Q[u].w) * sAn[k + 3] + sCn[k + 3], 0.f);
            } else {
                v = P[u];
            }
            __nv_bfloat162 h01 = __float22bfloat162_rn(make_float2(v.x, v.y));
            __nv_bfloat162 h23 = __float22bfloat162_rn(make_float2(v.z, v.w));
            float2 hf01 = __bfloat1622float2(h01);
            float2 hf23 = __bfloat1622float2(h23);
            __nv_bfloat162 l01 = __float22bfloat162_rn(make_float2(v.x - hf01.x, v.y - hf01.y));
            __nv_bfloat162 l23 = __float22bfloat162_rn(make_float2(v.z - hf23.x, v.w - hf23.y));
            uint2 H, L;
            H.x = *reinterpret_cast<uint32_t*>(&h01);
            H.y = *reinterpret_cast<uint32_t*>(&h23);
            L.x = *reinterpret_cast<uint32_t*>(&l01);
            L.y = *reinterpret_cast<uint32_t*>(&l23);
            int so = arow * SAS + acg + u * 4;
            *reinterpret_cast<uint2*>(&sAh[so]) = H;
            *reinterpret_cast<uint2*>(&sAl[so]) = L;
        }
        *reinterpret_cast<uint4*>(&sBh[bdoff]) = BHr;
        *reinterpret_cast<uint4*>(&sBl[bdoff]) = BLr;
    };

    const int a_lrow = (lane & 7) + ((lane >> 3) & 1) * 8;
    const int a_lcol = (lane >> 4) * 8;
    const int b_lrow = (lane & 7) + (lane >> 4) * 8;
    const int b_lcol = ((lane >> 3) & 1) * 8;

    load_chunk(0);
    load_B(0);

    for (int ch = 0; ch < NCH; ch++) {
        store_chunk(ch);
        __syncthreads();

        if (ch + 1 < NCH) { load_chunk(ch + 1); load_B(ch + 1); }

#pragma unroll
        for (int ks = 0; ks < 2; ks++) {
            const int kb = ks * 16;
            uint32_t ah[2][4], al[2][4];
#pragma unroll
            for (int mt = 0; mt < 2; mt++) {
                int r = wm * 32 + mt * 16 + a_lrow;
                uint32_t off = (uint32_t)(r * SAS + kb + a_lcol) * 2;
                LDSM_X4(ah[mt][0], ah[mt][1], ah[mt][2], ah[mt][3], sAh_u + off);
                LDSM_X4(al[mt][0], al[mt][1], al[mt][2], al[mt][3], sAl_u + off);
            }
#pragma unroll
            for (int p = 0; p < 2; p++) {
                int n0 = wn * 32 + p * 16;
                uint32_t boff = (uint32_t)((n0 + b_lrow) * SAS + kb + b_lcol) * 2;
                uint32_t bh[4], bl[4];
                LDSM_X4(bh[0], bh[1], bh[2], bh[3], sBh_u + boff);
                LDSM_X4(bl[0], bl[1], bl[2], bl[3], sBl_u + boff);
#pragma unroll
                for (int mt = 0; mt < 2; mt++) {
                    MMA_BF16(acc[mt][2 * p], ah[mt], (&bh[0]));
                    MMA_BF16(acc[mt][2 * p], ah[mt], (&bl[0]));
                    MMA_BF16(acc[mt][2 * p], al[mt], (&bh[0]));
                    MMA_BF16(acc[mt][2 * p + 1], ah[mt], (&bh[2]));
                    MMA_BF16(acc[mt][2 * p + 1], ah[mt], (&bl[2]));
                    MMA_BF16(acc[mt][2 * p + 1], al[mt], (&bh[2]));
                }
            }
        }
        __syncthreads();
    }

    // ---- epilogue ----
    float* ebuf = reinterpret_cast<float*>(SM + OFF_BUF);
    float* ssum = reinterpret_cast<float*>(SM + OFF_SSUM);
    float* ssq = reinterpret_cast<float*>(SM + OFF_SSQ);

    const int q = lane >> 2, s = lane & 3;

#pragma unroll
    for (int nt = 0; nt < 4; nt++) {
        const int col = col0 + wn * 32 + nt * 8 + s * 2;
        const float b0 = bias[col], b1 = bias[col + 1];
#pragma unroll
        for (int mt = 0; mt < 2; mt++) {
            acc[mt][nt][0] += b0; acc[mt][nt][1] += b1;
            acc[mt][nt][2] += b0; acc[mt][nt][3] += b1;
        }
    }

    if (STATS) {
        if (tid < 2 * BN) reinterpret_cast<float*>(SM + OFF_SSUM)[tid] = 0.f;
        __syncthreads();
#pragma unroll
        for (int nt = 0; nt < 4; nt++) {
            const int colw = wn * 32 + nt * 8 + s * 2;
            float s0 = 0.f, q0 = 0.f, s1 = 0.f, q1 = 0.f;
#pragma unroll
            for (int mt = 0; mt < 2; mt++) {
                const int r = wm * 32 + mt * 16 + q;
                if (e0 + r < Rows) {
                    s0 += acc[mt][nt][0]; q0 += acc[mt][nt][0] * acc[mt][nt][0];
                    s1 += acc[mt][nt][1]; q1 += acc[mt][nt][1] * acc[mt][nt][1];
                }
                if (e0 + r + 8 < Rows) {
                    s0 += acc[mt][nt][2]; q0 += acc[mt][nt][2] * acc[mt][nt][2];
                    s1 += acc[mt][nt][3]; q1 += acc[mt][nt][3] * acc[mt][nt][3];
                }
            }
#pragma unroll
            for (int m = 4; m <= 16; m <<= 1) {
                s0 += __shfl_xor_sync(0xffffffff, s0, m);
                q0 += __shfl_xor_sync(0xffffffff, q0, m);
                s1 += __shfl_xor_sync(0xffffffff, s1, m);
                q1 += __shfl_xor_sync(0xffffffff, q1, m);
            }
            if (q == 0) {
                atomicAdd(&ssum[colw], s0);
                atomicAdd(&ssq[colw], q0);
                atomicAdd(&ssum[colw + 1], s1);
                atomicAdd(&ssq[colw + 1], q1);
            }
        }
        __syncthreads();
        if (tid < BN) {
            atomicAdd(&stat_sum[col0 + tid], ssum[tid]);
            atomicAdd(&stat_sq[col0 + tid], ssq[tid]);
        }
    }

    // coalesced smem-staged store (two 64-row passes)
#pragma unroll
    for (int pass = 0; pass < 2; pass++) {
        __syncthreads();
        if ((wm >> 1) == pass) {
            const int wml = wm & 1;
#pragma unroll
            for (int mt = 0; mt < 2; mt++) {
                const int rl = wml * 32 + mt * 16 + q;
#pragma unroll
                for (int nt = 0; nt < 4; nt++) {
                    const int colw = wn * 32 + nt * 8 + s * 2;
                    *reinterpret_cast<float2*>(&ebuf[rl * EST + colw]) =
                        make_float2(acc[mt][nt][0], acc[mt][nt][1]);
                    *reinterpret_cast<float2*>(&ebuf[(rl + 8) * EST + colw]) =
                        make_float2(acc[mt][nt][2], acc[mt][nt][3]);
                }
            }
        }
        __syncthreads();
#pragma unroll
        for (int ii = 0; ii < 4; ii++) {
            const int i = tid + ii * THREADS;
            const int row = i / (BN / 4), c4 = i % (BN / 4);
            const int e = e0 + pass * 64 + row;
            if (e < Rows) {
                float4 v = *reinterpret_cast<float4*>(&ebuf[row * EST + c4 * 4]);
                *reinterpret_cast<float4*>(&out[(size_t)e * OC + col0 + c4 * 4]) = v;
            }
        }
    }
}

// ---------------- node-centric edge stats: Σ(U[d]+V[s]), Σ(U[d]+V[s])² ------
// Per node i: contrib = deg·U + ΣV  /  deg·U² + 2U·ΣV + ΣV²  (exact regroup)
template <int OC>
__global__ __launch_bounds__(256)
void estats_kernel(const float* __restrict__ UV, const int* __restrict__ psrc,
                   const int* __restrict__ rowptr,
                   float* __restrict__ sum, float* __restrict__ sq, int n) {
    constexpr int R = OC / 32;
    __shared__ float ss[OC], sv[OC];
    const int tid = threadIdx.x, lane = tid & 31, wid = tid >> 5;
    for (int i = tid; i < OC; i += 256) { ss[i] = 0.f; sv[i] = 0.f; }
    __syncthreads();
    float s[R], q[R];
#pragma unroll
    for (int j = 0; j < R; j++) { s[j] = 0.f; q[j] = 0.f; }
    const int nwarps = gridDim.x * 8;
    for (int i = blockIdx.x * 8 + wid; i < n; i += nwarps) {
        const int beg = rowptr[i], end = rowptr[i + 1];
        const float dg = (float)(end - beg);
        float U[R], sV[R], sV2[R];
        const float* Ur = UV + (size_t)i * (2 * OC);
#pragma unroll
        for (int j = 0; j < R; j++) { U[j] = Ur[j * 32 + lane]; sV[j] = 0.f; sV2[j] = 0.f; }
        for (int p = beg; p < end; p++) {
            const float* Vr = UV + (size_t)psrc[p] * (2 * OC) + OC;
#pragma unroll
            for (int j = 0; j < R; j++) {
                float v = Vr[j * 32 + lane];
                sV[j] += v; sV2[j] += v * v;
            }
        }
#pragma unroll
        for (int j = 0; j < R; j++) {
            s[j] += dg * U[j] + sV[j];
            q[j] += dg * U[j] * U[j] + 2.f * U[j] * sV[j] + sV2[j];
        }
    }
#pragma unroll
    for (int j = 0; j < R; j++) {
        atomicAdd(&ss[j * 32 + lane], s[j]);
        atomicAdd(&sv[j * 32 + lane], q[j]);
    }
    __syncthreads();
    for (int i = tid; i < OC; i += 256) {
        atomicAdd(&sum[i], ss[i]);
        atomicAdd(&sq[i], sv[i]);
    }
}

// ---------------- BN finalize (self-zeroing) ----------------
__global__ void finalize_kernel(float* __restrict__ sum, float* __restrict__ sq,
                                const float* __restrict__ gamma, const float* __restrict__ beta,
                                float* __restrict__ a, float* __restrict__ c,
                                int OC, float invE) {
    int i = blockIdx.x * blockDim.x + threadIdx.x;
    if (i < OC) {
        float m = sum[i] * invE;
        float var = sq[i] * invE - m * m;
        float rs = rsqrtf(var + 1e-5f);
        float ai = gamma[i] * rs;
        a[i] = ai;
        c[i] = beta[i] - m * ai;
        sum[i] = 0.f;
        sq[i] = 0.f;
    }
}

// ---------------- normalize + relu + mean-aggregate (CONTIGUOUS rows) ------
template <int OC>
__global__ __launch_bounds__(256)
void aggregate_kernel(const float* __restrict__ t, const int* __restrict__ rowptr,
                      const float* __restrict__ a,
                      const float* __restrict__ c, float* __restrict__ hout, int n) {
    int warp = (blockIdx.x * blockDim.x + threadIdx.x) >> 5;
    int lane = threadIdx.x & 31;
    if (warp >= n) return;
    constexpr int R = OC / 32;
    float av[R], cv[R], acc[R];
#pragma unroll
    for (int j = 0; j < R; j++) {
        int ch = j * 32 + lane;
        av[j] = a[ch]; cv[j] = c[ch]; acc[j] = 0.f;
    }
    int beg = rowptr[warp], end = rowptr[warp + 1];
    for (int p = beg; p < end; p++) {
        const float* rowp = t + (size_t)p * OC;
#pragma unroll
        for (int j = 0; j < R; j++) {
            float v = rowp[j * 32 + lane];
            acc[j] += fmaxf(v * av[j] + cv[j], 0.f);
        }
    }
    float inv = 1.f / fmaxf((float)(end - beg), 1.f);
#pragma unroll
    for (int j = 0; j < R; j++) hout[(size_t)warp * OC + j * 32 + lane] = acc[j] * inv;
}

// ---------------- global mean pool + head ----------------
__global__ void pool_kernel(const float* __restrict__ h, const int* __restrict__ gstart,
                            float* __restrict__ pool) {
    int g = blockIdx.x;
    int ch = threadIdx.x;
    int beg = gstart[g], end = gstart[g + 1];
    float s = 0.f;
    for (int nidx = beg; nidx < end; nidx++) s += h[(size_t)nidx * 256 + ch];
    pool[g * 256 + ch] = s / fmaxf((float)(end - beg), 1.f);
}
__global__ void head1_kernel(const float* __restrict__ pool, const float* __restrict__ W,
                             const float* __restrict__ b, float* __restrict__ z) {
    int g = blockIdx.x, j = threadIdx.x;
    __shared__ float sp[256];
    sp[j] = pool[g * 256 + j];
    sp[j + 128] = pool[g * 256 + j + 128];
    __syncthreads();
    float s = b[j];
#pragma unroll 8
    for (int k = 0; k < 256; k++) s += sp[k] * W[k * 128 + j];
    z[g * 128 + j] = fmaxf(s, 0.f);
}
__global__ void head2_kernel(const float* __restrict__ z, const float* __restrict__ W,
                             const float* __restrict__ b, float* __restrict__ out) {
    int t = threadIdx.x;
    int g = t >> 1, j = t & 1;
    float s = b[j];
#pragma unroll 8
    for (int k = 0; k < 128; k++) s += z[g * 128 + k] * W[k * 2 + j];
    out[g * 2 + j] = s;
}

// ---------------- launch ----------------
extern "C" void kernel_launch(void* const* d_in, const int* in_sizes, int n_in,
                              void* d_out, int out_size) {
    const float* x     = (const float*)d_in[0];
    const int*   ei    = (const int*)d_in[1];
    const int*   batch = (const int*)d_in[2];

    const int E = in_sizes[1] / 2;
    const int n = in_sizes[2];
    const int* srcp = ei;
    const int* dstp = ei + E;

    const float* W[3][2];  const float* B[3][2];
    const float* Gm[3][2]; const float* Bt[3][2];
    for (int l = 0; l < 3; l++) {
        int base = 3 + l * 8;
        W[l][0]  = (const float*)d_in[base + 0];
        B[l][0]  = (const float*)d_in[base + 1];
        Gm[l][0] = (const float*)d_in[base + 2];
        Bt[l][0] = (const float*)d_in[base + 3];
        W[l][1]  = (const float*)d_in[base + 4];
        B[l][1]  = (const float*)d_in[base + 5];
        Gm[l][1] = (const float*)d_in[base + 6];
        Bt[l][1] = (const float*)d_in[base + 7];
    }
    const float* hW1 = (const float*)d_in[27];
    const float* hb1 = (const float*)d_in[28];
    const float* hW2 = (const float*)d_in[29];
    const float* hb2 = (const float*)d_in[30];

    float *UV, *t2, *hA, *hB, *stats, *norm, *pool, *zbuf, *bias2;
    int *deg, *rowptr, *cursor, *psrc, *pdst, *cnt, *gstart;
    __nv_bfloat16 *wth, *wtl;
    cudaGetSymbolAddress((void**)&UV, g_t1);
    cudaGetSymbolAddress((void**)&t2, g_t2);
    cudaGetSymbolAddress((void**)&hA, g_hA);
    cudaGetSymbolAddress((void**)&hB, g_hB);
    cudaGetSymbolAddress((void**)&stats, g_stats);
    cudaGetSymbolAddress((void**)&norm, g_norm);
    cudaGetSymbolAddress((void**)&bias2, g_bias2);
    cudaGetSymbolAddress((void**)&deg, g_deg);
    cudaGetSymbolAddress((void**)&rowptr, g_rowptr);
    cudaGetSymbolAddress((void**)&cursor, g_cursor);
    cudaGetSymbolAddress((void**)&psrc, g_psrc);
    cudaGetSymbolAddress((void**)&pdst, g_pdst);
    cudaGetSymbolAddress((void**)&cnt, g_cnt);
    cudaGetSymbolAddress((void**)&gstart, g_gstart);
    cudaGetSymbolAddress((void**)&pool, g_pool);
    cudaGetSymbolAddress((void**)&zbuf, g_zbuf);
    cudaGetSymbolAddress((void**)&wth, g_wth);
    cudaGetSymbolAddress((void**)&wtl, g_wtl);

    float* sum1 = stats + 0;   float* sq1 = stats + 256;
    float* sum2 = stats + 512; float* sq2 = stats + 768;
    float* a1 = norm + 0;   float* c1 = norm + 256;
    float* a2 = norm + 512; float* c2 = norm + 768;

    const float invE = 1.f / (float)E;
    const int EB = (E + 127) / 128;
    const int NB = (n + 127) / 128;
    const int EG = (E + 255) / 256;
    const int NG = (n + 255) / 256;
    const int AGG = (n * 32 + 255) / 256;
    const int SGRID = 592;

    // ---- CSR build (permuted src/dst directly) ----
    cudaMemsetAsync(deg, 0, n * sizeof(int));
    cudaMemsetAsync(cnt, 0, GG * sizeof(int));
    cudaMemsetAsync(stats, 0, 1024 * sizeof(float));
    hist_deg_kernel<<<EG, 256>>>(dstp, deg, E);
    hist_cnt_kernel<<<NG, 256>>>(batch, cnt, n);
    scan_kernel<<<1, 1024>>>(deg, rowptr, cursor, cnt, gstart, n);
    fill_csr_kernel<<<EG, 256>>>(srcp, dstp, cursor, psrc, pdst, E);

    // ---- weight conversion ----
    convert_wsplit_kernel<<<(128 * 32 + 255) / 256, 256>>>(W[0][0], wth + 0, wtl + 0, 7, 64, 32);
    convert_w_kernel<<<(64 * 64 + 255) / 256, 256>>>(W[0][1], wth + 4096, wtl + 4096, 64, 64, 64);
    convert_wsplit_kernel<<<(256 * 64 + 255) / 256, 256>>>(W[1][0], wth + 8192, wtl + 8192, 64, 128, 64);
    convert_w_kernel<<<(128 * 128 + 255) / 256, 256>>>(W[1][1], wth + 24576, wtl + 24576, 128, 128, 128);
    convert_wsplit_kernel<<<(512 * 128 + 255) / 256, 256>>>(W[2][0], wth + 40960, wtl + 40960, 128, 256, 128);
    convert_w_kernel<<<(256 * 256 + 255) / 256, 256>>>(W[2][1], wth + 106496, wtl + 106496, 256, 256, 256);

    // ==== layer 1: 7 -> 64 ====
    cudaMemsetAsync(bias2, 0, 512 * sizeof(float));
    cudaMemcpyAsync(bias2, B[0][0], 64 * sizeof(float), cudaMemcpyDeviceToDevice);
    mgemm_kernel<7, 128, 128, 0, false><<<dim3(NB, 1), 512>>>(
        x, nullptr, nullptr, nullptr, nullptr, wth + 0, wtl + 0, bias2, UV, nullptr, nullptr, n);
    estats_kernel<64><<<SGRID, 256>>>(UV, psrc, rowptr, sum1, sq1, n);
    finalize_kernel<<<1, 64>>>(sum1, sq1, Gm[0][0], Bt[0][0], a1, c1, 64, invE);
    mgemm_kernel<64, 64, 64, 1, true><<<dim3(EB, 1), 256>>>(
        UV, psrc, pdst, a1, c1, wth + 4096, wtl + 4096, B[0][1], t2, sum2, sq2, E);
    finalize_kernel<<<1, 64>>>(sum2, sq2, Gm[0][1], Bt[0][1], a2, c2, 64, invE);
    aggregate_kernel<64><<<AGG, 256>>>(t2, rowptr, a2, c2, hA, n);

    // ==== layer 2: 64 -> 128 ====
    cudaMemsetAsync(bias2, 0, 512 * sizeof(float));
    cudaMemcpyAsync(bias2, B[1][0], 128 * sizeof(float), cudaMemcpyDeviceToDevice);
    mgemm_kernel<64, 256, 128, 0, false><<<dim3(NB, 2), 512>>>(
        hA, nullptr, nullptr, nullptr, nullptr, wth + 8192, wtl + 8192, bias2, UV, nullptr, nullptr, n);
    estats_kernel<128><<<SGRID, 256>>>(UV, psrc, rowptr, sum1, sq1, n);
    finalize_kernel<<<1, 128>>>(sum1, sq1, Gm[1][0], Bt[1][0], a1, c1, 128, invE);
    mgemm_kernel<128, 128, 128, 1, true><<<dim3(EB, 1), 512>>>(
        UV, psrc, pdst, a1, c1, wth + 24576, wtl + 24576, B[1][1], t2, sum2, sq2, E);
    finalize_kernel<<<1, 128>>>(sum2, sq2, Gm[1][1], Bt[1][1], a2, c2, 128, invE);
    aggregate_kernel<128><<<AGG, 256>>>(t2, rowptr, a2, c2, hB, n);

    // ==== layer 3: 128 -> 256 ====
    cudaMemsetAsync(bias2, 0, 512 * sizeof(float));
    cudaMemcpyAsync(bias2, B[2][0], 256 * sizeof(float), cudaMemcpyDeviceToDevice);
    mgemm_kernel<128, 512, 128, 0, false><<<dim3(NB, 4), 512>>>(
        hB, nullptr, nullptr, nullptr, nullptr, wth + 40960, wtl + 40960, bias2, UV, nullptr, nullptr, n);
    estats_kernel<256><<<SGRID, 256>>>(UV, psrc, rowptr, sum1, sq1, n);
    finalize_kernel<<<1, 256>>>(sum1, sq1, Gm[2][0], Bt[2][0], a1, c1, 256, invE);
    mgemm_kernel<256, 256, 128, 1, true><<<dim3(EB, 2), 512>>>(
        UV, psrc, pdst, a1, c1, wth + 106496, wtl + 106496, B[2][1], t2, sum2, sq2, E);
    finalize_kernel<<<1, 256>>>(sum2, sq2, Gm[2][1], Bt[2][1], a2, c2, 256, invE);
    aggregate_kernel<256><<<AGG, 256>>>(t2, rowptr, a2, c2, hA, n);

    // ---- pool + head ----
    pool_kernel<<<GG, 256>>>(hA, gstart, pool);
    head1_kernel<<<GG, 128>>>(pool, hW1, hb1, zbuf);
    head2_kernel<<<1, 128>>>(zbuf, hW2, hb2, (float*)d_out);
}

// round 12
// speedup vs baseline: 1.8913x; 1.0516x over previous
#include <cuda_runtime.h>
#include <cuda_bf16.h>
#include <cstdint>

// ---------------- problem constants ----------------
#define NN 50000
#define EE 500000
#define GG 64

// ---------------- scratch (device globals; no allocation allowed) ----------
__device__ float g_t1[(size_t)EE * 256];     // UV node buffer (<= 50K x 512)
__device__ float g_t2[(size_t)EE * 256];     // edge intermediate t2 (PERMUTED order)
__device__ float g_hA[(size_t)NN * 256];
__device__ float g_hB[(size_t)NN * 256];
__device__ float g_stats[1024];
__device__ float g_norm[1024];
__device__ float g_bias2[512];
__device__ int   g_deg[NN];
__device__ int   g_rowptr[NN + 1];
__device__ int   g_cursor[NN];
__device__ int   g_psrc[EE];
__device__ int   g_pdst[EE];
__device__ int   g_cnt[GG];
__device__ int   g_gstart[GG + 1];
__device__ float g_pool[GG * 256];
__device__ float g_zbuf[GG * 128];
__device__ __nv_bfloat16 g_wth[172032];
__device__ __nv_bfloat16 g_wtl[172032];

// ---------------- mma.sync / ldmatrix helpers ------------------------------
#define MMA_BF16(d, a, b)                                                        \
    asm volatile("mma.sync.aligned.m16n8k16.row.col.f32.bf16.bf16.f32 "          \
                 "{%0,%1,%2,%3}, {%4,%5,%6,%7}, {%8,%9}, {%0,%1,%2,%3};"         \
                 : "+f"((d)[0]), "+f"((d)[1]), "+f"((d)[2]), "+f"((d)[3])        \
                 : "r"((a)[0]), "r"((a)[1]), "r"((a)[2]), "r"((a)[3]),           \
                   "r"((b)[0]), "r"((b)[1]))

#define LDSM_X4(r0, r1, r2, r3, addr)                                            \
    asm volatile("ldmatrix.sync.aligned.m8n8.x4.shared.b16 {%0,%1,%2,%3}, [%4];" \
                 : "=r"(r0), "=r"(r1), "=r"(r2), "=r"(r3) : "r"(addr))

__device__ __forceinline__ uint32_t smem_u32(const void* p) {
    uint32_t a;
    asm("{ .reg .u64 t; cvta.to.shared.u64 t, %1; cvt.u32.u64 %0, t; }" : "=r"(a) : "l"(p));
    return a;
}

// ---------------- small utility kernels ----------------
__global__ void hist_deg_kernel(const int* __restrict__ dst, int* __restrict__ deg, int E) {
    int e = blockIdx.x * blockDim.x + threadIdx.x;
    if (e < E) atomicAdd(&deg[dst[e]], 1);
}
__global__ void hist_cnt_kernel(const int* __restrict__ batch, int* __restrict__ cnt, int n) {
    int i = blockIdx.x * blockDim.x + threadIdx.x;
    if (i < n) atomicAdd(&cnt[batch[i]], 1);
}
__global__ void scan_kernel(const int* __restrict__ deg, int* __restrict__ rowptr,
                            int* __restrict__ cursor, const int* __restrict__ cnt,
                            int* __restrict__ gstart, int n) {
    __shared__ int sh[1024];
    __shared__ int carry;
    int t = threadIdx.x;
    if (t == 0) carry = 0;
    __syncthreads();
    for (int base = 0; base < n; base += 1024) {
        int idx = base + t;
        int v = (idx < n) ? deg[idx] : 0;
        sh[t] = v;
        __syncthreads();
        for (int off = 1; off < 1024; off <<= 1) {
            int add = (t >= off) ? sh[t - off] : 0;
            __syncthreads();
            sh[t] += add;
            __syncthreads();
        }
        int ex = sh[t] - v;
        int cbase = carry;
        if (idx < n) { rowptr[idx] = cbase + ex; cursor[idx] = cbase + ex; }
        __syncthreads();
        if (t == 1023) carry = cbase + sh[1023];
        __syncthreads();
    }
    if (t == 0) {
        rowptr[n] = carry;
        int s = 0;
        for (int g = 0; g < GG; g++) { gstart[g] = s; s += cnt[g]; }
        gstart[GG] = s;
    }
}
__global__ void fill_csr_kernel(const int* __restrict__ src, const int* __restrict__ dst,
                                int* __restrict__ cursor,
                                int* __restrict__ psrc, int* __restrict__ pdst, int E) {
    int e = blockIdx.x * blockDim.x + threadIdx.x;
    if (e < E) {
        int d = dst[e];
        int p = atomicAdd(&cursor[d], 1);
        psrc[p] = src[e];
        pdst[p] = d;
    }
}

__global__ void convert_w_kernel(const float* __restrict__ W,
                                 __nv_bfloat16* __restrict__ Wth,
                                 __nv_bfloat16* __restrict__ Wtl,
                                 int K, int OC, int KPAD) {
    int idx = blockIdx.x * blockDim.x + threadIdx.x;
    if (idx >= OC * KPAD) return;
    int n = idx / KPAD, k = idx % KPAD;
    float w = (k < K) ? W[(size_t)k * OC + n] : 0.f;
    __nv_bfloat16 h = __float2bfloat16_rn(w);
    Wth[idx] = h;
    Wtl[idx] = __float2bfloat16_rn(w - __bfloat162float(h));
}

__global__ void convert_wsplit_kernel(const float* __restrict__ W1,
                                      __nv_bfloat16* __restrict__ Wth,
                                      __nv_bfloat16* __restrict__ Wtl,
                                      int C, int OC, int KPAD) {
    int idx = blockIdx.x * blockDim.x + threadIdx.x;
    if (idx >= 2 * OC * KPAD) return;
    int n = idx / KPAD, k = idx % KPAD;
    float w = 0.f;
    if (k < C) {
        if (n < OC) w = W1[(size_t)k * OC + n] - W1[(size_t)(k + C) * OC + n];
        else        w = W1[(size_t)(k + C) * OC + (n - OC)];
    }
    __nv_bfloat16 h = __float2bfloat16_rn(w);
    Wth[idx] = h;
    Wtl[idx] = __float2bfloat16_rn(w - __bfloat162float(h));
}

// ---------------- tensor-core GEMM (double-buffered, 1 sync/chunk) ---------
// BN in {64,128}.  THREADS = BN*4.  Warps = 4(M) x (BN/32)(N), warp tile 32x32.
// 3 MMAs per k16 (hi/lo split).  Dynamic smem; A/B chunks double-buffered:
//   loop: issue loads(ch+1) -> MMA(buf[ch&1]) -> convert+store(ch+1 -> other buf) -> sync
template <int K, int OC, int BN, int MODE, bool STATS>
__global__ __launch_bounds__(BN * 4, 128 / BN)
void mgemm_kernel(const float* __restrict__ fA,
                  const int* __restrict__ src, const int* __restrict__ dst,
                  const float* __restrict__ an, const float* __restrict__ cn,
                  const __nv_bfloat16* __restrict__ Wth,
                  const __nv_bfloat16* __restrict__ Wtl,
                  const float* __restrict__ bias,
                  float* __restrict__ out,
                  float* __restrict__ stat_sum, float* __restrict__ stat_sq,
                  int Rows) {
    constexpr int THREADS = BN * 4;
    constexpr int KPAD = (K + 31) / 32 * 32;
    constexpr int NCH = KPAD / 32;
    constexpr int SAS = 40;
    constexpr int ASTR = (MODE == 1) ? 2 * K : K;
    constexpr int TPR = THREADS / 128;
    constexpr int UNITS = 8 / TPR;
    constexpr int EST = BN + 8;

    constexpr int ABUF = 128 * SAS * 2;          // 10240 B per A buffer
    constexpr int BBUF = BN * SAS * 2;           // per B buffer
    constexpr int OFF_AH = 0;                    // + buf*ABUF  (2 bufs)
    constexpr int OFF_AL = 2 * ABUF;             // + buf*ABUF
    constexpr int OFF_BH = 4 * ABUF;             // + buf*BBUF
    constexpr int OFF_BL = 4 * ABUF + 2 * BBUF;  // + buf*BBUF
    constexpr int OFF_DST = 4 * ABUF + 4 * BBUF;
    constexpr int OFF_SRC = OFF_DST + 512;
    constexpr int OFF_AN = OFF_SRC + 512;
    constexpr int OFF_CN = OFF_AN + KPAD * 4;
    constexpr int OFF_SSUM = 64 * EST * 4;
    constexpr int OFF_SSQ = OFF_SSUM + BN * 4;

    extern __shared__ char SM[];
    int* sdst = reinterpret_cast<int*>(SM + OFF_DST);
    int* ssrc = reinterpret_cast<int*>(SM + OFF_SRC);
    float* sAn = reinterpret_cast<float*>(SM + OFF_AN);
    float* sCn = reinterpret_cast<float*>(SM + OFF_CN);

    const int tid = threadIdx.x;
    const int lane = tid & 31;
    const int wid = tid >> 5;
    const int wm = wid & 3;
    const int wn = wid >> 2;
    const int e0 = blockIdx.x * 128;
    const int col0 = blockIdx.y * BN;

    const uint32_t sAh_u = smem_u32(SM + OFF_AH);
    const uint32_t sAl_u = smem_u32(SM + OFF_AL);
    const uint32_t sBh_u = smem_u32(SM + OFF_BH);
    const uint32_t sBl_u = smem_u32(SM + OFF_BL);

    if (MODE == 1) {
        if (tid < 128) {
            int e = e0 + tid;
            int ee = (e < Rows) ? e : (Rows - 1);
            sdst[tid] = dst[ee];
            ssrc[tid] = src[ee];
        }
        for (int i = tid; i < K; i += THREADS) { sAn[i] = an[i]; sCn[i] = cn[i]; }
    }
    __syncthreads();

    float acc[2][4][4];
#pragma unroll
    for (int mt = 0; mt < 2; mt++)
#pragma unroll
        for (int nt = 0; nt < 4; nt++)
#pragma unroll
            for (int j = 0; j < 4; j++) acc[mt][nt][j] = 0.f;

    const int arow = tid / TPR;
    const int acg = (tid % TPR) * (32 / TPR);
    int nd = 0, ns = 0;
    if (MODE == 1) { nd = sdst[arow]; ns = ssrc[arow]; }

    const int bn_ = tid >> 2;
    const int bu_ = tid & 3;
    const int bdoff = (bn_ * SAS + bu_ * 8) * 2;     // bytes

    float4 P[UNITS], Q[UNITS];
    uint4 BHr, BLr;

    auto load_chunk = [&](int ch) {
        const int k0 = ch * 32 + acg;
        if (MODE == 1) {
            const float* Ur = fA + (size_t)nd * ASTR;
            const float* Vr = fA + (size_t)ns * ASTR + K;
#pragma unroll
            for (int u = 0; u < UNITS; u++) {
                P[u] = *reinterpret_cast<const float4*>(Ur + k0 + u * 4);
                Q[u] = *reinterpret_cast<const float4*>(Vr + k0 + u * 4);
            }
        } else {
            const int i = e0 + arow;
            if (K % 4 == 0) {
                if (i < Rows) {
#pragma unroll
                    for (int u = 0; u < UNITS; u++)
                        P[u] = *reinterpret_cast<const float4*>(&fA[(size_t)i * K + k0 + u * 4]);
                } else {
#pragma unroll
                    for (int u = 0; u < UNITS; u++) P[u] = make_float4(0.f, 0.f, 0.f, 0.f);
                }
            } else {  // K=7 scalar path (NCH==1)
#pragma unroll
                for (int u = 0; u < UNITS; u++) {
                    float t[4];
#pragma unroll
                    for (int j = 0; j < 4; j++) {
                        int kk = k0 + u * 4 + j;
                        t[j] = (i < Rows && kk < K) ? fA[(size_t)i * K + kk] : 0.f;
                    }
                    P[u] = make_float4(t[0], t[1], t[2], t[3]);
                }
            }
        }
    };
    auto load_B = [&](int ch) {
        size_t soff = (size_t)(col0 + bn_) * KPAD + ch * 32 + bu_ * 8;
        BHr = *reinterpret_cast<const uint4*>(Wth + soff);
        BLr = *reinterpret_cast<const uint4*>(Wtl + soff);
    };
    auto store_chunk = [&](int ch, int buf) {
        char* aH = SM + OFF_AH + buf * ABUF;
        char* aL = SM + OFF_AL + buf * ABUF;
        const int k0 = ch * 32 + acg;
#pragma unroll
        for (int u = 0; u < UNITS; u++) {
            float4 v;
            if (MODE == 1) {
                const int k = k0 + u * 4;
                v.x = fmaxf((P[u].x + Q[u].x) * sAn[k + 0] + sCn[k + 0], 0.f);
                v.y = fmaxf((P[u].y + Q[u].y) * sAn[k + 1] + sCn[k + 1], 0.f);
                v.z = fmaxf((P[u].z + Q[u].z) * sAn[k + 2] + sCn[k + 2], 0.f);
                v.w = fmaxf((P[u].w + Q[u].w) * sAn[k + 3] + sCn[k + 3], 0.f);
            } else {
                v = P[u];
            }
            __nv_bfloat162 h01 = __float22bfloat162_rn(make_float2(v.x, v.y));
            __nv_bfloat162 h23 = __float22bfloat162_rn(make_float2(v.z, v.w));
            float2 hf01 = __bfloat1622float2(h01);
            float2 hf23 = __bfloat1622float2(h23);
            __nv_bfloat162 l01 = __float22bfloat162_rn(make_float2(v.x - hf01.x, v.y - hf01.y));
            __nv_bfloat162 l23 = __float22bfloat162_rn(make_float2(v.z - hf23.x, v.w - hf23.y));
            uint2 H, L;
            H.x = *reinterpret_cast<uint32_t*>(&h01);
            H.y = *reinterpret_cast<uint32_t*>(&h23);
            L.x = *reinterpret_cast<uint32_t*>(&l01);
            L.y = *reinterpret_cast<uint32_t*>(&l23);
            int so = (arow * SAS + acg + u * 4) * 2;
            *reinterpret_cast<uint2*>(aH + so) = H;
            *reinterpret_cast<uint2*>(aL + so) = L;
        }
        *reinterpret_cast<uint4*>(SM + OFF_BH + buf * BBUF + bdoff) = BHr;
        *reinterpret_cast<uint4*>(SM + OFF_BL + buf * BBUF + bdoff) = BLr;
    };

    const int a_lrow = (lane & 7) + ((lane >> 3) & 1) * 8;
    const int a_lcol = (lane >> 4) * 8;
    const int b_lrow = (lane & 7) + (lane >> 4) * 8;
    const int b_lcol = ((lane >> 3) & 1) * 8;

    load_chunk(0);
    load_B(0);
    store_chunk(0, 0);
    __syncthreads();

    for (int ch = 0; ch < NCH; ch++) {
        const int cur = ch & 1;
        if (ch + 1 < NCH) { load_chunk(ch + 1); load_B(ch + 1); }

        const uint32_t aHb = sAh_u + cur * ABUF;
        const uint32_t aLb = sAl_u + cur * ABUF;
        const uint32_t bHb = sBh_u + cur * BBUF;
        const uint32_t bLb = sBl_u + cur * BBUF;
#pragma unroll
        for (int ks = 0; ks < 2; ks++) {
            const int kb = ks * 16;
            uint32_t ah[2][4], al[2][4];
#pragma unroll
            for (int mt = 0; mt < 2; mt++) {
                int r = wm * 32 + mt * 16 + a_lrow;
                uint32_t off = (uint32_t)(r * SAS + kb + a_lcol) * 2;
                LDSM_X4(ah[mt][0], ah[mt][1], ah[mt][2], ah[mt][3], aHb + off);
                LDSM_X4(al[mt][0], al[mt][1], al[mt][2], al[mt][3], aLb + off);
            }
#pragma unroll
            for (int p = 0; p < 2; p++) {
                int n0 = wn * 32 + p * 16;
                uint32_t boff = (uint32_t)((n0 + b_lrow) * SAS + kb + b_lcol) * 2;
                uint32_t bh[4], bl[4];
                LDSM_X4(bh[0], bh[1], bh[2], bh[3], bHb + boff);
                LDSM_X4(bl[0], bl[1], bl[2], bl[3], bLb + boff);
#pragma unroll
                for (int mt = 0; mt < 2; mt++) {
                    MMA_BF16(acc[mt][2 * p], ah[mt], (&bh[0]));
                    MMA_BF16(acc[mt][2 * p], ah[mt], (&bl[0]));
                    MMA_BF16(acc[mt][2 * p], al[mt], (&bh[0]));
                    MMA_BF16(acc[mt][2 * p + 1], ah[mt], (&bh[2]));
                    MMA_BF16(acc[mt][2 * p + 1], ah[mt], (&bl[2]));
                    MMA_BF16(acc[mt][2 * p + 1], al[mt], (&bh[2]));
                }
            }
        }
        if (ch + 1 < NCH) store_chunk(ch + 1, 1 - cur);
        __syncthreads();
    }

    // ---- epilogue ----
    float* ebuf = reinterpret_cast<float*>(SM);
    float* ssum = reinterpret_cast<float*>(SM + OFF_SSUM);
    float* ssq = reinterpret_cast<float*>(SM + OFF_SSQ);

    const int q = lane >> 2, s = lane & 3;

#pragma unroll
    for (int nt = 0; nt < 4; nt++) {
        const int col = col0 + wn * 32 + nt * 8 + s * 2;
        const float b0 = bias[col], b1 = bias[col + 1];
#pragma unroll
        for (int mt = 0; mt < 2; mt++) {
            acc[mt][nt][0] += b0; acc[mt][nt][1] += b1;
            acc[mt][nt][2] += b0; acc[mt][nt][3] += b1;
        }
    }

    if (STATS) {
        if (tid < 2 * BN) reinterpret_cast<float*>(SM + OFF_SSUM)[tid] = 0.f;
        __syncthreads();
#pragma unroll
        for (int nt = 0; nt < 4; nt++) {
            const int colw = wn * 32 + nt * 8 + s * 2;
            float s0 = 0.f, q0 = 0.f, s1 = 0.f, q1 = 0.f;
#pragma unroll
            for (int mt = 0; mt < 2; mt++) {
                const int r = wm * 32 + mt * 16 + q;
                if (e0 + r < Rows) {
                    s0 += acc[mt][nt][0]; q0 += acc[mt][nt][0] * acc[mt][nt][0];
                    s1 += acc[mt][nt][1]; q1 += acc[mt][nt][1] * acc[mt][nt][1];
                }
                if (e0 + r + 8 < Rows) {
                    s0 += acc[mt][nt][2]; q0 += acc[mt][nt][2] * acc[mt][nt][2];
                    s1 += acc[mt][nt][3]; q1 += acc[mt][nt][3] * acc[mt][nt][3];
                }
            }
#pragma unroll
            for (int m = 4; m <= 16; m <<= 1) {
                s0 += __shfl_xor_sync(0xffffffff, s0, m);
                q0 += __shfl_xor_sync(0xffffffff, q0, m);
                s1 += __shfl_xor_sync(0xffffffff, s1, m);
                q1 += __shfl_xor_sync(0xffffffff, q1, m);
            }
            if (q == 0) {
                atomicAdd(&ssum[colw], s0);
                atomicAdd(&ssq[colw], q0);
                atomicAdd(&ssum[colw + 1], s1);
                atomicAdd(&ssq[colw + 1], q1);
            }
        }
        __syncthreads();
        if (tid < BN) {
            atomicAdd(&stat_sum[col0 + tid], ssum[tid]);
            atomicAdd(&stat_sq[col0 + tid], ssq[tid]);
        }
    }

    // coalesced smem-staged store (two 64-row passes)
#pragma unroll
    for (int pass = 0; pass < 2; pass++) {
        __syncthreads();
        if ((wm >> 1) == pass) {
            const int wml = wm & 1;
#pragma unroll
            for (int mt = 0; mt < 2; mt++) {
                const int rl = wml * 32 + mt * 16 + q;
#pragma unroll
                for (int nt = 0; nt < 4; nt++) {
                    const int colw = wn * 32 + nt * 8 + s * 2;
                    *reinterpret_cast<float2*>(&ebuf[rl * EST + colw]) =
                        make_float2(acc[mt][nt][0], acc[mt][nt][1]);
                    *reinterpret_cast<float2*>(&ebuf[(rl + 8) * EST + colw]) =
                        make_float2(acc[mt][nt][2], acc[mt][nt][3]);
                }
            }
        }
        __syncthreads();
#pragma unroll
        for (int ii = 0; ii < 4; ii++) {
            const int i = tid + ii * THREADS;
            const int row = i / (BN / 4), c4 = i % (BN / 4);
            const int e = e0 + pass * 64 + row;
            if (e < Rows) {
                float4 v = *reinterpret_cast<float4*>(&ebuf[row * EST + c4 * 4]);
                *reinterpret_cast<float4*>(&out[(size_t)e * OC + col0 + c4 * 4]) = v;
            }
        }
    }
}

// ---------------- node-centric edge stats ----------------
template <int OC>
__global__ __launch_bounds__(256)
void estats_kernel(const float* __restrict__ UV, const int* __restrict__ psrc,
                   const int* __restrict__ rowptr,
                   float* __restrict__ sum, float* __restrict__ sq, int n) {
    constexpr int R = OC / 32;
    __shared__ float ss[OC], sv[OC];
    const int tid = threadIdx.x, lane = tid & 31, wid = tid >> 5;
    for (int i = tid; i < OC; i += 256) { ss[i] = 0.f; sv[i] = 0.f; }
    __syncthreads();
    float s[R], q[R];
#pragma unroll
    for (int j = 0; j < R; j++) { s[j] = 0.f; q[j] = 0.f; }
    const int nwarps = gridDim.x * 8;
    for (int i = blockIdx.x * 8 + wid; i < n; i += nwarps) {
        const int beg = rowptr[i], end = rowptr[i + 1];
        const float dg = (float)(end - beg);
        float U[R], sV[R], sV2[R];
        const float* Ur = UV + (size_t)i * (2 * OC);
#pragma unroll
        for (int j = 0; j < R; j++) { U[j] = Ur[j * 32 + lane]; sV[j] = 0.f; sV2[j] = 0.f; }
        for (int p = beg; p < end; p++) {
            const float* Vr = UV + (size_t)psrc[p] * (2 * OC) + OC;
#pragma unroll
            for (int j = 0; j < R; j++) {
                float v = Vr[j * 32 + lane];
                sV[j] += v; sV2[j] += v * v;
            }
        }
#pragma unroll
        for (int j = 0; j < R; j++) {
            s[j] += dg * U[j] + sV[j];
            q[j] += dg * U[j] * U[j] + 2.f * U[j] * sV[j] + sV2[j];
        }
    }
#pragma unroll
    for (int j = 0; j < R; j++) {
        atomicAdd(&ss[j * 32 + lane], s[j]);
        atomicAdd(&sv[j * 32 + lane], q[j]);
    }
    __syncthreads();
    for (int i = tid; i < OC; i += 256) {
        atomicAdd(&sum[i], ss[i]);
        atomicAdd(&sq[i], sv[i]);
    }
}

// ---------------- BN finalize (self-zeroing) ----------------
__global__ void finalize_kernel(float* __restrict__ sum, float* __restrict__ sq,
                                const float* __restrict__ gamma, const float* __restrict__ beta,
                                float* __restrict__ a, float* __restrict__ c,
                                int OC, float invE) {
    int i = blockIdx.x * blockDim.x + threadIdx.x;
    if (i < OC) {
        float m = sum[i] * invE;
        float var = sq[i] * invE - m * m;
        float rs = rsqrtf(var + 1e-5f);
        float ai = gamma[i] * rs;
        a[i] = ai;
        c[i] = beta[i] - m * ai;
        sum[i] = 0.f;
        sq[i] = 0.f;
    }
}

// ---------------- normalize + relu + mean-aggregate (contiguous rows) ------
template <int OC>
__global__ __launch_bounds__(256)
void aggregate_kernel(const float* __restrict__ t, const int* __restrict__ rowptr,
                      const float* __restrict__ a,
                      const float* __restrict__ c, float* __restrict__ hout, int n) {
    int warp = (blockIdx.x * blockDim.x + threadIdx.x) >> 5;
    int lane = threadIdx.x & 31;
    if (warp >= n) return;
    constexpr int R = OC / 32;
    float av[R], cv[R], acc[R];
#pragma unroll
    for (int j = 0; j < R; j++) {
        int ch = j * 32 + lane;
        av[j] = a[ch]; cv[j] = c[ch]; acc[j] = 0.f;
    }
    int beg = rowptr[warp], end = rowptr[warp + 1];
    for (int p = beg; p < end; p++) {
        const float* rowp = t + (size_t)p * OC;
#pragma unroll
        for (int j = 0; j < R; j++) {
            float v = rowp[j * 32 + lane];
            acc[j] += fmaxf(v * av[j] + cv[j], 0.f);
        }
    }
    float inv = 1.f / fmaxf((float)(end - beg), 1.f);
#pragma unroll
    for (int j = 0; j < R; j++) hout[(size_t)warp * OC + j * 32 + lane] = acc[j] * inv;
}

// ---------------- global mean pool + head ----------------
__global__ void pool_kernel(const float* __restrict__ h, const int* __restrict__ gstart,
                            float* __restrict__ pool) {
    int g = blockIdx.x;
    int ch = threadIdx.x;
    int beg = gstart[g], end = gstart[g + 1];
    float s = 0.f;
    for (int nidx = beg; nidx < end; nidx++) s += h[(size_t)nidx * 256 + ch];
    pool[g * 256 + ch] = s / fmaxf((float)(end - beg), 1.f);
}
__global__ void head1_kernel(const float* __restrict__ pool, const float* __restrict__ W,
                             const float* __restrict__ b, float* __restrict__ z) {
    int g = blockIdx.x, j = threadIdx.x;
    __shared__ float sp[256];
    sp[j] = pool[g * 256 + j];
    sp[j + 128] = pool[g * 256 + j + 128];
    __syncthreads();
    float s = b[j];
#pragma unroll 8
    for (int k = 0; k < 256; k++) s += sp[k] * W[k * 128 + j];
    z[g * 128 + j] = fmaxf(s, 0.f);
}
__global__ void head2_kernel(const float* __restrict__ z, const float* __restrict__ W,
                             const float* __restrict__ b, float* __restrict__ out) {
    int t = threadIdx.x;
    int g = t >> 1, j = t & 1;
    float s = b[j];
#pragma unroll 8
    for (int k = 0; k < 128; k++) s += z[g * 128 + k] * W[k * 2 + j];
    out[g * 2 + j] = s;
}

// ---------------- launch ----------------
static inline int gemm_smem(int KPAD, int BN) {
    int prod = 4 * 10240 + 4 * BN * 80 + 1024 + 2 * KPAD * 4;
    int epi = 64 * (BN + 8) * 4 + 8 * BN;
    return prod > epi ? prod : epi;
}

extern "C" void kernel_launch(void* const* d_in, const int* in_sizes, int n_in,
                              void* d_out, int out_size) {
    const float* x     = (const float*)d_in[0];
    const int*   ei    = (const int*)d_in[1];
    const int*   batch = (const int*)d_in[2];

    const int E = in_sizes[1] / 2;
    const int n = in_sizes[2];
    const int* srcp = ei;
    const int* dstp = ei + E;

    const float* W[3][2];  const float* B[3][2];
    const float* Gm[3][2]; const float* Bt[3][2];
    for (int l = 0; l < 3; l++) {
        int base = 3 + l * 8;
        W[l][0]  = (const float*)d_in[base + 0];
        B[l][0]  = (const float*)d_in[base + 1];
        Gm[l][0] = (const float*)d_in[base + 2];
        Bt[l][0] = (const float*)d_in[base + 3];
        W[l][1]  = (const float*)d_in[base + 4];
        B[l][1]  = (const float*)d_in[base + 5];
        Gm[l][1] = (const float*)d_in[base + 6];
        Bt[l][1] = (const float*)d_in[base + 7];
    }
    const float* hW1 = (const float*)d_in[27];
    const float* hb1 = (const float*)d_in[28];
    const float* hW2 = (const float*)d_in[29];
    const float* hb2 = (const float*)d_in[30];

    float *UV, *t2, *hA, *hB, *stats, *norm, *pool, *zbuf, *bias2;
    int *deg, *rowptr, *cursor, *psrc, *pdst, *cnt, *gstart;
    __nv_bfloat16 *wth, *wtl;
    cudaGetSymbolAddress((void**)&UV, g_t1);
    cudaGetSymbolAddress((void**)&t2, g_t2);
    cudaGetSymbolAddress((void**)&hA, g_hA);
    cudaGetSymbolAddress((void**)&hB, g_hB);
    cudaGetSymbolAddress((void**)&stats, g_stats);
    cudaGetSymbolAddress((void**)&norm, g_norm);
    cudaGetSymbolAddress((void**)&bias2, g_bias2);
    cudaGetSymbolAddress((void**)&deg, g_deg);
    cudaGetSymbolAddress((void**)&rowptr, g_rowptr);
    cudaGetSymbolAddress((void**)&cursor, g_cursor);
    cudaGetSymbolAddress((void**)&psrc, g_psrc);
    cudaGetSymbolAddress((void**)&pdst, g_pdst);
    cudaGetSymbolAddress((void**)&cnt, g_cnt);
    cudaGetSymbolAddress((void**)&gstart, g_gstart);
    cudaGetSymbolAddress((void**)&pool, g_pool);
    cudaGetSymbolAddress((void**)&zbuf, g_zbuf);
    cudaGetSymbolAddress((void**)&wth, g_wth);
    cudaGetSymbolAddress((void**)&wtl, g_wtl);

    float* sum1 = stats + 0;   float* sq1 = stats + 256;
    float* sum2 = stats + 512; float* sq2 = stats + 768;
    float* a1 = norm + 0;   float* c1 = norm + 256;
    float* a2 = norm + 512; float* c2 = norm + 768;

    const float invE = 1.f / (float)E;
    const int EB = (E + 127) / 128;
    const int NB = (n + 127) / 128;
    const int EG = (E + 255) / 256;
    const int NG = (n + 255) / 256;
    const int AGG = (n * 32 + 255) / 256;
    const int SGRID = 592;

    // dynamic smem opt-in (idempotent host calls; sizes per instantiation)
    cudaFuncSetAttribute(mgemm_kernel<7, 128, 128, 0, false>,  cudaFuncAttributeMaxDynamicSharedMemorySize, gemm_smem(32, 128));
    cudaFuncSetAttribute(mgemm_kernel<64, 64, 64, 1, true>,    cudaFuncAttributeMaxDynamicSharedMemorySize, gemm_smem(64, 64));
    cudaFuncSetAttribute(mgemm_kernel<64, 256, 128, 0, false>, cudaFuncAttributeMaxDynamicSharedMemorySize, gemm_smem(64, 128));
    cudaFuncSetAttribute(mgemm_kernel<128, 128, 128, 1, true>, cudaFuncAttributeMaxDynamicSharedMemorySize, gemm_smem(128, 128));
    cudaFuncSetAttribute(mgemm_kernel<128, 512, 128, 0, false>, cudaFuncAttributeMaxDynamicSharedMemorySize, gemm_smem(128, 128));
    cudaFuncSetAttribute(mgemm_kernel<256, 256, 128, 1, true>, cudaFuncAttributeMaxDynamicSharedMemorySize, gemm_smem(256, 128));

    // ---- CSR build (permuted src/dst directly) ----
    cudaMemsetAsync(deg, 0, n * sizeof(int));
    cudaMemsetAsync(cnt, 0, GG * sizeof(int));
    cudaMemsetAsync(stats, 0, 1024 * sizeof(float));
    hist_deg_kernel<<<EG, 256>>>(dstp, deg, E);
    hist_cnt_kernel<<<NG, 256>>>(batch, cnt, n);
    scan_kernel<<<1, 1024>>>(deg, rowptr, cursor, cnt, gstart, n);
    fill_csr_kernel<<<EG, 256>>>(srcp, dstp, cursor, psrc, pdst, E);

    // ---- weight conversion ----
    convert_wsplit_kernel<<<(128 * 32 + 255) / 256, 256>>>(W[0][0], wth + 0, wtl + 0, 7, 64, 32);
    convert_w_kernel<<<(64 * 64 + 255) / 256, 256>>>(W[0][1], wth + 4096, wtl + 4096, 64, 64, 64);
    convert_wsplit_kernel<<<(256 * 64 + 255) / 256, 256>>>(W[1][0], wth + 8192, wtl + 8192, 64, 128, 64);
    convert_w_kernel<<<(128 * 128 + 255) / 256, 256>>>(W[1][1], wth + 24576, wtl + 24576, 128, 128, 128);
    convert_wsplit_kernel<<<(512 * 128 + 255) / 256, 256>>>(W[2][0], wth + 40960, wtl + 40960, 128, 256, 128);
    convert_w_kernel<<<(256 * 256 + 255) / 256, 256>>>(W[2][1], wth + 106496, wtl + 106496, 256, 256, 256);

    // ==== layer 1: 7 -> 64 ====
    cudaMemsetAsync(bias2, 0, 512 * sizeof(float));
    cudaMemcpyAsync(bias2, B[0][0], 64 * sizeof(float), cudaMemcpyDeviceToDevice);
    mgemm_kernel<7, 128, 128, 0, false><<<dim3(NB, 1), 512, gemm_smem(32, 128)>>>(
        x, nullptr, nullptr, nullptr, nullptr, wth + 0, wtl + 0, bias2, UV, nullptr, nullptr, n);
    estats_kernel<64><<<SGRID, 256>>>(UV, psrc, rowptr, sum1, sq1, n);
    finalize_kernel<<<1, 64>>>(sum1, sq1, Gm[0][0], Bt[0][0], a1, c1, 64, invE);
    mgemm_kernel<64, 64, 64, 1, true><<<dim3(EB, 1), 256, gemm_smem(64, 64)>>>(
        UV, psrc, pdst, a1, c1, wth + 4096, wtl + 4096, B[0][1], t2, sum2, sq2, E);
    finalize_kernel<<<1, 64>>>(sum2, sq2, Gm[0][1], Bt[0][1], a2, c2, 64, invE);
    aggregate_kernel<64><<<AGG, 256>>>(t2, rowptr, a2, c2, hA, n);

    // ==== layer 2: 64 -> 128 ====
    cudaMemsetAsync(bias2, 0, 512 * sizeof(float));
    cudaMemcpyAsync(bias2, B[1][0], 128 * sizeof(float), cudaMemcpyDeviceToDevice);
    mgemm_kernel<64, 256, 128, 0, false><<<dim3(NB, 2), 512, gemm_smem(64, 128)>>>(
        hA, nullptr, nullptr, nullptr, nullptr, wth + 8192, wtl + 8192, bias2, UV, nullptr, nullptr, n);
    estats_kernel<128><<<SGRID, 256>>>(UV, psrc, rowptr, sum1, sq1, n);
    finalize_kernel<<<1, 128>>>(sum1, sq1, Gm[1][0], Bt[1][0], a1, c1, 128, invE);
    mgemm_kernel<128, 128, 128, 1, true><<<dim3(EB, 1), 512, gemm_smem(128, 128)>>>(
        UV, psrc, pdst, a1, c1, wth + 24576, wtl + 24576, B[1][1], t2, sum2, sq2, E);
    finalize_kernel<<<1, 128>>>(sum2, sq2, Gm[1][1], Bt[1][1], a2, c2, 128, invE);
    aggregate_kernel<128><<<AGG, 256>>>(t2, rowptr, a2, c2, hB, n);

    // ==== layer 3: 128 -> 256 ====
    cudaMemsetAsync(bias2, 0, 512 * sizeof(float));
    cudaMemcpyAsync(bias2, B[2][0], 256 * sizeof(float), cudaMemcpyDeviceToDevice);
    mgemm_kernel<128, 512, 128, 0, false><<<dim3(NB, 4), 512, gemm_smem(128, 128)>>>(
        hB, nullptr, nullptr, nullptr, nullptr, wth + 40960, wtl + 40960, bias2, UV, nullptr, nullptr, n);
    estats_kernel<256><<<SGRID, 256>>>(UV, psrc, rowptr, sum1, sq1, n);
    finalize_kernel<<<1, 256>>>(sum1, sq1, Gm[2][0], Bt[2][0], a1, c1, 256, invE);
    mgemm_kernel<256, 256, 128, 1, true><<<dim3(EB, 2), 512, gemm_smem(256, 128)>>>(
        UV, psrc, pdst, a1, c1, wth + 106496, wtl + 106496, B[2][1], t2, sum2, sq2, E);
    finalize_kernel<<<1, 256>>>(sum2, sq2, Gm[2][1], Bt[2][1], a2, c2, 256, invE);
    aggregate_kernel<256><<<AGG, 256>>>(t2, rowptr, a2, c2, hA, n);

    // ---- pool + head ----
    pool_kernel<<<GG, 256>>>(hA, gstart, pool);
    head1_kernel<<<GG, 128>>>(pool, hW1, hb1, zbuf);
    head2_kernel<<<1, 128>>>(zbuf, hW2, hb2, (float*)d_out);
}

// round 13
// speedup vs baseline: 1.9325x; 1.0218x over previous
#include <cuda_runtime.h>
#include <cuda_bf16.h>
#include <cstdint>

// ---------------- problem constants ----------------
#define NN 50000
#define EE 500000
#define GG 64

// ---------------- scratch (device globals; no allocation allowed) ----------
__device__ float g_t1[(size_t)EE * 256];     // UV node buffer (<= 50K x 512)
__device__ float g_t2[(size_t)EE * 256];     // edge intermediate t2 (PERMUTED order)
__device__ float g_hA[(size_t)NN * 256];
__device__ float g_hB[(size_t)NN * 256];
__device__ float g_stats[1024];
__device__ float g_norm[1024];
__device__ float g_bias2[512];
__device__ int   g_deg[NN];
__device__ int   g_rowptr[NN + 1];
__device__ int   g_cursor[NN];
__device__ int   g_psrc[EE];
__device__ int   g_pdst[EE];
__device__ int   g_cnt[GG];
__device__ int   g_gstart[GG + 1];
__device__ float g_pool[GG * 256];
__device__ float g_zbuf[GG * 128];
__device__ __nv_bfloat16 g_wth[172032];
__device__ __nv_bfloat16 g_wtl[172032];

// ---------------- mma.sync / ldmatrix helpers ------------------------------
#define MMA_BF16(d, a, b)                                                        \
    asm volatile("mma.sync.aligned.m16n8k16.row.col.f32.bf16.bf16.f32 "          \
                 "{%0,%1,%2,%3}, {%4,%5,%6,%7}, {%8,%9}, {%0,%1,%2,%3};"         \
                 : "+f"((d)[0]), "+f"((d)[1]), "+f"((d)[2]), "+f"((d)[3])        \
                 : "r"((a)[0]), "r"((a)[1]), "r"((a)[2]), "r"((a)[3]),           \
                   "r"((b)[0]), "r"((b)[1]))

#define LDSM_X4(r0, r1, r2, r3, addr)                                            \
    asm volatile("ldmatrix.sync.aligned.m8n8.x4.shared.b16 {%0,%1,%2,%3}, [%4];" \
                 : "=r"(r0), "=r"(r1), "=r"(r2), "=r"(r3) : "r"(addr))

__device__ __forceinline__ uint32_t smem_u32(const void* p) {
    uint32_t a;
    asm("{ .reg .u64 t; cvta.to.shared.u64 t, %1; cvt.u32.u64 %0, t; }" : "=r"(a) : "l"(p));
    return a;
}

// ---------------- small utility kernels ----------------
__global__ void hist_deg_kernel(const int* __restrict__ dst, int* __restrict__ deg, int E) {
    int e = blockIdx.x * blockDim.x + threadIdx.x;
    if (e < E) atomicAdd(&deg[dst[e]], 1);
}
__global__ void hist_cnt_kernel(const int* __restrict__ batch, int* __restrict__ cnt, int n) {
    int i = blockIdx.x * blockDim.x + threadIdx.x;
    if (i < n) atomicAdd(&cnt[batch[i]], 1);
}
__global__ void scan_kernel(const int* __restrict__ deg, int* __restrict__ rowptr,
                            int* __restrict__ cursor, const int* __restrict__ cnt,
                            int* __restrict__ gstart, int n) {
    __shared__ int sh[1024];
    __shared__ int carry;
    int t = threadIdx.x;
    if (t == 0) carry = 0;
    __syncthreads();
    for (int base = 0; base < n; base += 1024) {
        int idx = base + t;
        int v = (idx < n) ? deg[idx] : 0;
        sh[t] = v;
        __syncthreads();
        for (int off = 1; off < 1024; off <<= 1) {
            int add = (t >= off) ? sh[t - off] : 0;
            __syncthreads();
            sh[t] += add;
            __syncthreads();
        }
        int ex = sh[t] - v;
        int cbase = carry;
        if (idx < n) { rowptr[idx] = cbase + ex; cursor[idx] = cbase + ex; }
        __syncthreads();
        if (t == 1023) carry = cbase + sh[1023];
        __syncthreads();
    }
    if (t == 0) {
        rowptr[n] = carry;
        int s = 0;
        for (int g = 0; g < GG; g++) { gstart[g] = s; s += cnt[g]; }
        gstart[GG] = s;
    }
}
__global__ void fill_csr_kernel(const int* __restrict__ src, const int* __restrict__ dst,
                                int* __restrict__ cursor,
                                int* __restrict__ psrc, int* __restrict__ pdst, int E) {
    int e = blockIdx.x * blockDim.x + threadIdx.x;
    if (e < E) {
        int d = dst[e];
        int p = atomicAdd(&cursor[d], 1);
        psrc[p] = src[e];
        pdst[p] = d;
    }
}

__global__ void convert_w_kernel(const float* __restrict__ W,
                                 __nv_bfloat16* __restrict__ Wth,
                                 __nv_bfloat16* __restrict__ Wtl,
                                 int K, int OC, int KPAD) {
    int idx = blockIdx.x * blockDim.x + threadIdx.x;
    if (idx >= OC * KPAD) return;
    int n = idx / KPAD, k = idx % KPAD;
    float w = (k < K) ? W[(size_t)k * OC + n] : 0.f;
    __nv_bfloat16 h = __float2bfloat16_rn(w);
    Wth[idx] = h;
    Wtl[idx] = __float2bfloat16_rn(w - __bfloat162float(h));
}

__global__ void convert_wsplit_kernel(const float* __restrict__ W1,
                                      __nv_bfloat16* __restrict__ Wth,
                                      __nv_bfloat16* __restrict__ Wtl,
                                      int C, int OC, int KPAD) {
    int idx = blockIdx.x * blockDim.x + threadIdx.x;
    if (idx >= 2 * OC * KPAD) return;
    int n = idx / KPAD, k = idx % KPAD;
    float w = 0.f;
    if (k < C) {
        if (n < OC) w = W1[(size_t)k * OC + n] - W1[(size_t)(k + C) * OC + n];
        else        w = W1[(size_t)(k + C) * OC + (n - OC)];
    }
    __nv_bfloat16 h = __float2bfloat16_rn(w);
    Wth[idx] = h;
    Wtl[idx] = __float2bfloat16_rn(w - __bfloat162float(h));
}

// ---------------- tensor-core GEMM (double-buffered, 1 sync/chunk) ---------
// Block tile BM x BN; warps = (BM/32) x (BN/32); warp tile 32x32 (acc 32 regs).
// THREADS = BM*BN/32.  3 MMAs per k16 (hi/lo split).  Dynamic smem.
// MODE 0: node GEMM, A row i = fA[i*K..].  Rows = N.
// MODE 1: edge GEMM over permuted edges: A row p = relu((U[pdst]+V[psrc])*an+cn).
template <int K, int OC, int BM, int BN, int MODE, bool STATS>
__global__ __launch_bounds__(BM * BN / 32, 512 * 32 / (BM * BN))
void mgemm_kernel(const float* __restrict__ fA,
                  const int* __restrict__ src, const int* __restrict__ dst,
                  const float* __restrict__ an, const float* __restrict__ cn,
                  const __nv_bfloat16* __restrict__ Wth,
                  const __nv_bfloat16* __restrict__ Wtl,
                  const float* __restrict__ bias,
                  float* __restrict__ out,
                  float* __restrict__ stat_sum, float* __restrict__ stat_sq,
                  int Rows) {
    constexpr int THREADS = BM * BN / 32;
    constexpr int MW = BM / 32;              // M warps
    constexpr int KPAD = (K + 31) / 32 * 32;
    constexpr int NCH = KPAD / 32;
    constexpr int SAS = 40;
    constexpr int ASTR = (MODE == 1) ? 2 * K : K;
    constexpr int TPR = THREADS / BM;        // threads per A row
    constexpr int UNITS = 8 / TPR;           // float4 per thread per chunk
    constexpr int NB_LD = 128 / BM;          // B rows loaded per thread
    constexpr int EST = BN + 8;
    constexpr int NPASS = BM / 64;

    constexpr int ABUF = BM * SAS * 2;
    constexpr int BBUF = BN * SAS * 2;
    constexpr int OFF_AH = 0;
    constexpr int OFF_AL = 2 * ABUF;
    constexpr int OFF_BH = 4 * ABUF;
    constexpr int OFF_BL = 4 * ABUF + 2 * BBUF;
    constexpr int OFF_DST = 4 * ABUF + 4 * BBUF;
    constexpr int OFF_SRC = OFF_DST + 512;
    constexpr int OFF_AN = OFF_SRC + 512;
    constexpr int OFF_CN = OFF_AN + KPAD * 4;
    constexpr int OFF_SSUM = 64 * EST * 4;
    constexpr int OFF_SSQ = OFF_SSUM + BN * 4;

    extern __shared__ char SM[];
    int* sdst = reinterpret_cast<int*>(SM + OFF_DST);
    int* ssrc = reinterpret_cast<int*>(SM + OFF_SRC);
    float* sAn = reinterpret_cast<float*>(SM + OFF_AN);
    float* sCn = reinterpret_cast<float*>(SM + OFF_CN);

    const int tid = threadIdx.x;
    const int lane = tid & 31;
    const int wid = tid >> 5;
    const int wm = wid % MW;
    const int wn = wid / MW;
    const int e0 = blockIdx.x * BM;
    const int col0 = blockIdx.y * BN;

    const uint32_t sAh_u = smem_u32(SM + OFF_AH);
    const uint32_t sAl_u = smem_u32(SM + OFF_AL);
    const uint32_t sBh_u = smem_u32(SM + OFF_BH);
    const uint32_t sBl_u = smem_u32(SM + OFF_BL);

    if (MODE == 1) {
        if (tid < BM) {
            int e = e0 + tid;
            int ee = (e < Rows) ? e : (Rows - 1);
            sdst[tid] = dst[ee];
            ssrc[tid] = src[ee];
        }
        for (int i = tid; i < K; i += THREADS) { sAn[i] = an[i]; sCn[i] = cn[i]; }
    }
    __syncthreads();

    float acc[2][4][4];
#pragma unroll
    for (int mt = 0; mt < 2; mt++)
#pragma unroll
        for (int nt = 0; nt < 4; nt++)
#pragma unroll
            for (int j = 0; j < 4; j++) acc[mt][nt][j] = 0.f;

    const int arow = tid / TPR;
    const int acg = (tid % TPR) * (32 / TPR);
    int nd = 0, ns = 0;
    if (MODE == 1) { nd = sdst[arow]; ns = ssrc[arow]; }

    const int bn0 = tid >> 2;                // first B row handled
    const int bu_ = tid & 3;

    float4 P[UNITS], Q[UNITS];
    uint4 BHr[NB_LD], BLr[NB_LD];

    auto load_chunk = [&](int ch) {
        const int k0 = ch * 32 + acg;
        if (MODE == 1) {
            const float* Ur = fA + (size_t)nd * ASTR;
            const float* Vr = fA + (size_t)ns * ASTR + K;
#pragma unroll
            for (int u = 0; u < UNITS; u++) {
                P[u] = *reinterpret_cast<const float4*>(Ur + k0 + u * 4);
                Q[u] = *reinterpret_cast<const float4*>(Vr + k0 + u * 4);
            }
        } else {
            const int i = e0 + arow;
            if (K % 4 == 0) {
                if (i < Rows) {
#pragma unroll
                    for (int u = 0; u < UNITS; u++)
                        P[u] = *reinterpret_cast<const float4*>(&fA[(size_t)i * K + k0 + u * 4]);
                } else {
#pragma unroll
                    for (int u = 0; u < UNITS; u++) P[u] = make_float4(0.f, 0.f, 0.f, 0.f);
                }
            } else {  // K=7 scalar path (NCH==1)
#pragma unroll
                for (int u = 0; u < UNITS; u++) {
                    float t[4];
#pragma unroll
                    for (int j = 0; j < 4; j++) {
                        int kk = k0 + u * 4 + j;
                        t[j] = (i < Rows && kk < K) ? fA[(size_t)i * K + kk] : 0.f;
                    }
                    P[u] = make_float4(t[0], t[1], t[2], t[3]);
                }
            }
        }
    };
    auto load_B = [&](int ch) {
#pragma unroll
        for (int l = 0; l < NB_LD; l++) {
            int r = bn0 + l * (THREADS / 4);
            size_t soff = (size_t)(col0 + r) * KPAD + ch * 32 + bu_ * 8;
            BHr[l] = *reinterpret_cast<const uint4*>(Wth + soff);
            BLr[l] = *reinterpret_cast<const uint4*>(Wtl + soff);
        }
    };
    auto store_chunk = [&](int ch, int buf) {
        char* aH = SM + OFF_AH + buf * ABUF;
        char* aL = SM + OFF_AL + buf * ABUF;
        const int k0 = ch * 32 + acg;
#pragma unroll
        for (int u = 0; u < UNITS; u++) {
            float4 v;
            if (MODE == 1) {
                const int k = k0 + u * 4;
                v.x = fmaxf((P[u].x + Q[u].x) * sAn[k + 0] + sCn[k + 0], 0.f);
                v.y = fmaxf((P[u].y + Q[u].y) * sAn[k + 1] + sCn[k + 1], 0.f);
                v.z = fmaxf((P[u].z + Q[u].z) * sAn[k + 2] + sCn[k + 2], 0.f);
                v.w = fmaxf((P[u].w + Q[u].w) * sAn[k + 3] + sCn[k + 3], 0.f);
            } else {
                v = P[u];
            }
            __nv_bfloat162 h01 = __float22bfloat162_rn(make_float2(v.x, v.y));
            __nv_bfloat162 h23 = __float22bfloat162_rn(make_float2(v.z, v.w));
            float2 hf01 = __bfloat1622float2(h01);
            float2 hf23 = __bfloat1622float2(h23);
            __nv_bfloat162 l01 = __float22bfloat162_rn(make_float2(v.x - hf01.x, v.y - hf01.y));
            __nv_bfloat162 l23 = __float22bfloat162_rn(make_float2(v.z - hf23.x, v.w - hf23.y));
            uint2 H, L;
            H.x = *reinterpret_cast<uint32_t*>(&h01);
            H.y = *reinterpret_cast<uint32_t*>(&h23);
            L.x = *reinterpret_cast<uint32_t*>(&l01);
            L.y = *reinterpret_cast<uint32_t*>(&l23);
            int so = (arow * SAS + acg + u * 4) * 2;
            *reinterpret_cast<uint2*>(aH + so) = H;
            *reinterpret_cast<uint2*>(aL + so) = L;
        }
#pragma unroll
        for (int l = 0; l < NB_LD; l++) {
            int r = bn0 + l * (THREADS / 4);
            int doff = (r * SAS + bu_ * 8) * 2;
            *reinterpret_cast<uint4*>(SM + OFF_BH + buf * BBUF + doff) = BHr[l];
            *reinterpret_cast<uint4*>(SM + OFF_BL + buf * BBUF + doff) = BLr[l];
        }
    };

    const int a_lrow = (lane & 7) + ((lane >> 3) & 1) * 8;
    const int a_lcol = (lane >> 4) * 8;
    const int b_lrow = (lane & 7) + (lane >> 4) * 8;
    const int b_lcol = ((lane >> 3) & 1) * 8;

    load_chunk(0);
    load_B(0);
    store_chunk(0, 0);
    __syncthreads();

    for (int ch = 0; ch < NCH; ch++) {
        const int cur = ch & 1;
        if (ch + 1 < NCH) { load_chunk(ch + 1); load_B(ch + 1); }

        const uint32_t aHb = sAh_u + cur * ABUF;
        const uint32_t aLb = sAl_u + cur * ABUF;
        const uint32_t bHb = sBh_u + cur * BBUF;
        const uint32_t bLb = sBl_u + cur * BBUF;
#pragma unroll
        for (int ks = 0; ks < 2; ks++) {
            const int kb = ks * 16;
            uint32_t ah[2][4], al[2][4];
#pragma unroll
            for (int mt = 0; mt < 2; mt++) {
                int r = wm * 32 + mt * 16 + a_lrow;
                uint32_t off = (uint32_t)(r * SAS + kb + a_lcol) * 2;
                LDSM_X4(ah[mt][0], ah[mt][1], ah[mt][2], ah[mt][3], aHb + off);
                LDSM_X4(al[mt][0], al[mt][1], al[mt][2], al[mt][3], aLb + off);
            }
#pragma unroll
            for (int p = 0; p < 2; p++) {
                int n0 = wn * 32 + p * 16;
                uint32_t boff = (uint32_t)((n0 + b_lrow) * SAS + kb + b_lcol) * 2;
                uint32_t bh[4], bl[4];
                LDSM_X4(bh[0], bh[1], bh[2], bh[3], bHb + boff);
                LDSM_X4(bl[0], bl[1], bl[2], bl[3], bLb + boff);
#pragma unroll
                for (int mt = 0; mt < 2; mt++) {
                    MMA_BF16(acc[mt][2 * p], ah[mt], (&bh[0]));
                    MMA_BF16(acc[mt][2 * p], ah[mt], (&bl[0]));
                    MMA_BF16(acc[mt][2 * p], al[mt], (&bh[0]));
                    MMA_BF16(acc[mt][2 * p + 1], ah[mt], (&bh[2]));
                    MMA_BF16(acc[mt][2 * p + 1], ah[mt], (&bl[2]));
                    MMA_BF16(acc[mt][2 * p + 1], al[mt], (&bh[2]));
                }
            }
        }
        if (ch + 1 < NCH) store_chunk(ch + 1, 1 - cur);
        __syncthreads();
    }

    // ---- epilogue ----
    float* ebuf = reinterpret_cast<float*>(SM);
    float* ssum = reinterpret_cast<float*>(SM + OFF_SSUM);
    float* ssq = reinterpret_cast<float*>(SM + OFF_SSQ);

    const int q = lane >> 2, s = lane & 3;

#pragma unroll
    for (int nt = 0; nt < 4; nt++) {
        const int col = col0 + wn * 32 + nt * 8 + s * 2;
        const float b0 = bias[col], b1 = bias[col + 1];
#pragma unroll
        for (int mt = 0; mt < 2; mt++) {
            acc[mt][nt][0] += b0; acc[mt][nt][1] += b1;
            acc[mt][nt][2] += b0; acc[mt][nt][3] += b1;
        }
    }

    if (STATS) {
        for (int i = tid; i < 2 * BN; i += THREADS)
            reinterpret_cast<float*>(SM + OFF_SSUM)[i] = 0.f;
        __syncthreads();
#pragma unroll
        for (int nt = 0; nt < 4; nt++) {
            const int colw = wn * 32 + nt * 8 + s * 2;
            float s0 = 0.f, q0 = 0.f, s1 = 0.f, q1 = 0.f;
#pragma unroll
            for (int mt = 0; mt < 2; mt++) {
                const int r = wm * 32 + mt * 16 + q;
                if (e0 + r < Rows) {
                    s0 += acc[mt][nt][0]; q0 += acc[mt][nt][0] * acc[mt][nt][0];
                    s1 += acc[mt][nt][1]; q1 += acc[mt][nt][1] * acc[mt][nt][1];
                }
                if (e0 + r + 8 < Rows) {
                    s0 += acc[mt][nt][2]; q0 += acc[mt][nt][2] * acc[mt][nt][2];
                    s1 += acc[mt][nt][3]; q1 += acc[mt][nt][3] * acc[mt][nt][3];
                }
            }
#pragma unroll
            for (int m = 4; m <= 16; m <<= 1) {
                s0 += __shfl_xor_sync(0xffffffff, s0, m);
                q0 += __shfl_xor_sync(0xffffffff, q0, m);
                s1 += __shfl_xor_sync(0xffffffff, s1, m);
                q1 += __shfl_xor_sync(0xffffffff, q1, m);
            }
            if (q == 0) {
                atomicAdd(&ssum[colw], s0);
                atomicAdd(&ssq[colw], q0);
                atomicAdd(&ssum[colw + 1], s1);
                atomicAdd(&ssq[colw + 1], q1);
            }
        }
        __syncthreads();
        if (tid < BN) {
            atomicAdd(&stat_sum[col0 + tid], ssum[tid]);
            atomicAdd(&stat_sq[col0 + tid], ssq[tid]);
        }
    }

    // coalesced smem-staged store (NPASS 64-row passes)
#pragma unroll
    for (int pass = 0; pass < NPASS; pass++) {
        __syncthreads();
        if (NPASS == 1 || (wm >> 1) == pass) {
            const int wml = wm & 1;
#pragma unroll
            for (int mt = 0; mt < 2; mt++) {
                const int rl = wml * 32 + mt * 16 + q;
#pragma unroll
                for (int nt = 0; nt < 4; nt++) {
                    const int colw = wn * 32 + nt * 8 + s * 2;
                    *reinterpret_cast<float2*>(&ebuf[rl * EST + colw]) =
                        make_float2(acc[mt][nt][0], acc[mt][nt][1]);
                    *reinterpret_cast<float2*>(&ebuf[(rl + 8) * EST + colw]) =
                        make_float2(acc[mt][nt][2], acc[mt][nt][3]);
                }
            }
        }
        __syncthreads();
        constexpr int II = 16 * BN / THREADS;
#pragma unroll
        for (int ii = 0; ii < II; ii++) {
            const int i = tid + ii * THREADS;
            const int row = i / (BN / 4), c4 = i % (BN / 4);
            const int e = e0 + pass * 64 + row;
            if (e < Rows) {
                float4 v = *reinterpret_cast<float4*>(&ebuf[row * EST + c4 * 4]);
                *reinterpret_cast<float4*>(&out[(size_t)e * OC + col0 + c4 * 4]) = v;
            }
        }
    }
}

// ---------------- node-centric edge stats ----------------
template <int OC>
__global__ __launch_bounds__(256)
void estats_kernel(const float* __restrict__ UV, const int* __restrict__ psrc,
                   const int* __restrict__ rowptr,
                   float* __restrict__ sum, float* __restrict__ sq, int n) {
    constexpr int R = OC / 32;
    __shared__ float ss[OC], sv[OC];
    const int tid = threadIdx.x, lane = tid & 31, wid = tid >> 5;
    for (int i = tid; i < OC; i += 256) { ss[i] = 0.f; sv[i] = 0.f; }
    __syncthreads();
    float s[R], q[R];
#pragma unroll
    for (int j = 0; j < R; j++) { s[j] = 0.f; q[j] = 0.f; }
    const int nwarps = gridDim.x * 8;
    for (int i = blockIdx.x * 8 + wid; i < n; i += nwarps) {
        const int beg = rowptr[i], end = rowptr[i + 1];
        const float dg = (float)(end - beg);
        float U[R], sV[R], sV2[R];
        const float* Ur = UV + (size_t)i * (2 * OC);
#pragma unroll
        for (int j = 0; j < R; j++) { U[j] = Ur[j * 32 + lane]; sV[j] = 0.f; sV2[j] = 0.f; }
        for (int p = beg; p < end; p++) {
            const float* Vr = UV + (size_t)psrc[p] * (2 * OC) + OC;
#pragma unroll
            for (int j = 0; j < R; j++) {
                float v = Vr[j * 32 + lane];
                sV[j] += v; sV2[j] += v * v;
            }
        }
#pragma unroll
        for (int j = 0; j < R; j++) {
            s[j] += dg * U[j] + sV[j];
            q[j] += dg * U[j] * U[j] + 2.f * U[j] * sV[j] + sV2[j];
        }
    }
#pragma unroll
    for (int j = 0; j < R; j++) {
        atomicAdd(&ss[j * 32 + lane], s[j]);
        atomicAdd(&sv[j * 32 + lane], q[j]);
    }
    __syncthreads();
    for (int i = tid; i < OC; i += 256) {
        atomicAdd(&sum[i], ss[i]);
        atomicAdd(&sq[i], sv[i]);
    }
}

// ---------------- BN finalize (self-zeroing) ----------------
__global__ void finalize_kernel(float* __restrict__ sum, float* __restrict__ sq,
                                const float* __restrict__ gamma, const float* __restrict__ beta,
                                float* __restrict__ a, float* __restrict__ c,
                                int OC, float invE) {
    int i = blockIdx.x * blockDim.x + threadIdx.x;
    if (i < OC) {
        float m = sum[i] * invE;
        float var = sq[i] * invE - m * m;
        float rs = rsqrtf(var + 1e-5f);
        float ai = gamma[i] * rs;
        a[i] = ai;
        c[i] = beta[i] - m * ai;
        sum[i] = 0.f;
        sq[i] = 0.f;
    }
}

// ---------------- normalize + relu + mean-aggregate (contiguous rows) ------
template <int OC>
__global__ __launch_bounds__(256)
void aggregate_kernel(const float* __restrict__ t, const int* __restrict__ rowptr,
                      const float* __restrict__ a,
                      const float* __restrict__ c, float* __restrict__ hout, int n) {
    int warp = (blockIdx.x * blockDim.x + threadIdx.x) >> 5;
    int lane = threadIdx.x & 31;
    if (warp >= n) return;
    constexpr int R = OC / 32;
    float av[R], cv[R], acc[R];
#pragma unroll
    for (int j = 0; j < R; j++) {
        int ch = j * 32 + lane;
        av[j] = a[ch]; cv[j] = c[ch]; acc[j] = 0.f;
    }
    int beg = rowptr[warp], end = rowptr[warp + 1];
    for (int p = beg; p < end; p++) {
        const float* rowp = t + (size_t)p * OC;
#pragma unroll
        for (int j = 0; j < R; j++) {
            float v = rowp[j * 32 + lane];
            acc[j] += fmaxf(v * av[j] + cv[j], 0.f);
        }
    }
    float inv = 1.f / fmaxf((float)(end - beg), 1.f);
#pragma unroll
    for (int j = 0; j < R; j++) hout[(size_t)warp * OC + j * 32 + lane] = acc[j] * inv;
}

// ---------------- global mean pool + head ----------------
__global__ void pool_kernel(const float* __restrict__ h, const int* __restrict__ gstart,
                            float* __restrict__ pool) {
    int g = blockIdx.x;
    int ch = threadIdx.x;
    int beg = gstart[g], end = gstart[g + 1];
    float s = 0.f;
    for (int nidx = beg; nidx < end; nidx++) s += h[(size_t)nidx * 256 + ch];
    pool[g * 256 + ch] = s / fmaxf((float)(end - beg), 1.f);
}
__global__ void head1_kernel(const float* __restrict__ pool, const float* __restrict__ W,
                             const float* __restrict__ b, float* __restrict__ z) {
    int g = blockIdx.x, j = threadIdx.x;
    __shared__ float sp[256];
    sp[j] = pool[g * 256 + j];
    sp[j + 128] = pool[g * 256 + j + 128];
    __syncthreads();
    float s = b[j];
#pragma unroll 8
    for (int k = 0; k < 256; k++) s += sp[k] * W[k * 128 + j];
    z[g * 128 + j] = fmaxf(s, 0.f);
}
__global__ void head2_kernel(const float* __restrict__ z, const float* __restrict__ W,
                             const float* __restrict__ b, float* __restrict__ out) {
    int t = threadIdx.x;
    int g = t >> 1, j = t & 1;
    float s = b[j];
#pragma unroll 8
    for (int k = 0; k < 128; k++) s += z[g * 128 + k] * W[k * 2 + j];
    out[g * 2 + j] = s;
}

// ---------------- launch ----------------
static inline int gemm_smem(int KPAD, int BM, int BN) {
    int prod = 4 * BM * 80 + 4 * BN * 80 + 1024 + 2 * KPAD * 4;
    int epi = 64 * (BN + 8) * 4 + 8 * BN;
    return prod > epi ? prod : epi;
}

extern "C" void kernel_launch(void* const* d_in, const int* in_sizes, int n_in,
                              void* d_out, int out_size) {
    const float* x     = (const float*)d_in[0];
    const int*   ei    = (const int*)d_in[1];
    const int*   batch = (const int*)d_in[2];

    const int E = in_sizes[1] / 2;
    const int n = in_sizes[2];
    const int* srcp = ei;
    const int* dstp = ei + E;

    const float* W[3][2];  const float* B[3][2];
    const float* Gm[3][2]; const float* Bt[3][2];
    for (int l = 0; l < 3; l++) {
        int base = 3 + l * 8;
        W[l][0]  = (const float*)d_in[base + 0];
        B[l][0]  = (const float*)d_in[base + 1];
        Gm[l][0] = (const float*)d_in[base + 2];
        Bt[l][0] = (const float*)d_in[base + 3];
        W[l][1]  = (const float*)d_in[base + 4];
        B[l][1]  = (const float*)d_in[base + 5];
        Gm[l][1] = (const float*)d_in[base + 6];
        Bt[l][1] = (const float*)d_in[base + 7];
    }
    const float* hW1 = (const float*)d_in[27];
    const float* hb1 = (const float*)d_in[28];
    const float* hW2 = (const float*)d_in[29];
    const float* hb2 = (const float*)d_in[30];

    float *UV, *t2, *hA, *hB, *stats, *norm, *pool, *zbuf, *bias2;
    int *deg, *rowptr, *cursor, *psrc, *pdst, *cnt, *gstart;
    __nv_bfloat16 *wth, *wtl;
    cudaGetSymbolAddress((void**)&UV, g_t1);
    cudaGetSymbolAddress((void**)&t2, g_t2);
    cudaGetSymbolAddress((void**)&hA, g_hA);
    cudaGetSymbolAddress((void**)&hB, g_hB);
    cudaGetSymbolAddress((void**)&stats, g_stats);
    cudaGetSymbolAddress((void**)&norm, g_norm);
    cudaGetSymbolAddress((void**)&bias2, g_bias2);
    cudaGetSymbolAddress((void**)&deg, g_deg);
    cudaGetSymbolAddress((void**)&rowptr, g_rowptr);
    cudaGetSymbolAddress((void**)&cursor, g_cursor);
    cudaGetSymbolAddress((void**)&psrc, g_psrc);
    cudaGetSymbolAddress((void**)&pdst, g_pdst);
    cudaGetSymbolAddress((void**)&cnt, g_cnt);
    cudaGetSymbolAddress((void**)&gstart, g_gstart);
    cudaGetSymbolAddress((void**)&pool, g_pool);
    cudaGetSymbolAddress((void**)&zbuf, g_zbuf);
    cudaGetSymbolAddress((void**)&wth, g_wth);
    cudaGetSymbolAddress((void**)&wtl, g_wtl);

    float* sum1 = stats + 0;   float* sq1 = stats + 256;
    float* sum2 = stats + 512; float* sq2 = stats + 768;
    float* a1 = norm + 0;   float* c1 = norm + 256;
    float* a2 = norm + 512; float* c2 = norm + 768;

    const float invE = 1.f / (float)E;
    const int EB128 = (E + 127) / 128;
    const int EB64 = (E + 63) / 64;
    const int NB = (n + 127) / 128;
    const int EG = (E + 255) / 256;
    const int NG = (n + 255) / 256;
    const int AGG = (n * 32 + 255) / 256;
    const int SGRID = 592;

    // dynamic smem opt-in
    cudaFuncSetAttribute(mgemm_kernel<7, 128, 128, 128, 0, false>,   cudaFuncAttributeMaxDynamicSharedMemorySize, gemm_smem(32, 128, 128));
    cudaFuncSetAttribute(mgemm_kernel<64, 64, 128, 64, 1, true>,     cudaFuncAttributeMaxDynamicSharedMemorySize, gemm_smem(64, 128, 64));
    cudaFuncSetAttribute(mgemm_kernel<64, 256, 128, 128, 0, false>,  cudaFuncAttributeMaxDynamicSharedMemorySize, gemm_smem(64, 128, 128));
    cudaFuncSetAttribute(mgemm_kernel<128, 128, 128, 128, 1, true>,  cudaFuncAttributeMaxDynamicSharedMemorySize, gemm_smem(128, 128, 128));
    cudaFuncSetAttribute(mgemm_kernel<128, 512, 128, 128, 0, false>, cudaFuncAttributeMaxDynamicSharedMemorySize, gemm_smem(128, 128, 128));
    cudaFuncSetAttribute(mgemm_kernel<256, 256, 64, 256, 1, true>,   cudaFuncAttributeMaxDynamicSharedMemorySize, gemm_smem(256, 64, 256));

    // ---- CSR build (permuted src/dst directly) ----
    cudaMemsetAsync(deg, 0, n * sizeof(int));
    cudaMemsetAsync(cnt, 0, GG * sizeof(int));
    cudaMemsetAsync(stats, 0, 1024 * sizeof(float));
    hist_deg_kernel<<<EG, 256>>>(dstp, deg, E);
    hist_cnt_kernel<<<NG, 256>>>(batch, cnt, n);
    scan_kernel<<<1, 1024>>>(deg, rowptr, cursor, cnt, gstart, n);
    fill_csr_kernel<<<EG, 256>>>(srcp, dstp, cursor, psrc, pdst, E);

    // ---- weight conversion ----
    convert_wsplit_kernel<<<(128 * 32 + 255) / 256, 256>>>(W[0][0], wth + 0, wtl + 0, 7, 64, 32);
    convert_w_kernel<<<(64 * 64 + 255) / 256, 256>>>(W[0][1], wth + 4096, wtl + 4096, 64, 64, 64);
    convert_wsplit_kernel<<<(256 * 64 + 255) / 256, 256>>>(W[1][0], wth + 8192, wtl + 8192, 64, 128, 64);
    convert_w_kernel<<<(128 * 128 + 255) / 256, 256>>>(W[1][1], wth + 24576, wtl + 24576, 128, 128, 128);
    convert_wsplit_kernel<<<(512 * 128 + 255) / 256, 256>>>(W[2][0], wth + 40960, wtl + 40960, 128, 256, 128);
    convert_w_kernel<<<(256 * 256 + 255) / 256, 256>>>(W[2][1], wth + 106496, wtl + 106496, 256, 256, 256);

    // ==== layer 1: 7 -> 64 ====
    cudaMemsetAsync(bias2, 0, 512 * sizeof(float));
    cudaMemcpyAsync(bias2, B[0][0], 64 * sizeof(float), cudaMemcpyDeviceToDevice);
    mgemm_kernel<7, 128, 128, 128, 0, false><<<dim3(NB, 1), 512, gemm_smem(32, 128, 128)>>>(
        x, nullptr, nullptr, nullptr, nullptr, wth + 0, wtl + 0, bias2, UV, nullptr, nullptr, n);
    estats_kernel<64><<<SGRID, 256>>>(UV, psrc, rowptr, sum1, sq1, n);
    finalize_kernel<<<1, 64>>>(sum1, sq1, Gm[0][0], Bt[0][0], a1, c1, 64, invE);
    mgemm_kernel<64, 64, 128, 64, 1, true><<<dim3(EB128, 1), 256, gemm_smem(64, 128, 64)>>>(
        UV, psrc, pdst, a1, c1, wth + 4096, wtl + 4096, B[0][1], t2, sum2, sq2, E);
    finalize_kernel<<<1, 64>>>(sum2, sq2, Gm[0][1], Bt[0][1], a2, c2, 64, invE);
    aggregate_kernel<64><<<AGG, 256>>>(t2, rowptr, a2, c2, hA, n);

    // ==== layer 2: 64 -> 128 ====
    cudaMemsetAsync(bias2, 0, 512 * sizeof(float));
    cudaMemcpyAsync(bias2, B[1][0], 128 * sizeof(float), cudaMemcpyDeviceToDevice);
    mgemm_kernel<64, 256, 128, 128, 0, false><<<dim3(NB, 2), 512, gemm_smem(64, 128, 128)>>>(
        hA, nullptr, nullptr, nullptr, nullptr, wth + 8192, wtl + 8192, bias2, UV, nullptr, nullptr, n);
    estats_kernel<128><<<SGRID, 256>>>(UV, psrc, rowptr, sum1, sq1, n);
    finalize_kernel<<<1, 128>>>(sum1, sq1, Gm[1][0], Bt[1][0], a1, c1, 128, invE);
    mgemm_kernel<128, 128, 128, 128, 1, true><<<dim3(EB128, 1), 512, gemm_smem(128, 128, 128)>>>(
        UV, psrc, pdst, a1, c1, wth + 24576, wtl + 24576, B[1][1], t2, sum2, sq2, E);
    finalize_kernel<<<1, 128>>>(sum2, sq2, Gm[1][1], Bt[1][1], a2, c2, 128, invE);
    aggregate_kernel<128><<<AGG, 256>>>(t2, rowptr, a2, c2, hB, n);

    // ==== layer 3: 128 -> 256 ====
    cudaMemsetAsync(bias2, 0, 512 * sizeof(float));
    cudaMemcpyAsync(bias2, B[2][0], 256 * sizeof(float), cudaMemcpyDeviceToDevice);
    mgemm_kernel<128, 512, 128, 128, 0, false><<<dim3(NB, 4), 512, gemm_smem(128, 128, 128)>>>(
        hB, nullptr, nullptr, nullptr, nullptr, wth + 40960, wtl + 40960, bias2, UV, nullptr, nullptr, n);
    estats_kernel<256><<<SGRID, 256>>>(UV, psrc, rowptr, sum1, sq1, n);
    finalize_kernel<<<1, 256>>>(sum1, sq1, Gm[2][0], Bt[2][0], a1, c1, 256, invE);
    mgemm_kernel<256, 256, 64, 256, 1, true><<<dim3(EB64, 1), 512, gemm_smem(256, 64, 256)>>>(
        UV, psrc, pdst, a1, c1, wth + 106496, wtl + 106496, B[2][1], t2, sum2, sq2, E);
    finalize_kernel<<<1, 256>>>(sum2, sq2, Gm[2][1], Bt[2][1], a2, c2, 256, invE);
    aggregate_kernel<256><<<AGG, 256>>>(t2, rowptr, a2, c2, hA, n);

    // ---- pool + head ----
    pool_kernel<<<GG, 256>>>(hA, gstart, pool);
    head1_kernel<<<GG, 128>>>(pool, hW1, hb1, zbuf);
    head2_kernel<<<1, 128>>>(zbuf, hW2, hb2, (float*)d_out);
}

// round 14
// speedup vs baseline: 2.1039x; 1.0887x over previous
#include <cuda_runtime.h>
#include <cuda_bf16.h>
#include <cstdint>

// ---------------- problem constants ----------------
#define NN 50000
#define EE 500000
#define GG 64

// ---------------- scratch (device globals; no allocation allowed) ----------
__device__ float g_t1[(size_t)EE * 256];            // UV node buffer (<= 50K x 512)
__device__ __nv_bfloat16 g_t2[(size_t)EE * 256];    // edge intermediate t2 (bf16, permuted)
__device__ float g_hA[(size_t)NN * 256];
__device__ float g_hB[(size_t)NN * 256];
__device__ float g_stats[1024];
__device__ float g_norm[1024];
__device__ float g_bias2[512];
__device__ int   g_deg[NN];
__device__ int   g_rowptr[NN + 1];
__device__ int   g_cursor[NN];
__device__ int   g_psrc[EE];
__device__ int   g_pdst[EE];
__device__ int   g_cnt[GG];
__device__ int   g_gstart[GG + 1];
__device__ float g_pool[GG * 256];
__device__ float g_zbuf[GG * 128];
__device__ __nv_bfloat16 g_wth[172032];
__device__ __nv_bfloat16 g_wtl[172032];

// ---------------- mma.sync / ldmatrix helpers ------------------------------
#define MMA_BF16(d, a, b)                                                        \
    asm volatile("mma.sync.aligned.m16n8k16.row.col.f32.bf16.bf16.f32 "          \
                 "{%0,%1,%2,%3}, {%4,%5,%6,%7}, {%8,%9}, {%0,%1,%2,%3};"         \
                 : "+f"((d)[0]), "+f"((d)[1]), "+f"((d)[2]), "+f"((d)[3])        \
                 : "r"((a)[0]), "r"((a)[1]), "r"((a)[2]), "r"((a)[3]),           \
                   "r"((b)[0]), "r"((b)[1]))

#define LDSM_X4(r0, r1, r2, r3, addr)                                            \
    asm volatile("ldmatrix.sync.aligned.m8n8.x4.shared.b16 {%0,%1,%2,%3}, [%4];" \
                 : "=r"(r0), "=r"(r1), "=r"(r2), "=r"(r3) : "r"(addr))

__device__ __forceinline__ uint32_t smem_u32(const void* p) {
    uint32_t a;
    asm("{ .reg .u64 t; cvta.to.shared.u64 t, %1; cvt.u32.u64 %0, t; }" : "=r"(a) : "l"(p));
    return a;
}

// ---------------- small utility kernels ----------------
__global__ void hist_deg_kernel(const int* __restrict__ dst, int* __restrict__ deg, int E) {
    int e = blockIdx.x * blockDim.x + threadIdx.x;
    if (e < E) atomicAdd(&deg[dst[e]], 1);
}
__global__ void hist_cnt_kernel(const int* __restrict__ batch, int* __restrict__ cnt, int n) {
    int i = blockIdx.x * blockDim.x + threadIdx.x;
    if (i < n) atomicAdd(&cnt[batch[i]], 1);
}
__global__ void scan_kernel(const int* __restrict__ deg, int* __restrict__ rowptr,
                            int* __restrict__ cursor, const int* __restrict__ cnt,
                            int* __restrict__ gstart, int n) {
    __shared__ int sh[1024];
    __shared__ int carry;
    int t = threadIdx.x;
    if (t == 0) carry = 0;
    __syncthreads();
    for (int base = 0; base < n; base += 1024) {
        int idx = base + t;
        int v = (idx < n) ? deg[idx] : 0;
        sh[t] = v;
        __syncthreads();
        for (int off = 1; off < 1024; off <<= 1) {
            int add = (t >= off) ? sh[t - off] : 0;
            __syncthreads();
            sh[t] += add;
            __syncthreads();
        }
        int ex = sh[t] - v;
        int cbase = carry;
        if (idx < n) { rowptr[idx] = cbase + ex; cursor[idx] = cbase + ex; }
        __syncthreads();
        if (t == 1023) carry = cbase + sh[1023];
        __syncthreads();
    }
    if (t == 0) {
        rowptr[n] = carry;
        int s = 0;
        for (int g = 0; g < GG; g++) { gstart[g] = s; s += cnt[g]; }
        gstart[GG] = s;
    }
}
__global__ void fill_csr_kernel(const int* __restrict__ src, const int* __restrict__ dst,
                                int* __restrict__ cursor,
                                int* __restrict__ psrc, int* __restrict__ pdst, int E) {
    int e = blockIdx.x * blockDim.x + threadIdx.x;
    if (e < E) {
        int d = dst[e];
        int p = atomicAdd(&cursor[d], 1);
        psrc[p] = src[e];
        pdst[p] = d;
    }
}

__global__ void convert_w_kernel(const float* __restrict__ W,
                                 __nv_bfloat16* __restrict__ Wth,
                                 __nv_bfloat16* __restrict__ Wtl,
                                 int K, int OC, int KPAD) {
    int idx = blockIdx.x * blockDim.x + threadIdx.x;
    if (idx >= OC * KPAD) return;
    int n = idx / KPAD, k = idx % KPAD;
    float w = (k < K) ? W[(size_t)k * OC + n] : 0.f;
    __nv_bfloat16 h = __float2bfloat16_rn(w);
    Wth[idx] = h;
    Wtl[idx] = __float2bfloat16_rn(w - __bfloat162float(h));
}

__global__ void convert_wsplit_kernel(const float* __restrict__ W1,
                                      __nv_bfloat16* __restrict__ Wth,
                                      __nv_bfloat16* __restrict__ Wtl,
                                      int C, int OC, int KPAD) {
    int idx = blockIdx.x * blockDim.x + threadIdx.x;
    if (idx >= 2 * OC * KPAD) return;
    int n = idx / KPAD, k = idx % KPAD;
    float w = 0.f;
    if (k < C) {
        if (n < OC) w = W1[(size_t)k * OC + n] - W1[(size_t)(k + C) * OC + n];
        else        w = W1[(size_t)(k + C) * OC + (n - OC)];
    }
    __nv_bfloat16 h = __float2bfloat16_rn(w);
    Wth[idx] = h;
    Wtl[idx] = __float2bfloat16_rn(w - __bfloat162float(h));
}

// ---------------- tensor-core GEMM (double-buffered, 1 sync/chunk) ---------
// Block tile BM x BN; warps = (BM/32) x (BN/32); warp tile 32x32 (acc 32 regs).
// 3 MMAs per k16 (hi/lo split).  Dynamic smem.
// MODE 0: node GEMM, A row i = fA[i*K..], fp32 output.        Rows = N.
// MODE 1: edge GEMM over permuted edges, A row p =
//         relu((U[pdst]+V[psrc])*an+cn); BF16 output (t2); exact fp32 stats.
template <int K, int OC, int BM, int BN, int MODE, bool STATS>
__global__ __launch_bounds__(BM * BN / 32, 512 * 32 / (BM * BN))
void mgemm_kernel(const float* __restrict__ fA,
                  const int* __restrict__ src, const int* __restrict__ dst,
                  const float* __restrict__ an, const float* __restrict__ cn,
                  const __nv_bfloat16* __restrict__ Wth,
                  const __nv_bfloat16* __restrict__ Wtl,
                  const float* __restrict__ bias,
                  void* __restrict__ out_v,
                  float* __restrict__ stat_sum, float* __restrict__ stat_sq,
                  int Rows) {
    constexpr int THREADS = BM * BN / 32;
    constexpr int MW = BM / 32;
    constexpr int KPAD = (K + 31) / 32 * 32;
    constexpr int NCH = KPAD / 32;
    constexpr int SAS = 40;
    constexpr int ASTR = (MODE == 1) ? 2 * K : K;
    constexpr int TPR = THREADS / BM;
    constexpr int UNITS = 8 / TPR;
    constexpr int NB_LD = 128 / BM;
    constexpr int EST = BN + 8;
    constexpr int NPASS = BM / 64;

    constexpr int ABUF = BM * SAS * 2;
    constexpr int BBUF = BN * SAS * 2;
    constexpr int OFF_AH = 0;
    constexpr int OFF_AL = 2 * ABUF;
    constexpr int OFF_BH = 4 * ABUF;
    constexpr int OFF_BL = 4 * ABUF + 2 * BBUF;
    constexpr int OFF_DST = 4 * ABUF + 4 * BBUF;
    constexpr int OFF_SRC = OFF_DST + 512;
    constexpr int OFF_AN = OFF_SRC + 512;
    constexpr int OFF_CN = OFF_AN + KPAD * 4;
    constexpr int OFF_SSUM = 64 * EST * 4;
    constexpr int OFF_SSQ = OFF_SSUM + BN * 4;

    extern __shared__ char SM[];
    int* sdst = reinterpret_cast<int*>(SM + OFF_DST);
    int* ssrc = reinterpret_cast<int*>(SM + OFF_SRC);
    float* sAn = reinterpret_cast<float*>(SM + OFF_AN);
    float* sCn = reinterpret_cast<float*>(SM + OFF_CN);

    const int tid = threadIdx.x;
    const int lane = tid & 31;
    const int wid = tid >> 5;
    const int wm = wid % MW;
    const int wn = wid / MW;
    const int e0 = blockIdx.x * BM;
    const int col0 = blockIdx.y * BN;

    const uint32_t sAh_u = smem_u32(SM + OFF_AH);
    const uint32_t sAl_u = smem_u32(SM + OFF_AL);
    const uint32_t sBh_u = smem_u32(SM + OFF_BH);
    const uint32_t sBl_u = smem_u32(SM + OFF_BL);

    if (MODE == 1) {
        if (tid < BM) {
            int e = e0 + tid;
            int ee = (e < Rows) ? e : (Rows - 1);
            sdst[tid] = dst[ee];
            ssrc[tid] = src[ee];
        }
        for (int i = tid; i < K; i += THREADS) { sAn[i] = an[i]; sCn[i] = cn[i]; }
    }
    __syncthreads();

    float acc[2][4][4];
#pragma unroll
    for (int mt = 0; mt < 2; mt++)
#pragma unroll
        for (int nt = 0; nt < 4; nt++)
#pragma unroll
            for (int j = 0; j < 4; j++) acc[mt][nt][j] = 0.f;

    const int arow = tid / TPR;
    const int acg = (tid % TPR) * (32 / TPR);
    int nd = 0, ns = 0;
    if (MODE == 1) { nd = sdst[arow]; ns = ssrc[arow]; }

    const int bn0 = tid >> 2;
    const int bu_ = tid & 3;

    float4 P[UNITS], Q[UNITS];
    uint4 BHr[NB_LD], BLr[NB_LD];

    auto load_chunk = [&](int ch) {
        const int k0 = ch * 32 + acg;
        if (MODE == 1) {
            const float* Ur = fA + (size_t)nd * ASTR;
            const float* Vr = fA + (size_t)ns * ASTR + K;
#pragma unroll
            for (int u = 0; u < UNITS; u++) {
                P[u] = *reinterpret_cast<const float4*>(Ur + k0 + u * 4);
                Q[u] = *reinterpret_cast<const float4*>(Vr + k0 + u * 4);
            }
        } else {
            const int i = e0 + arow;
            if (K % 4 == 0) {
                if (i < Rows) {
#pragma unroll
                    for (int u = 0; u < UNITS; u++)
                        P[u] = *reinterpret_cast<const float4*>(&fA[(size_t)i * K + k0 + u * 4]);
                } else {
#pragma unroll
                    for (int u = 0; u < UNITS; u++) P[u] = make_float4(0.f, 0.f, 0.f, 0.f);
                }
            } else {  // K=7 scalar path (NCH==1)
#pragma unroll
                for (int u = 0; u < UNITS; u++) {
                    float t[4];
#pragma unroll
                    for (int j = 0; j < 4; j++) {
                        int kk = k0 + u * 4 + j;
                        t[j] = (i < Rows && kk < K) ? fA[(size_t)i * K + kk] : 0.f;
                    }
                    P[u] = make_float4(t[0], t[1], t[2], t[3]);
                }
            }
        }
    };
    auto load_B = [&](int ch) {
#pragma unroll
        for (int l = 0; l < NB_LD; l++) {
            int r = bn0 + l * (THREADS / 4);
            size_t soff = (size_t)(col0 + r) * KPAD + ch * 32 + bu_ * 8;
            BHr[l] = *reinterpret_cast<const uint4*>(Wth + soff);
            BLr[l] = *reinterpret_cast<const uint4*>(Wtl + soff);
        }
    };
    auto store_chunk = [&](int ch, int buf) {
        char* aH = SM + OFF_AH + buf * ABUF;
        char* aL = SM + OFF_AL + buf * ABUF;
        const int k0 = ch * 32 + acg;
#pragma unroll
        for (int u = 0; u < UNITS; u++) {
            float4 v;
            if (MODE == 1) {
                const int k = k0 + u * 4;
                v.x = fmaxf((P[u].x + Q[u].x) * sAn[k + 0] + sCn[k + 0], 0.f);
                v.y = fmaxf((P[u].y + Q[u].y) * sAn[k + 1] + sCn[k + 1], 0.f);
                v.z = fmaxf((P[u].z + Q[u].z) * sAn[k + 2] + sCn[k + 2], 0.f);
                v.w = fmaxf((P[u].w + Q[u].w) * sAn[k + 3] + sCn[k + 3], 0.f);
            } else {
                v = P[u];
            }
            __nv_bfloat162 h01 = __float22bfloat162_rn(make_float2(v.x, v.y));
            __nv_bfloat162 h23 = __float22bfloat162_rn(make_float2(v.z, v.w));
            float2 hf01 = __bfloat1622float2(h01);
            float2 hf23 = __bfloat1622float2(h23);
            __nv_bfloat162 l01 = __float22bfloat162_rn(make_float2(v.x - hf01.x, v.y - hf01.y));
            __nv_bfloat162 l23 = __float22bfloat162_rn(make_float2(v.z - hf23.x, v.w - hf23.y));
            uint2 H, L;
            H.x = *reinterpret_cast<uint32_t*>(&h01);
            H.y = *reinterpret_cast<uint32_t*>(&h23);
            L.x = *reinterpret_cast<uint32_t*>(&l01);
            L.y = *reinterpret_cast<uint32_t*>(&l23);
            int so = (arow * SAS + acg + u * 4) * 2;
            *reinterpret_cast<uint2*>(aH + so) = H;
            *reinterpret_cast<uint2*>(aL + so) = L;
        }
#pragma unroll
        for (int l = 0; l < NB_LD; l++) {
            int r = bn0 + l * (THREADS / 4);
            int doff = (r * SAS + bu_ * 8) * 2;
            *reinterpret_cast<uint4*>(SM + OFF_BH + buf * BBUF + doff) = BHr[l];
            *reinterpret_cast<uint4*>(SM + OFF_BL + buf * BBUF + doff) = BLr[l];
        }
    };

    const int a_lrow = (lane & 7) + ((lane >> 3) & 1) * 8;
    const int a_lcol = (lane >> 4) * 8;
    const int b_lrow = (lane & 7) + (lane >> 4) * 8;
    const int b_lcol = ((lane >> 3) & 1) * 8;

    load_chunk(0);
    load_B(0);
    store_chunk(0, 0);
    __syncthreads();

    for (int ch = 0; ch < NCH; ch++) {
        const int cur = ch & 1;
        if (ch + 1 < NCH) { load_chunk(ch + 1); load_B(ch + 1); }

        const uint32_t aHb = sAh_u + cur * ABUF;
        const uint32_t aLb = sAl_u + cur * ABUF;
        const uint32_t bHb = sBh_u + cur * BBUF;
        const uint32_t bLb = sBl_u + cur * BBUF;
#pragma unroll
        for (int ks = 0; ks < 2; ks++) {
            const int kb = ks * 16;
            uint32_t ah[2][4], al[2][4];
#pragma unroll
            for (int mt = 0; mt < 2; mt++) {
                int r = wm * 32 + mt * 16 + a_lrow;
                uint32_t off = (uint32_t)(r * SAS + kb + a_lcol) * 2;
                LDSM_X4(ah[mt][0], ah[mt][1], ah[mt][2], ah[mt][3], aHb + off);
                LDSM_X4(al[mt][0], al[mt][1], al[mt][2], al[mt][3], aLb + off);
            }
#pragma unroll
            for (int p = 0; p < 2; p++) {
                int n0 = wn * 32 + p * 16;
                uint32_t boff = (uint32_t)((n0 + b_lrow) * SAS + kb + b_lcol) * 2;
                uint32_t bh[4], bl[4];
                LDSM_X4(bh[0], bh[1], bh[2], bh[3], bHb + boff);
                LDSM_X4(bl[0], bl[1], bl[2], bl[3], bLb + boff);
#pragma unroll
                for (int mt = 0; mt < 2; mt++) {
                    MMA_BF16(acc[mt][2 * p], ah[mt], (&bh[0]));
                    MMA_BF16(acc[mt][2 * p], ah[mt], (&bl[0]));
                    MMA_BF16(acc[mt][2 * p], al[mt], (&bh[0]));
                    MMA_BF16(acc[mt][2 * p + 1], ah[mt], (&bh[2]));
                    MMA_BF16(acc[mt][2 * p + 1], ah[mt], (&bl[2]));
                    MMA_BF16(acc[mt][2 * p + 1], al[mt], (&bh[2]));
                }
            }
        }
        if (ch + 1 < NCH) store_chunk(ch + 1, 1 - cur);
        __syncthreads();
    }

    // ---- epilogue ----
    float* ssum = reinterpret_cast<float*>(SM + OFF_SSUM);
    float* ssq = reinterpret_cast<float*>(SM + OFF_SSQ);

    const int q = lane >> 2, s = lane & 3;

#pragma unroll
    for (int nt = 0; nt < 4; nt++) {
        const int col = col0 + wn * 32 + nt * 8 + s * 2;
        const float b0 = bias[col], b1 = bias[col + 1];
#pragma unroll
        for (int mt = 0; mt < 2; mt++) {
            acc[mt][nt][0] += b0; acc[mt][nt][1] += b1;
            acc[mt][nt][2] += b0; acc[mt][nt][3] += b1;
        }
    }

    if (STATS) {   // exact fp32 stats from accumulators (before any bf16 rounding)
        for (int i = tid; i < 2 * BN; i += THREADS)
            reinterpret_cast<float*>(SM + OFF_SSUM)[i] = 0.f;
        __syncthreads();
#pragma unroll
        for (int nt = 0; nt < 4; nt++) {
            const int colw = wn * 32 + nt * 8 + s * 2;
            float s0 = 0.f, q0 = 0.f, s1 = 0.f, q1 = 0.f;
#pragma unroll
            for (int mt = 0; mt < 2; mt++) {
                const int r = wm * 32 + mt * 16 + q;
                if (e0 + r < Rows) {
                    s0 += acc[mt][nt][0]; q0 += acc[mt][nt][0] * acc[mt][nt][0];
                    s1 += acc[mt][nt][1]; q1 += acc[mt][nt][1] * acc[mt][nt][1];
                }
                if (e0 + r + 8 < Rows) {
                    s0 += acc[mt][nt][2]; q0 += acc[mt][nt][2] * acc[mt][nt][2];
                    s1 += acc[mt][nt][3]; q1 += acc[mt][nt][3] * acc[mt][nt][3];
                }
            }
#pragma unroll
            for (int m = 4; m <= 16; m <<= 1) {
                s0 += __shfl_xor_sync(0xffffffff, s0, m);
                q0 += __shfl_xor_sync(0xffffffff, q0, m);
                s1 += __shfl_xor_sync(0xffffffff, s1, m);
                q1 += __shfl_xor_sync(0xffffffff, q1, m);
            }
            if (q == 0) {
                atomicAdd(&ssum[colw], s0);
                atomicAdd(&ssq[colw], q0);
                atomicAdd(&ssum[colw + 1], s1);
                atomicAdd(&ssq[colw + 1], q1);
            }
        }
        __syncthreads();
        if (tid < BN) {
            atomicAdd(&stat_sum[col0 + tid], ssum[tid]);
            atomicAdd(&stat_sq[col0 + tid], ssq[tid]);
        }
    }

    // coalesced smem-staged store (NPASS 64-row passes)
    if (MODE == 1) {
        // bf16 output path
        __nv_bfloat16* out = reinterpret_cast<__nv_bfloat16*>(out_v);
        __nv_bfloat16* ebuf = reinterpret_cast<__nv_bfloat16*>(SM);
#pragma unroll
        for (int pass = 0; pass < NPASS; pass++) {
            __syncthreads();
            if (NPASS == 1 || (wm >> 1) == pass) {
                const int wml = wm & 1;
#pragma unroll
                for (int mt = 0; mt < 2; mt++) {
                    const int rl = wml * 32 + mt * 16 + q;
#pragma unroll
                    for (int nt = 0; nt < 4; nt++) {
                        const int colw = wn * 32 + nt * 8 + s * 2;
                        __nv_bfloat162 v01 = __float22bfloat162_rn(
                            make_float2(acc[mt][nt][0], acc[mt][nt][1]));
                        __nv_bfloat162 v23 = __float22bfloat162_rn(
                            make_float2(acc[mt][nt][2], acc[mt][nt][3]));
                        *reinterpret_cast<__nv_bfloat162*>(&ebuf[rl * EST + colw]) = v01;
                        *reinterpret_cast<__nv_bfloat162*>(&ebuf[(rl + 8) * EST + colw]) = v23;
                    }
                }
            }
            __syncthreads();
            constexpr int II = 8 * BN / THREADS;
#pragma unroll
            for (int ii = 0; ii < II; ii++) {
                const int i = tid + ii * THREADS;
                const int row = i / (BN / 8), c8 = i % (BN / 8);
                const int e = e0 + pass * 64 + row;
                if (e < Rows) {
                    uint4 v = *reinterpret_cast<uint4*>(&ebuf[row * EST + c8 * 8]);
                    *reinterpret_cast<uint4*>(&out[(size_t)e * OC + col0 + c8 * 8]) = v;
                }
            }
        }
    } else {
        float* out = reinterpret_cast<float*>(out_v);
        float* ebuf = reinterpret_cast<float*>(SM);
#pragma unroll
        for (int pass = 0; pass < NPASS; pass++) {
            __syncthreads();
            if (NPASS == 1 || (wm >> 1) == pass) {
                const int wml = wm & 1;
#pragma unroll
                for (int mt = 0; mt < 2; mt++) {
                    const int rl = wml * 32 + mt * 16 + q;
#pragma unroll
                    for (int nt = 0; nt < 4; nt++) {
                        const int colw = wn * 32 + nt * 8 + s * 2;
                        *reinterpret_cast<float2*>(&ebuf[rl * EST + colw]) =
                            make_float2(acc[mt][nt][0], acc[mt][nt][1]);
                        *reinterpret_cast<float2*>(&ebuf[(rl + 8) * EST + colw]) =
                            make_float2(acc[mt][nt][2], acc[mt][nt][3]);
                    }
                }
            }
            __syncthreads();
            constexpr int II = 16 * BN / THREADS;
#pragma unroll
            for (int ii = 0; ii < II; ii++) {
                const int i = tid + ii * THREADS;
                const int row = i / (BN / 4), c4 = i % (BN / 4);
                const int e = e0 + pass * 64 + row;
                if (e < Rows) {
                    float4 v = *reinterpret_cast<float4*>(&ebuf[row * EST + c4 * 4]);
                    *reinterpret_cast<float4*>(&out[(size_t)e * OC + col0 + c4 * 4]) = v;
                }
            }
        }
    }
}

// ---------------- node-centric edge stats ----------------
template <int OC>
__global__ __launch_bounds__(256)
void estats_kernel(const float* __restrict__ UV, const int* __restrict__ psrc,
                   const int* __restrict__ rowptr,
                   float* __restrict__ sum, float* __restrict__ sq, int n) {
    constexpr int R = OC / 32;
    __shared__ float ss[OC], sv[OC];
    const int tid = threadIdx.x, lane = tid & 31, wid = tid >> 5;
    for (int i = tid; i < OC; i += 256) { ss[i] = 0.f; sv[i] = 0.f; }
    __syncthreads();
    float s[R], q[R];
#pragma unroll
    for (int j = 0; j < R; j++) { s[j] = 0.f; q[j] = 0.f; }
    const int nwarps = gridDim.x * 8;
    for (int i = blockIdx.x * 8 + wid; i < n; i += nwarps) {
        const int beg = rowptr[i], end = rowptr[i + 1];
        const float dg = (float)(end - beg);
        float U[R], sV[R], sV2[R];
        const float* Ur = UV + (size_t)i * (2 * OC);
#pragma unroll
        for (int j = 0; j < R; j++) { U[j] = Ur[j * 32 + lane]; sV[j] = 0.f; sV2[j] = 0.f; }
        for (int p = beg; p < end; p++) {
            const float* Vr = UV + (size_t)psrc[p] * (2 * OC) + OC;
#pragma unroll
            for (int j = 0; j < R; j++) {
                float v = Vr[j * 32 + lane];
                sV[j] += v; sV2[j] += v * v;
            }
        }
#pragma unroll
        for (int j = 0; j < R; j++) {
            s[j] += dg * U[j] + sV[j];
            q[j] += dg * U[j] * U[j] + 2.f * U[j] * sV[j] + sV2[j];
        }
    }
#pragma unroll
    for (int j = 0; j < R; j++) {
        atomicAdd(&ss[j * 32 + lane], s[j]);
        atomicAdd(&sv[j * 32 + lane], q[j]);
    }
    __syncthreads();
    for (int i = tid; i < OC; i += 256) {
        atomicAdd(&sum[i], ss[i]);
        atomicAdd(&sq[i], sv[i]);
    }
}

// ---------------- BN finalize (self-zeroing) ----------------
__global__ void finalize_kernel(float* __restrict__ sum, float* __restrict__ sq,
                                const float* __restrict__ gamma, const float* __restrict__ beta,
                                float* __restrict__ a, float* __restrict__ c,
                                int OC, float invE) {
    int i = blockIdx.x * blockDim.x + threadIdx.x;
    if (i < OC) {
        float m = sum[i] * invE;
        float var = sq[i] * invE - m * m;
        float rs = rsqrtf(var + 1e-5f);
        float ai = gamma[i] * rs;
        a[i] = ai;
        c[i] = beta[i] - m * ai;
        sum[i] = 0.f;
        sq[i] = 0.f;
    }
}

// ---------------- normalize + relu + mean-aggregate (bf16 rows) ------------
template <int OC>
__global__ __launch_bounds__(256)
void aggregate_kernel(const __nv_bfloat16* __restrict__ t, const int* __restrict__ rowptr,
                      const float* __restrict__ a,
                      const float* __restrict__ c, float* __restrict__ hout, int n) {
    int warp = (blockIdx.x * blockDim.x + threadIdx.x) >> 5;
    int lane = threadIdx.x & 31;
    if (warp >= n) return;
    constexpr int R = OC / 64;           // bf16x2 pairs per lane
    float2 av[R], cv[R], acc[R];
#pragma unroll
    for (int j = 0; j < R; j++) {
        int ch = j * 64 + lane * 2;
        av[j] = make_float2(a[ch], a[ch + 1]);
        cv[j] = make_float2(c[ch], c[ch + 1]);
        acc[j] = make_float2(0.f, 0.f);
    }
    int beg = rowptr[warp], end = rowptr[warp + 1];
    for (int p = beg; p < end; p++) {
        const __nv_bfloat162* rowp =
            reinterpret_cast<const __nv_bfloat162*>(t + (size_t)p * OC);
#pragma unroll
        for (int j = 0; j < R; j++) {
            float2 v = __bfloat1622float2(rowp[j * 32 + lane]);
            acc[j].x += fmaxf(v.x * av[j].x + cv[j].x, 0.f);
            acc[j].y += fmaxf(v.y * av[j].y + cv[j].y, 0.f);
        }
    }
    float inv = 1.f / fmaxf((float)(end - beg), 1.f);
#pragma unroll
    for (int j = 0; j < R; j++) {
        int ch = j * 64 + lane * 2;
        hout[(size_t)warp * OC + ch] = acc[j].x * inv;
        hout[(size_t)warp * OC + ch + 1] = acc[j].y * inv;
    }
}

// ---------------- global mean pool + head ----------------
__global__ void pool_kernel(const float* __restrict__ h, const int* __restrict__ gstart,
                            float* __restrict__ pool) {
    int g = blockIdx.x;
    int ch = threadIdx.x;
    int beg = gstart[g], end = gstart[g + 1];
    float s = 0.f;
    for (int nidx = beg; nidx < end; nidx++) s += h[(size_t)nidx * 256 + ch];
    pool[g * 256 + ch] = s / fmaxf((float)(end - beg), 1.f);
}
__global__ void head1_kernel(const float* __restrict__ pool, const float* __restrict__ W,
                             const float* __restrict__ b, float* __restrict__ z) {
    int g = blockIdx.x, j = threadIdx.x;
    __shared__ float sp[256];
    sp[j] = pool[g * 256 + j];
    sp[j + 128] = pool[g * 256 + j + 128];
    __syncthreads();
    float s = b[j];
#pragma unroll 8
    for (int k = 0; k < 256; k++) s += sp[k] * W[k * 128 + j];
    z[g * 128 + j] = fmaxf(s, 0.f);
}
__global__ void head2_kernel(const float* __restrict__ z, const float* __restrict__ W,
                             const float* __restrict__ b, float* __restrict__ out) {
    int t = threadIdx.x;
    int g = t >> 1, j = t & 1;
    float s = b[j];
#pragma unroll 8
    for (int k = 0; k < 128; k++) s += z[g * 128 + k] * W[k * 2 + j];
    out[g * 2 + j] = s;
}

// ---------------- launch ----------------
static inline int gemm_smem(int KPAD, int BM, int BN) {
    int prod = 4 * BM * 80 + 4 * BN * 80 + 1024 + 2 * KPAD * 4;
    int epi = 64 * (BN + 8) * 4 + 8 * BN;
    return prod > epi ? prod : epi;
}

extern "C" void kernel_launch(void* const* d_in, const int* in_sizes, int n_in,
                              void* d_out, int out_size) {
    const float* x     = (const float*)d_in[0];
    const int*   ei    = (const int*)d_in[1];
    const int*   batch = (const int*)d_in[2];

    const int E = in_sizes[1] / 2;
    const int n = in_sizes[2];
    const int* srcp = ei;
    const int* dstp = ei + E;

    const float* W[3][2];  const float* B[3][2];
    const float* Gm[3][2]; const float* Bt[3][2];
    for (int l = 0; l < 3; l++) {
        int base = 3 + l * 8;
        W[l][0]  = (const float*)d_in[base + 0];
        B[l][0]  = (const float*)d_in[base + 1];
        Gm[l][0] = (const float*)d_in[base + 2];
        Bt[l][0] = (const float*)d_in[base + 3];
        W[l][1]  = (const float*)d_in[base + 4];
        B[l][1]  = (const float*)d_in[base + 5];
        Gm[l][1] = (const float*)d_in[base + 6];
        Bt[l][1] = (const float*)d_in[base + 7];
    }
    const float* hW1 = (const float*)d_in[27];
    const float* hb1 = (const float*)d_in[28];
    const float* hW2 = (const float*)d_in[29];
    const float* hb2 = (const float*)d_in[30];

    float *UV, *hA, *hB, *stats, *norm, *pool, *zbuf, *bias2;
    __nv_bfloat16 *t2;
    int *deg, *rowptr, *cursor, *psrc, *pdst, *cnt, *gstart;
    __nv_bfloat16 *wth, *wtl;
    cudaGetSymbolAddress((void**)&UV, g_t1);
    cudaGetSymbolAddress((void**)&t2, g_t2);
    cudaGetSymbolAddress((void**)&hA, g_hA);
    cudaGetSymbolAddress((void**)&hB, g_hB);
    cudaGetSymbolAddress((void**)&stats, g_stats);
    cudaGetSymbolAddress((void**)&norm, g_norm);
    cudaGetSymbolAddress((void**)&bias2, g_bias2);
    cudaGetSymbolAddress((void**)&deg, g_deg);
    cudaGetSymbolAddress((void**)&rowptr, g_rowptr);
    cudaGetSymbolAddress((void**)&cursor, g_cursor);
    cudaGetSymbolAddress((void**)&psrc, g_psrc);
    cudaGetSymbolAddress((void**)&pdst, g_pdst);
    cudaGetSymbolAddress((void**)&cnt, g_cnt);
    cudaGetSymbolAddress((void**)&gstart, g_gstart);
    cudaGetSymbolAddress((void**)&pool, g_pool);
    cudaGetSymbolAddress((void**)&zbuf, g_zbuf);
    cudaGetSymbolAddress((void**)&wth, g_wth);
    cudaGetSymbolAddress((void**)&wtl, g_wtl);

    float* sum1 = stats + 0;   float* sq1 = stats + 256;
    float* sum2 = stats + 512; float* sq2 = stats + 768;
    float* a1 = norm + 0;   float* c1 = norm + 256;
    float* a2 = norm + 512; float* c2 = norm + 768;

    const float invE = 1.f / (float)E;
    const int EB128 = (E + 127) / 128;
    const int EB64 = (E + 63) / 64;
    const int NB = (n + 127) / 128;
    const int EG = (E + 255) / 256;
    const int NG = (n + 255) / 256;
    const int AGG = (n * 32 + 255) / 256;
    const int SGRID = 592;

    cudaFuncSetAttribute(mgemm_kernel<7, 128, 128, 128, 0, false>,   cudaFuncAttributeMaxDynamicSharedMemorySize, gemm_smem(32, 128, 128));
    cudaFuncSetAttribute(mgemm_kernel<64, 64, 128, 64, 1, true>,     cudaFuncAttributeMaxDynamicSharedMemorySize, gemm_smem(64, 128, 64));
    cudaFuncSetAttribute(mgemm_kernel<64, 256, 128, 128, 0, false>,  cudaFuncAttributeMaxDynamicSharedMemorySize, gemm_smem(64, 128, 128));
    cudaFuncSetAttribute(mgemm_kernel<128, 128, 128, 128, 1, true>,  cudaFuncAttributeMaxDynamicSharedMemorySize, gemm_smem(128, 128, 128));
    cudaFuncSetAttribute(mgemm_kernel<128, 512, 128, 128, 0, false>, cudaFuncAttributeMaxDynamicSharedMemorySize, gemm_smem(128, 128, 128));
    cudaFuncSetAttribute(mgemm_kernel<256, 256, 64, 256, 1, true>,   cudaFuncAttributeMaxDynamicSharedMemorySize, gemm_smem(256, 64, 256));

    // ---- CSR build (permuted src/dst directly) ----
    cudaMemsetAsync(deg, 0, n * sizeof(int));
    cudaMemsetAsync(cnt, 0, GG * sizeof(int));
    cudaMemsetAsync(stats, 0, 1024 * sizeof(float));
    hist_deg_kernel<<<EG, 256>>>(dstp, deg, E);
    hist_cnt_kernel<<<NG, 256>>>(batch, cnt, n);
    scan_kernel<<<1, 1024>>>(deg, rowptr, cursor, cnt, gstart, n);
    fill_csr_kernel<<<EG, 256>>>(srcp, dstp, cursor, psrc, pdst, E);

    // ---- weight conversion ----
    convert_wsplit_kernel<<<(128 * 32 + 255) / 256, 256>>>(W[0][0], wth + 0, wtl + 0, 7, 64, 32);
    convert_w_kernel<<<(64 * 64 + 255) / 256, 256>>>(W[0][1], wth + 4096, wtl + 4096, 64, 64, 64);
    convert_wsplit_kernel<<<(256 * 64 + 255) / 256, 256>>>(W[1][0], wth + 8192, wtl + 8192, 64, 128, 64);
    convert_w_kernel<<<(128 * 128 + 255) / 256, 256>>>(W[1][1], wth + 24576, wtl + 24576, 128, 128, 128);
    convert_wsplit_kernel<<<(512 * 128 + 255) / 256, 256>>>(W[2][0], wth + 40960, wtl + 40960, 128, 256, 128);
    convert_w_kernel<<<(256 * 256 + 255) / 256, 256>>>(W[2][1], wth + 106496, wtl + 106496, 256, 256, 256);

    // ==== layer 1: 7 -> 64 ====
    cudaMemsetAsync(bias2, 0, 512 * sizeof(float));
    cudaMemcpyAsync(bias2, B[0][0], 64 * sizeof(float), cudaMemcpyDeviceToDevice);
    mgemm_kernel<7, 128, 128, 128, 0, false><<<dim3(NB, 1), 512, gemm_smem(32, 128, 128)>>>(
        x, nullptr, nullptr, nullptr, nullptr, wth + 0, wtl + 0, bias2, UV, nullptr, nullptr, n);
    estats_kernel<64><<<SGRID, 256>>>(UV, psrc, rowptr, sum1, sq1, n);
    finalize_kernel<<<1, 64>>>(sum1, sq1, Gm[0][0], Bt[0][0], a1, c1, 64, invE);
    mgemm_kernel<64, 64, 128, 64, 1, true><<<dim3(EB128, 1), 256, gemm_smem(64, 128, 64)>>>(
        UV, psrc, pdst, a1, c1, wth + 4096, wtl + 4096, B[0][1], t2, sum2, sq2, E);
    finalize_kernel<<<1, 64>>>(sum2, sq2, Gm[0][1], Bt[0][1], a2, c2, 64, invE);
    aggregate_kernel<64><<<AGG, 256>>>(t2, rowptr, a2, c2, hA, n);

    // ==== layer 2: 64 -> 128 ====
    cudaMemsetAsync(bias2, 0, 512 * sizeof(float));
    cudaMemcpyAsync(bias2, B[1][0], 128 * sizeof(float), cudaMemcpyDeviceToDevice);
    mgemm_kernel<64, 256, 128, 128, 0, false><<<dim3(NB, 2), 512, gemm_smem(64, 128, 128)>>>(
        hA, nullptr, nullptr, nullptr, nullptr, wth + 8192, wtl + 8192, bias2, UV, nullptr, nullptr, n);
    estats_kernel<128><<<SGRID, 256>>>(UV, psrc, rowptr, sum1, sq1, n);
    finalize_kernel<<<1, 128>>>(sum1, sq1, Gm[1][0], Bt[1][0], a1, c1, 128, invE);
    mgemm_kernel<128, 128, 128, 128, 1, true><<<dim3(EB128, 1), 512, gemm_smem(128, 128, 128)>>>(
        UV, psrc, pdst, a1, c1, wth + 24576, wtl + 24576, B[1][1], t2, sum2, sq2, E);
    finalize_kernel<<<1, 128>>>(sum2, sq2, Gm[1][1], Bt[1][1], a2, c2, 128, invE);
    aggregate_kernel<128><<<AGG, 256>>>(t2, rowptr, a2, c2, hB, n);

    // ==== layer 3: 128 -> 256 ====
    cudaMemsetAsync(bias2, 0, 512 * sizeof(float));
    cudaMemcpyAsync(bias2, B[2][0], 256 * sizeof(float), cudaMemcpyDeviceToDevice);
    mgemm_kernel<128, 512, 128, 128, 0, false><<<dim3(NB, 4), 512, gemm_smem(128, 128, 128)>>>(
        hB, nullptr, nullptr, nullptr, nullptr, wth + 40960, wtl + 40960, bias2, UV, nullptr, nullptr, n);
    estats_kernel<256><<<SGRID, 256>>>(UV, psrc, rowptr, sum1, sq1, n);
    finalize_kernel<<<1, 256>>>(sum1, sq1, Gm[2][0], Bt[2][0], a1, c1, 256, invE);
    mgemm_kernel<256, 256, 64, 256, 1, true><<<dim3(EB64, 1), 512, gemm_smem(256, 64, 256)>>>(
        UV, psrc, pdst, a1, c1, wth + 106496, wtl + 106496, B[2][1], t2, sum2, sq2, E);
    finalize_kernel<<<1, 256>>>(sum2, sq2, Gm[2][1], Bt[2][1], a2, c2, 256, invE);
    aggregate_kernel<256><<<AGG, 256>>>(t2, rowptr, a2, c2, hA, n);

    // ---- pool + head ----
    pool_kernel<<<GG, 256>>>(hA, gstart, pool);
    head1_kernel<<<GG, 128>>>(pool, hW1, hb1, zbuf);
    head2_kernel<<<1, 128>>>(zbuf, hW2, hb2, (float*)d_out);
}